// round 1
// baseline (speedup 1.0000x reference)
#include <cuda_runtime.h>

// Problem constants (fixed by the dataset)
#define BB   8
#define NN   4096
#define EE   16384
#define PP   64
#define DD   256
#define HH   512
#define MSG  256
#define UPD  254
#define STEPS 3   // msg_steps == 3 in setup_inputs; graph topology must be host-static

// Scratch (no cudaMalloc allowed)
__device__ float g_ns[BB * NN * DD];    // 32 MB working node state
__device__ float g_inc[BB * NN * MSG];  // 32 MB incoming message accumulator

// ---------------------------------------------------------------------------
__global__ void copy_ns_kernel(const float* __restrict__ src) {
    int i = blockIdx.x * blockDim.x + threadIdx.x;
    if (i < BB * NN * DD) g_ns[i] = src[i];
}

__global__ void zero_inc_kernel() {
    int i = blockIdx.x * blockDim.x + threadIdx.x;
    if (i < BB * NN * MSG) g_inc[i] = 0.0f;
}

// ---------------------------------------------------------------------------
// Edge MLP: for 32 edges per block
//   e_in[32][512] = [ns[src] , ns[snk]]
//   h    = relu(e_in @ W_e1 + b_e1)   (512 cols)
//   msgs = h @ W_e2 + b_e2            (256 cols)
//   atomicAdd into g_inc[b][snk]
// 256 threads: ty = tid>>6 (4 row groups), tx = tid&63 (64 col groups)
// Each thread: 8 edges (ty+4i) x 8 cols (tx+64j) register tile.
__global__ __launch_bounds__(256, 1)
void edge_kernel(const int* __restrict__ esrc, const int* __restrict__ esnk,
                 const float* __restrict__ We1, const float* __restrict__ be1,
                 const float* __restrict__ We2, const float* __restrict__ be2)
{
    extern __shared__ float sm[];
    float* sm_ein = sm;              // 32*512 floats
    float* sm_h   = sm + 32 * 512;   // 32*512 floats
    __shared__ int s_src[32], s_snk[32];

    const int tid = threadIdx.x;
    const int b   = blockIdx.y;
    const int e0  = blockIdx.x * 32;
    const float* __restrict__ nsb = g_ns + (size_t)b * NN * DD;

    if (tid < 32)       s_src[tid]      = esrc[e0 + tid];
    else if (tid < 64)  s_snk[tid - 32] = esnk[e0 + tid - 32];
    __syncthreads();

    // Gather e_in = [src row (256) | snk row (256)]
    #pragma unroll 4
    for (int idx = tid; idx < 32 * 512; idx += 256) {
        int e = idx >> 9, c = idx & 511;
        float v = (c < 256) ? nsb[s_src[e] * DD + c]
                            : nsb[s_snk[e] * DD + (c - 256)];
        sm_ein[idx] = v;
    }
    __syncthreads();

    const int ty = tid >> 6;   // 0..3
    const int tx = tid & 63;   // 0..63

    // ---- h = relu(e_in @ W_e1 + b_e1) ----
    float acc[8][8];
    #pragma unroll
    for (int i = 0; i < 8; i++)
        #pragma unroll
        for (int j = 0; j < 8; j++) acc[i][j] = 0.0f;

    #pragma unroll 4
    for (int k = 0; k < 512; k++) {
        float a[8], w[8];
        #pragma unroll
        for (int i = 0; i < 8; i++) a[i] = sm_ein[(ty + 4 * i) * 512 + k];
        #pragma unroll
        for (int j = 0; j < 8; j++) w[j] = We1[k * HH + tx + 64 * j];
        #pragma unroll
        for (int i = 0; i < 8; i++)
            #pragma unroll
            for (int j = 0; j < 8; j++) acc[i][j] = fmaf(a[i], w[j], acc[i][j]);
    }

    #pragma unroll
    for (int j = 0; j < 8; j++) {
        float bias = be1[tx + 64 * j];
        #pragma unroll
        for (int i = 0; i < 8; i++)
            sm_h[(ty + 4 * i) * 512 + tx + 64 * j] = fmaxf(acc[i][j] + bias, 0.0f);
    }
    __syncthreads();

    // ---- msgs = h @ W_e2 + b_e2 (256 cols) ----
    float acc2[8][4];
    #pragma unroll
    for (int i = 0; i < 8; i++)
        #pragma unroll
        for (int j = 0; j < 4; j++) acc2[i][j] = 0.0f;

    #pragma unroll 4
    for (int k = 0; k < 512; k++) {
        float a[8], w[4];
        #pragma unroll
        for (int i = 0; i < 8; i++) a[i] = sm_h[(ty + 4 * i) * 512 + k];
        #pragma unroll
        for (int j = 0; j < 4; j++) w[j] = We2[k * MSG + tx + 64 * j];
        #pragma unroll
        for (int i = 0; i < 8; i++)
            #pragma unroll
            for (int j = 0; j < 4; j++) acc2[i][j] = fmaf(a[i], w[j], acc2[i][j]);
    }

    float* __restrict__ incb = g_inc + (size_t)b * NN * MSG;
    #pragma unroll
    for (int j = 0; j < 4; j++) {
        float bias = be2[tx + 64 * j];
        #pragma unroll
        for (int i = 0; i < 8; i++) {
            atomicAdd(&incb[s_snk[ty + 4 * i] * MSG + tx + 64 * j], acc2[i][j] + bias);
        }
    }
}

// ---------------------------------------------------------------------------
// Node MLP: 32 nodes per block
//   n_in = [incoming(256) | ns(256)]
//   h2   = relu(n_in @ W_n1 + b_n1)  (512)
//   upd  = h2 @ W_n2 + b_n2          (254)
//   ns[..., 2:256] += upd
__global__ __launch_bounds__(256, 1)
void node_kernel(const float* __restrict__ Wn1, const float* __restrict__ bn1,
                 const float* __restrict__ Wn2, const float* __restrict__ bn2)
{
    extern __shared__ float sm[];
    float* sm_nin = sm;
    float* sm_h   = sm + 32 * 512;

    const int tid = threadIdx.x;
    const int b   = blockIdx.y;
    const int n0  = blockIdx.x * 32;
    const float* __restrict__ incb = g_inc + (size_t)b * NN * MSG;
    float* __restrict__ nsb = g_ns + (size_t)b * NN * DD;

    #pragma unroll 4
    for (int idx = tid; idx < 32 * 512; idx += 256) {
        int e = idx >> 9, c = idx & 511;
        float v = (c < 256) ? incb[(n0 + e) * MSG + c]
                            : nsb[(n0 + e) * DD + (c - 256)];
        sm_nin[idx] = v;
    }
    __syncthreads();

    const int ty = tid >> 6;
    const int tx = tid & 63;

    float acc[8][8];
    #pragma unroll
    for (int i = 0; i < 8; i++)
        #pragma unroll
        for (int j = 0; j < 8; j++) acc[i][j] = 0.0f;

    #pragma unroll 4
    for (int k = 0; k < 512; k++) {
        float a[8], w[8];
        #pragma unroll
        for (int i = 0; i < 8; i++) a[i] = sm_nin[(ty + 4 * i) * 512 + k];
        #pragma unroll
        for (int j = 0; j < 8; j++) w[j] = Wn1[k * HH + tx + 64 * j];
        #pragma unroll
        for (int i = 0; i < 8; i++)
            #pragma unroll
            for (int j = 0; j < 8; j++) acc[i][j] = fmaf(a[i], w[j], acc[i][j]);
    }

    #pragma unroll
    for (int j = 0; j < 8; j++) {
        float bias = bn1[tx + 64 * j];
        #pragma unroll
        for (int i = 0; i < 8; i++)
            sm_h[(ty + 4 * i) * 512 + tx + 64 * j] = fmaxf(acc[i][j] + bias, 0.0f);
    }
    __syncthreads();

    float acc2[8][4];
    #pragma unroll
    for (int i = 0; i < 8; i++)
        #pragma unroll
        for (int j = 0; j < 4; j++) acc2[i][j] = 0.0f;

    #pragma unroll 4
    for (int k = 0; k < 512; k++) {
        float a[8], w[4];
        #pragma unroll
        for (int i = 0; i < 8; i++) a[i] = sm_h[(ty + 4 * i) * 512 + k];
        #pragma unroll
        for (int j = 0; j < 4; j++) {
            int col = tx + 64 * j;
            w[j] = (col < UPD) ? Wn2[k * UPD + col] : 0.0f;
        }
        #pragma unroll
        for (int i = 0; i < 8; i++)
            #pragma unroll
            for (int j = 0; j < 4; j++) acc2[i][j] = fmaf(a[i], w[j], acc2[i][j]);
    }

    #pragma unroll
    for (int j = 0; j < 4; j++) {
        int col = tx + 64 * j;
        if (col < UPD) {
            float bias = bn2[col];
            #pragma unroll
            for (int i = 0; i < 8; i++) {
                int n = n0 + ty + 4 * i;
                // ns[..., -254:] += upd  -> offset 2..255
                nsb[n * DD + 2 + col] += acc2[i][j] + bias;
            }
        }
    }
}

// ---------------------------------------------------------------------------
// extraction[b][p][d] = sum_n attn[b][p][n] * ns[b][n][d]
__global__ __launch_bounds__(256)
void extract_kernel(const float* __restrict__ attn, float* __restrict__ out)
{
    const int b = blockIdx.y;
    const int p = blockIdx.x;
    const int d = threadIdx.x;  // 0..255
    const float* __restrict__ arow = attn + ((size_t)b * PP + p) * NN;
    const float* __restrict__ nsb  = g_ns + (size_t)b * NN * DD;

    float acc = 0.0f;
    #pragma unroll 8
    for (int n = 0; n < NN; n++) {
        acc = fmaf(arow[n], nsb[n * DD + d], acc);
    }
    out[((size_t)b * PP + p) * DD + d] = acc;
}

// ---------------------------------------------------------------------------
extern "C" void kernel_launch(void* const* d_in, const int* in_sizes, int n_in,
                              void* d_out, int out_size)
{
    const float* nodes = (const float*)d_in[0];
    const float* attn  = (const float*)d_in[1];
    const float* We1   = (const float*)d_in[2];
    const float* be1   = (const float*)d_in[3];
    const float* We2   = (const float*)d_in[4];
    const float* be2   = (const float*)d_in[5];
    const float* Wn1   = (const float*)d_in[6];
    const float* bn1   = (const float*)d_in[7];
    const float* Wn2   = (const float*)d_in[8];
    const float* bn2   = (const float*)d_in[9];
    const int*   esrc  = (const int*)d_in[10];
    const int*   esnk  = (const int*)d_in[11];
    float* out = (float*)d_out;

    const int SMEM = 32 * 512 * 4 * 2;  // 128 KB
    cudaFuncSetAttribute(edge_kernel, cudaFuncAttributeMaxDynamicSharedMemorySize, SMEM);
    cudaFuncSetAttribute(node_kernel, cudaFuncAttributeMaxDynamicSharedMemorySize, SMEM);

    copy_ns_kernel<<<(BB * NN * DD + 255) / 256, 256>>>(nodes);

    for (int s = 0; s < STEPS; s++) {
        zero_inc_kernel<<<(BB * NN * MSG + 255) / 256, 256>>>();
        edge_kernel<<<dim3(EE / 32, BB), 256, SMEM>>>(esrc, esnk, We1, be1, We2, be2);
        node_kernel<<<dim3(NN / 32, BB), 256, SMEM>>>(Wn1, bn1, Wn2, bn2);
    }

    extract_kernel<<<dim3(PP, BB), 256>>>(attn, out);
}

// round 2
// speedup vs baseline: 1.5583x; 1.5583x over previous
#include <cuda_runtime.h>

#define BB   8
#define NN   4096
#define EE   16384
#define PP   64
#define DD   256
#define HH   512
#define MSG  256
#define UPD  254
#define STEPS 3

typedef unsigned long long u64;

__device__ float g_ns[BB * NN * DD];    // working node state
__device__ float g_inc[BB * NN * MSG];  // incoming message accumulator

// ---- packed f32x2 helpers -------------------------------------------------
__device__ __forceinline__ u64 ffma2(u64 a, u64 b, u64 c) {
    u64 d;
    asm("fma.rn.f32x2 %0, %1, %2, %3;" : "=l"(d) : "l"(a), "l"(b), "l"(c));
    return d;
}
__device__ __forceinline__ u64 pack2(float lo, float hi) {
    u64 d;
    asm("mov.b64 %0, {%1, %2};" : "=l"(d) : "f"(lo), "f"(hi));
    return d;
}
__device__ __forceinline__ void unpack2(u64 v, float& lo, float& hi) {
    asm("mov.b64 {%0, %1}, %2;" : "=f"(lo), "=f"(hi) : "l"(v));
}

// ---------------------------------------------------------------------------
__global__ void copy_ns_kernel(const float* __restrict__ src) {
    int i = blockIdx.x * blockDim.x + threadIdx.x;
    if (i < BB * NN * DD) g_ns[i] = src[i];
}
__global__ void zero_inc_kernel() {
    int i = blockIdx.x * blockDim.x + threadIdx.x;
    if (i < BB * NN * MSG) g_inc[i] = 0.0f;
}
__global__ void zero_out_kernel(float* __restrict__ out, int n) {
    int i = blockIdx.x * blockDim.x + threadIdx.x;
    if (i < n) out[i] = 0.0f;
}

// ---------------------------------------------------------------------------
// Edge MLP, 32 edges/CTA, 256 threads, single 64KB smem buffer (reused for h).
// ty = tid>>6 (rows ty+4i), tx = tid&63 (GEMM1: cols 8tx..8tx+7 / GEMM2: 4tx..)
__global__ __launch_bounds__(256, 2)
void edge_kernel(const int* __restrict__ esrc, const int* __restrict__ esnk,
                 const float* __restrict__ We1, const float* __restrict__ be1,
                 const float* __restrict__ We2, const float* __restrict__ be2)
{
    extern __shared__ float sm[];          // 32*512 floats, e_in then h
    __shared__ int s_src[32], s_snk[32];

    const int tid = threadIdx.x;
    const int b   = blockIdx.y;
    const int e0  = blockIdx.x * 32;
    const float* __restrict__ nsb = g_ns + (size_t)b * NN * DD;

    if (tid < 32)       s_src[tid]      = esrc[e0 + tid];
    else if (tid < 64)  s_snk[tid - 32] = esnk[e0 + tid - 32];
    __syncthreads();

    // gather e_in = [ns[src](256) | ns[snk](256)] as float4
    #pragma unroll 4
    for (int idx = tid; idx < 32 * 128; idx += 256) {
        int e = idx >> 7, c4 = idx & 127;
        float4 v;
        if (c4 < 64) v = *(const float4*)(nsb + s_src[e] * DD + 4 * c4);
        else         v = *(const float4*)(nsb + s_snk[e] * DD + 4 * (c4 - 64));
        *(float4*)(sm + e * 512 + 4 * c4) = v;
    }
    __syncthreads();

    const int ty = tid >> 6;
    const int tx = tid & 63;

    // ---- GEMM1: h = relu(e_in @ W_e1 + b_e1), thread cols 8tx..8tx+7 ----
    u64 acc[8][4];
    #pragma unroll
    for (int i = 0; i < 8; i++)
        #pragma unroll
        for (int j = 0; j < 4; j++) acc[i][j] = 0ull;

    #pragma unroll 2
    for (int k = 0; k < 512; k++) {
        const ulonglong2* wp = (const ulonglong2*)(We1 + k * HH + 8 * tx);
        ulonglong2 wA = wp[0], wB = wp[1];
        u64 w[4] = { wA.x, wA.y, wB.x, wB.y };
        u64 ap[8];
        #pragma unroll
        for (int i = 0; i < 8; i++) {
            float a = sm[(ty + 4 * i) * 512 + k];
            ap[i] = pack2(a, a);
        }
        #pragma unroll
        for (int i = 0; i < 8; i++)
            #pragma unroll
            for (int j = 0; j < 4; j++)
                acc[i][j] = ffma2(ap[i], w[j], acc[i][j]);
    }
    __syncthreads();   // all reads of e_in done -> safe to overwrite with h

    #pragma unroll
    for (int j = 0; j < 4; j++) {
        int c = 8 * tx + 2 * j;
        float b0 = be1[c], b1 = be1[c + 1];
        #pragma unroll
        for (int i = 0; i < 8; i++) {
            float lo, hi; unpack2(acc[i][j], lo, hi);
            float2 hv = { fmaxf(lo + b0, 0.0f), fmaxf(hi + b1, 0.0f) };
            *(float2*)(sm + (ty + 4 * i) * 512 + c) = hv;
        }
    }
    __syncthreads();

    // ---- GEMM2: msgs = h @ W_e2 + b_e2, thread cols 4tx..4tx+3 ----
    u64 acc2[8][2];
    #pragma unroll
    for (int i = 0; i < 8; i++) { acc2[i][0] = 0ull; acc2[i][1] = 0ull; }

    #pragma unroll 2
    for (int k = 0; k < 512; k++) {
        ulonglong2 wv = *(const ulonglong2*)(We2 + k * MSG + 4 * tx);
        u64 ap[8];
        #pragma unroll
        for (int i = 0; i < 8; i++) {
            float a = sm[(ty + 4 * i) * 512 + k];
            ap[i] = pack2(a, a);
        }
        #pragma unroll
        for (int i = 0; i < 8; i++) {
            acc2[i][0] = ffma2(ap[i], wv.x, acc2[i][0]);
            acc2[i][1] = ffma2(ap[i], wv.y, acc2[i][1]);
        }
    }

    float* __restrict__ incb = g_inc + (size_t)b * NN * MSG;
    #pragma unroll
    for (int j = 0; j < 2; j++) {
        int c = 4 * tx + 2 * j;
        float b0 = be2[c], b1 = be2[c + 1];
        #pragma unroll
        for (int i = 0; i < 8; i++) {
            float lo, hi; unpack2(acc2[i][j], lo, hi);
            float* base = &incb[s_snk[ty + 4 * i] * MSG + c];
            atomicAdd(base,     lo + b0);
            atomicAdd(base + 1, hi + b1);
        }
    }
}

// ---------------------------------------------------------------------------
// Node MLP, 32 nodes/CTA, same structure.
__global__ __launch_bounds__(256, 2)
void node_kernel(const float* __restrict__ Wn1, const float* __restrict__ bn1,
                 const float* __restrict__ Wn2, const float* __restrict__ bn2)
{
    extern __shared__ float sm[];

    const int tid = threadIdx.x;
    const int b   = blockIdx.y;
    const int n0  = blockIdx.x * 32;
    const float* __restrict__ incb = g_inc + (size_t)b * NN * MSG;
    float* __restrict__ nsb = g_ns + (size_t)b * NN * DD;

    #pragma unroll 4
    for (int idx = tid; idx < 32 * 128; idx += 256) {
        int e = idx >> 7, c4 = idx & 127;
        float4 v;
        if (c4 < 64) v = *(const float4*)(incb + (n0 + e) * MSG + 4 * c4);
        else         v = *(const float4*)(nsb + (n0 + e) * DD + 4 * (c4 - 64));
        *(float4*)(sm + e * 512 + 4 * c4) = v;
    }
    __syncthreads();

    const int ty = tid >> 6;
    const int tx = tid & 63;

    u64 acc[8][4];
    #pragma unroll
    for (int i = 0; i < 8; i++)
        #pragma unroll
        for (int j = 0; j < 4; j++) acc[i][j] = 0ull;

    #pragma unroll 2
    for (int k = 0; k < 512; k++) {
        const ulonglong2* wp = (const ulonglong2*)(Wn1 + k * HH + 8 * tx);
        ulonglong2 wA = wp[0], wB = wp[1];
        u64 w[4] = { wA.x, wA.y, wB.x, wB.y };
        u64 ap[8];
        #pragma unroll
        for (int i = 0; i < 8; i++) {
            float a = sm[(ty + 4 * i) * 512 + k];
            ap[i] = pack2(a, a);
        }
        #pragma unroll
        for (int i = 0; i < 8; i++)
            #pragma unroll
            for (int j = 0; j < 4; j++)
                acc[i][j] = ffma2(ap[i], w[j], acc[i][j]);
    }
    __syncthreads();

    #pragma unroll
    for (int j = 0; j < 4; j++) {
        int c = 8 * tx + 2 * j;
        float b0 = bn1[c], b1 = bn1[c + 1];
        #pragma unroll
        for (int i = 0; i < 8; i++) {
            float lo, hi; unpack2(acc[i][j], lo, hi);
            float2 hv = { fmaxf(lo + b0, 0.0f), fmaxf(hi + b1, 0.0f) };
            *(float2*)(sm + (ty + 4 * i) * 512 + c) = hv;
        }
    }
    __syncthreads();

    // GEMM2: 254 cols, thread cols 4tx..4tx+3 (cols >= 254 masked to zero)
    u64 acc2[8][2];
    #pragma unroll
    for (int i = 0; i < 8; i++) { acc2[i][0] = 0ull; acc2[i][1] = 0ull; }

    #pragma unroll 2
    for (int k = 0; k < 512; k++) {
        const float* wr = Wn2 + k * UPD + 4 * tx;
        float2 w01 = *(const float2*)wr;                 // cols 4tx,4tx+1 always valid
        float2 w23 = (tx < 63) ? *(const float2*)(wr + 2)
                               : make_float2(0.0f, 0.0f);
        u64 wp0 = pack2(w01.x, w01.y);
        u64 wp1 = pack2(w23.x, w23.y);
        u64 ap[8];
        #pragma unroll
        for (int i = 0; i < 8; i++) {
            float a = sm[(ty + 4 * i) * 512 + k];
            ap[i] = pack2(a, a);
        }
        #pragma unroll
        for (int i = 0; i < 8; i++) {
            acc2[i][0] = ffma2(ap[i], wp0, acc2[i][0]);
            acc2[i][1] = ffma2(ap[i], wp1, acc2[i][1]);
        }
    }

    #pragma unroll
    for (int j = 0; j < 2; j++) {
        int c = 4 * tx + 2 * j;
        if (c < UPD) {
            float b0 = bn2[c], b1 = bn2[c + 1];
            #pragma unroll
            for (int i = 0; i < 8; i++) {
                float lo, hi; unpack2(acc2[i][j], lo, hi);
                float* base = &nsb[(n0 + ty + 4 * i) * DD + 2 + c];
                base[0] += lo + b0;
                base[1] += hi + b1;
            }
        }
    }
}

// ---------------------------------------------------------------------------
// Extraction: out[b][p][d] = sum_n attn[b][p][n] * ns[b][n][d]
// grid (nchunk=16, b=8); smem holds attn transposed [256 n][64 p] (pad 66).
__global__ __launch_bounds__(256)
void extract_kernel(const float* __restrict__ attn, float* __restrict__ out)
{
    extern __shared__ float smA[];   // 256 * 66 floats
    const int tid = threadIdx.x;
    const int b   = blockIdx.y;
    const int n0  = blockIdx.x * 256;
    const float* __restrict__ nsb = g_ns + (size_t)b * NN * DD;

    // load attn[b][p][n0+j] -> smA[j*66 + p]
    #pragma unroll 4
    for (int idx = tid; idx < 64 * 256; idx += 256) {
        int p = idx >> 8, j = idx & 255;
        smA[j * 66 + p] = attn[((size_t)b * PP + p) * NN + n0 + j];
    }
    __syncthreads();

    const int d = tid;  // 0..255
    u64 accp[32];
    #pragma unroll
    for (int pj = 0; pj < 32; pj++) accp[pj] = 0ull;

    for (int n = 0; n < 256; n++) {
        float s = nsb[(n0 + n) * DD + d];
        u64 sp = pack2(s, s);
        const u64* arow = (const u64*)(smA + n * 66);
        #pragma unroll
        for (int pj = 0; pj < 32; pj++) {
            accp[pj] = ffma2(arow[pj], sp, accp[pj]);
        }
    }

    #pragma unroll
    for (int pj = 0; pj < 32; pj++) {
        float lo, hi; unpack2(accp[pj], lo, hi);
        atomicAdd(&out[((size_t)b * PP + 2 * pj)     * DD + d], lo);
        atomicAdd(&out[((size_t)b * PP + 2 * pj + 1) * DD + d], hi);
    }
}

// ---------------------------------------------------------------------------
extern "C" void kernel_launch(void* const* d_in, const int* in_sizes, int n_in,
                              void* d_out, int out_size)
{
    const float* nodes = (const float*)d_in[0];
    const float* attn  = (const float*)d_in[1];
    const float* We1   = (const float*)d_in[2];
    const float* be1   = (const float*)d_in[3];
    const float* We2   = (const float*)d_in[4];
    const float* be2   = (const float*)d_in[5];
    const float* Wn1   = (const float*)d_in[6];
    const float* bn1   = (const float*)d_in[7];
    const float* Wn2   = (const float*)d_in[8];
    const float* bn2   = (const float*)d_in[9];
    const int*   esrc  = (const int*)d_in[10];
    const int*   esnk  = (const int*)d_in[11];
    float* out = (float*)d_out;

    const int SMEM_MLP = 32 * 512 * 4;        // 64 KB
    const int SMEM_EXT = 256 * 66 * 4;        // 66 KB
    cudaFuncSetAttribute(edge_kernel,    cudaFuncAttributeMaxDynamicSharedMemorySize, SMEM_MLP);
    cudaFuncSetAttribute(node_kernel,    cudaFuncAttributeMaxDynamicSharedMemorySize, SMEM_MLP);
    cudaFuncSetAttribute(extract_kernel, cudaFuncAttributeMaxDynamicSharedMemorySize, SMEM_EXT);

    copy_ns_kernel<<<(BB * NN * DD + 255) / 256, 256>>>(nodes);

    for (int s = 0; s < STEPS; s++) {
        zero_inc_kernel<<<(BB * NN * MSG + 255) / 256, 256>>>();
        edge_kernel<<<dim3(EE / 32, BB), 256, SMEM_MLP>>>(esrc, esnk, We1, be1, We2, be2);
        node_kernel<<<dim3(NN / 32, BB), 256, SMEM_MLP>>>(Wn1, bn1, Wn2, bn2);
    }

    zero_out_kernel<<<(BB * PP * DD + 255) / 256, 256>>>(out, BB * PP * DD);
    extract_kernel<<<dim3(NN / 256, BB), 256, SMEM_EXT>>>(attn, out);
}

// round 4
// speedup vs baseline: 3.1287x; 2.0078x over previous
#include <cuda_runtime.h>
#include <cuda_bf16.h>
#include <cstdint>

#define BB   8
#define NN   4096
#define EE   16384
#define PP   64
#define DD   256
#define HH   512
#define MSG  256
#define UPD  254
#define STEPS 3

#define EROWS (BB * EE)   // 131072 edge rows
#define NROWS (BB * NN)   // 32768 node rows

typedef unsigned long long u64;

// ---------------------------------------------------------------------------
// Device globals (no cudaMalloc allowed)
// ---------------------------------------------------------------------------
__device__ float g_ns [NROWS * DD];     // fp32 node state
__device__ float g_inc[NROWS * MSG];    // fp32 incoming accumulator

__device__ __nv_bfloat16 g_ns_hi [NROWS * DD];
__device__ __nv_bfloat16 g_ns_lo [NROWS * DD];
__device__ __nv_bfloat16 g_inc_hi[NROWS * MSG];
__device__ __nv_bfloat16 g_inc_lo[NROWS * MSG];
__device__ __nv_bfloat16 g_h_hi[(size_t)EROWS * HH];   // hidden acts hi
__device__ __nv_bfloat16 g_h_lo[(size_t)EROWS * HH];   // hidden acts lo

// transposed + split weights: WT[n][k] = W[k][n], k contiguous (512)
__device__ __nv_bfloat16 g_We1T_hi[HH * 512],  g_We1T_lo[HH * 512];
__device__ __nv_bfloat16 g_We2T_hi[MSG * 512], g_We2T_lo[MSG * 512];
__device__ __nv_bfloat16 g_Wn1T_hi[HH * 512],  g_Wn1T_lo[HH * 512];
__device__ __nv_bfloat16 g_Wn2T_hi[256 * 512], g_Wn2T_lo[256 * 512];  // 254->256 pad

// ---------------------------------------------------------------------------
// PTX helpers (base ISA only: ldmatrix / mma.sync / cp.async)
// ---------------------------------------------------------------------------
__device__ __forceinline__ uint32_t smem_u32(const void* p) {
    uint32_t a;
    asm("{ .reg .u64 t; cvta.to.shared.u64 t, %1; cvt.u32.u64 %0, t; }" : "=r"(a) : "l"(p));
    return a;
}
__device__ __forceinline__ void ldsm4(uint32_t* r, uint32_t a) {
    asm volatile("ldmatrix.sync.aligned.m8n8.x4.shared.b16 {%0,%1,%2,%3}, [%4];"
        : "=r"(r[0]), "=r"(r[1]), "=r"(r[2]), "=r"(r[3]) : "r"(a));
}
__device__ __forceinline__ void mma_bf16(float* c, const uint32_t* a, uint32_t b0, uint32_t b1) {
    asm volatile("mma.sync.aligned.m16n8k16.row.col.f32.bf16.bf16.f32 "
        "{%0,%1,%2,%3}, {%4,%5,%6,%7}, {%8,%9}, {%0,%1,%2,%3};"
        : "+f"(c[0]), "+f"(c[1]), "+f"(c[2]), "+f"(c[3])
        : "r"(a[0]), "r"(a[1]), "r"(a[2]), "r"(a[3]), "r"(b0), "r"(b1));
}
__device__ __forceinline__ void cpa16(uint32_t d, const void* s) {
    asm volatile("cp.async.cg.shared.global [%0], [%1], 16;" :: "r"(d), "l"(s) : "memory");
}
#define CP_COMMIT() asm volatile("cp.async.commit_group;" ::: "memory")
#define CP_WAIT1()  asm volatile("cp.async.wait_group 1;" ::: "memory")
#define CP_WAIT0()  asm volatile("cp.async.wait_group 0;" ::: "memory")

__device__ __forceinline__ uint32_t swz(uint32_t off) { return off ^ ((off >> 3) & 0x70); }

__device__ __forceinline__ void split_bf16(float v, __nv_bfloat16& hi, __nv_bfloat16& lo) {
    hi = __float2bfloat16_rn(v);
    lo = __float2bfloat16_rn(v - __bfloat162float(hi));
}

// ---------------------------------------------------------------------------
// Small utility kernels
// ---------------------------------------------------------------------------
__global__ void copy_ns_kernel(const float* __restrict__ src) {
    int i = blockIdx.x * blockDim.x + threadIdx.x;
    if (i < NROWS * DD) g_ns[i] = src[i];
}
__global__ void zero_inc_kernel() {
    int i = blockIdx.x * blockDim.x + threadIdx.x;
    if (i < NROWS * MSG) g_inc[i] = 0.0f;
}
__global__ void zero_out_kernel(float* __restrict__ out, int n) {
    int i = blockIdx.x * blockDim.x + threadIdx.x;
    if (i < n) out[i] = 0.0f;
}
__global__ void split_kernel(const float* __restrict__ src,
                             __nv_bfloat16* __restrict__ hi,
                             __nv_bfloat16* __restrict__ lo, int n) {
    int i = blockIdx.x * blockDim.x + threadIdx.x;
    if (i < n) {
        __nv_bfloat16 h, l;
        split_bf16(src[i], h, l);
        hi[i] = h; lo[i] = l;
    }
}
// WT[n][k] = W[k][n], rows n >= N zero-padded; W is [512][N] row-major
__global__ void splitT_kernel(const float* __restrict__ W,
                              __nv_bfloat16* __restrict__ hi,
                              __nv_bfloat16* __restrict__ lo, int N, int NT) {
    int i = blockIdx.x * blockDim.x + threadIdx.x;
    if (i < NT * 512) {
        int n = i >> 9, k = i & 511;
        float v = (n < N) ? W[k * N + n] : 0.0f;
        __nv_bfloat16 h, l;
        split_bf16(v, h, l);
        hi[i] = h; lo[i] = l;
    }
}

// ---------------------------------------------------------------------------
// Generic mma.sync GEMM: D[64 rows, Ntot] = A[64, 512] @ W[512, Ntot]
//   MODE 0: edge GEMM1 (Ntot=512): A = gather [ns[src]|ns[snk]], epi relu->h hi/lo
//   MODE 1: edge GEMM2 (Ntot=256): A = h rows, epi bias + atomic scatter -> g_inc
//   MODE 2: node GEMM1 (Ntot=512): A = [inc|ns], epi relu->h hi/lo
//   MODE 3: node GEMM2 (Ntot=256 pad): A = h rows, epi bias + add -> g_ns[...,2+c]
// A resident in smem (hi+lo, 8 chunk-tiles of 64x64), B double-buffered cp.async.
// 256 threads = 8 warps (2 m x 4 n); warp tile 32x32.
// ---------------------------------------------------------------------------
#define A_HI_OFF 0
#define A_LO_OFF (64 * 1024)
#define B_OFF    (128 * 1024)     // stage s: B_OFF + s*32768; lo at +16384
#define SMEM_GEMM (192 * 1024)

template <int MODE>
__global__ __launch_bounds__(256, 1)
void gemm_kernel(const int* __restrict__ esrc, const int* __restrict__ esnk,
                 const float* __restrict__ bias)
{
    extern __shared__ char sm[];
    __shared__ int s_src[64], s_snk[64];

    const int tid  = threadIdx.x;
    const int wid  = tid >> 5, lane = tid & 31;
    const int r0   = blockIdx.x * 64;
    int b = 0, e0 = 0;
    if (MODE == 0 || MODE == 1) { b = r0 >> 14; e0 = r0 & 16383; }

    const uint32_t smb = smem_u32(sm);

    if (MODE == 0) {
        if (tid < 64)       s_src[tid]      = esrc[e0 + tid];
        else if (tid < 128) s_snk[tid - 64] = esnk[e0 + tid - 64];
    } else if (MODE == 1) {
        if (tid < 64)       s_snk[tid]      = esnk[e0 + tid];
    }
    __syncthreads();

    // ---- load A resident: 64 rows x 512 cols, hi + lo, chunk-tiled ----
    #pragma unroll 1
    for (int h = 0; h < 2; h++) {
        char* abase = sm + (h ? A_LO_OFF : A_HI_OFF);
        #pragma unroll
        for (int it = 0; it < 16; it++) {
            int u   = tid + it * 256;
            int row = u >> 6;          // 0..63
            int seg = u & 63;          // 16B segment across 512 cols
            int col = seg * 8;
            const __nv_bfloat16* src;
            if (MODE == 0) {
                int node = (col < 256) ? s_src[row] : s_snk[row];
                int c2   = (col < 256) ? col : col - 256;
                src = (h ? g_ns_lo : g_ns_hi) + ((size_t)(b * NN + node)) * DD + c2;
            } else if (MODE == 2) {
                src = (col < 256)
                    ? (h ? g_inc_lo : g_inc_hi) + ((size_t)(r0 + row)) * MSG + col
                    : (h ? g_ns_lo  : g_ns_hi ) + ((size_t)(r0 + row)) * DD + (col - 256);
            } else {
                src = (h ? g_h_lo : g_h_hi) + ((size_t)(r0 + row)) * HH + col;
            }
            uint4 v = *(const uint4*)src;
            int kc = seg >> 3, kseg = seg & 7;
            *(uint4*)(abase + kc * 8192 + swz((uint32_t)(row * 128 + kseg * 16))) = v;
        }
    }

    // B matrices
    const __nv_bfloat16 *bt_hi, *bt_lo;
    if      (MODE == 0) { bt_hi = g_We1T_hi; bt_lo = g_We1T_lo; }
    else if (MODE == 1) { bt_hi = g_We2T_hi; bt_lo = g_We2T_lo; }
    else if (MODE == 2) { bt_hi = g_Wn1T_hi; bt_lo = g_Wn1T_lo; }
    else                { bt_hi = g_Wn2T_hi; bt_lo = g_Wn2T_lo; }

    const int NCH = (MODE == 0 || MODE == 2) ? 4 : 2;
    const int TOT = NCH * 8;

    auto prefetch = [&](int c, int s) {
        int nc = c >> 3, kc = c & 7;
        uint32_t dsth = smb + B_OFF + s * 32768;
        uint32_t dstl = dsth + 16384;
        #pragma unroll
        for (int it = 0; it < 4; it++) {
            int u = tid + it * 256;
            int row = u >> 3, seg = u & 7;
            size_t so = ((size_t)(nc * 128 + row)) * 512 + kc * 64 + seg * 8;
            uint32_t d = swz((uint32_t)(row * 128 + seg * 16));
            cpa16(dsth + d, bt_hi + so);
            cpa16(dstl + d, bt_lo + so);
        }
    };

    float acc[2][4][4];
    #pragma unroll
    for (int mi = 0; mi < 2; mi++)
        #pragma unroll
        for (int nt = 0; nt < 4; nt++)
            #pragma unroll
            for (int q = 0; q < 4; q++) acc[mi][nt][q] = 0.0f;

    prefetch(0, 0);
    CP_COMMIT();

    const int wm = wid & 1, wn = wid >> 1;
    const int la15 = lane & 15, la_h = lane >> 4;
    const int lb_n = (lane & 7) + ((lane >> 4) << 3);
    const int lb_k = ((lane >> 3) & 1) << 4;
    const int rq = lane >> 2, cq = (lane & 3) * 2;

    __syncthreads();   // A resident visible (also covers s_src/s_snk)

    #pragma unroll 1
    for (int c = 0; c < TOT; c++) {
        const int s = c & 1;
        if (c + 1 < TOT) prefetch(c + 1, s ^ 1);
        CP_COMMIT();
        CP_WAIT1();
        __syncthreads();

        const int kc = c & 7;
        const uint32_t abh = smb + A_HI_OFF + kc * 8192;
        const uint32_t abl = smb + A_LO_OFF + kc * 8192;
        const uint32_t bbh = smb + B_OFF + s * 32768;
        const uint32_t bbl = bbh + 16384;

        #pragma unroll
        for (int ks = 0; ks < 4; ks++) {
            uint32_t ah[2][4], al[2][4], bh[2][4], bl[2][4];
            #pragma unroll
            for (int mi = 0; mi < 2; mi++) {
                uint32_t ro = swz((uint32_t)((wm * 32 + mi * 16 + la15) * 128 + ks * 32 + la_h * 16));
                ldsm4(ah[mi], abh + ro);
                ldsm4(al[mi], abl + ro);
            }
            #pragma unroll
            for (int p = 0; p < 2; p++) {
                uint32_t ro = swz((uint32_t)((wn * 32 + p * 16 + lb_n) * 128 + ks * 32 + lb_k));
                ldsm4(bh[p], bbh + ro);
                ldsm4(bl[p], bbl + ro);
            }
            #pragma unroll
            for (int mi = 0; mi < 2; mi++)
                #pragma unroll
                for (int p = 0; p < 2; p++) {
                    mma_bf16(acc[mi][2 * p],     ah[mi], bh[p][0], bh[p][1]);
                    mma_bf16(acc[mi][2 * p + 1], ah[mi], bh[p][2], bh[p][3]);
                    mma_bf16(acc[mi][2 * p],     ah[mi], bl[p][0], bl[p][1]);
                    mma_bf16(acc[mi][2 * p + 1], ah[mi], bl[p][2], bl[p][3]);
                    mma_bf16(acc[mi][2 * p],     al[mi], bh[p][0], bh[p][1]);
                    mma_bf16(acc[mi][2 * p + 1], al[mi], bh[p][2], bh[p][3]);
                }
        }
        __syncthreads();

        // ---- epilogue at end of each n-chunk ----
        if (kc == 7) {
            const int n0 = (c >> 3) * 128;
            #pragma unroll
            for (int mi = 0; mi < 2; mi++) {
                #pragma unroll
                for (int nt = 0; nt < 4; nt++) {
                    int col = n0 + wn * 32 + nt * 8 + cq;   // even global col
                    int rl0 = wm * 32 + mi * 16 + rq;
                    int rl1 = rl0 + 8;
                    float* a4 = acc[mi][nt];
                    if (MODE == 0 || MODE == 2) {
                        float2 bv = *(const float2*)(bias + col);
                        #pragma unroll
                        for (int hrow = 0; hrow < 2; hrow++) {
                            int rl = hrow ? rl1 : rl0;
                            float v0 = fmaxf(a4[2 * hrow]     + bv.x, 0.0f);
                            float v1 = fmaxf(a4[2 * hrow + 1] + bv.y, 0.0f);
                            __nv_bfloat16 h0, l0, h1, l1;
                            split_bf16(v0, h0, l0);
                            split_bf16(v1, h1, l1);
                            uint32_t ph = ((uint32_t)__bfloat16_as_ushort(h1) << 16) | __bfloat16_as_ushort(h0);
                            uint32_t pl = ((uint32_t)__bfloat16_as_ushort(l1) << 16) | __bfloat16_as_ushort(l0);
                            size_t go = (size_t)(r0 + rl) * HH + col;
                            *(uint32_t*)(g_h_hi + go) = ph;
                            *(uint32_t*)(g_h_lo + go) = pl;
                        }
                    } else if (MODE == 1) {
                        float2 bv = *(const float2*)(bias + col);
                        float* p0 = g_inc + ((size_t)(b * NN + s_snk[rl0])) * MSG + col;
                        atomicAdd(p0,     a4[0] + bv.x);
                        atomicAdd(p0 + 1, a4[1] + bv.y);
                        float* p1 = g_inc + ((size_t)(b * NN + s_snk[rl1])) * MSG + col;
                        atomicAdd(p1,     a4[2] + bv.x);
                        atomicAdd(p1 + 1, a4[3] + bv.y);
                    } else {
                        if (col < UPD) {
                            float bv = bias[col];
                            g_ns[((size_t)(r0 + rl0)) * DD + 2 + col] += a4[0] + bv;
                            g_ns[((size_t)(r0 + rl1)) * DD + 2 + col] += a4[2] + bv;
                        }
                        if (col + 1 < UPD) {
                            float bv = bias[col + 1];
                            g_ns[((size_t)(r0 + rl0)) * DD + 3 + col] += a4[1] + bv;
                            g_ns[((size_t)(r0 + rl1)) * DD + 3 + col] += a4[3] + bv;
                        }
                    }
                    a4[0] = a4[1] = a4[2] = a4[3] = 0.0f;
                }
            }
        }
    }
    CP_WAIT0();
}

// ---------------------------------------------------------------------------
// Extraction: out[b][p][d] = sum_n attn[b][p][n] * ns[b][n][d]  (FFMA2 SIMT)
// ---------------------------------------------------------------------------
__device__ __forceinline__ u64 ffma2(u64 a, u64 b, u64 c) {
    u64 d; asm("fma.rn.f32x2 %0, %1, %2, %3;" : "=l"(d) : "l"(a), "l"(b), "l"(c)); return d;
}
__device__ __forceinline__ u64 pack2(float lo, float hi) {
    u64 d; asm("mov.b64 %0, {%1, %2};" : "=l"(d) : "f"(lo), "f"(hi)); return d;
}
__device__ __forceinline__ void unpack2(u64 v, float& lo, float& hi) {
    asm("mov.b64 {%0, %1}, %2;" : "=f"(lo), "=f"(hi) : "l"(v));
}

__global__ __launch_bounds__(256)
void extract_kernel(const float* __restrict__ attn, float* __restrict__ out)
{
    extern __shared__ float smA[];   // 256 * 66
    const int tid = threadIdx.x;
    const int b   = blockIdx.y;
    const int n0  = blockIdx.x * 256;
    const float* __restrict__ nsb = g_ns + (size_t)b * NN * DD;

    #pragma unroll 4
    for (int idx = tid; idx < 64 * 256; idx += 256) {
        int p = idx >> 8, j = idx & 255;
        smA[j * 66 + p] = attn[((size_t)b * PP + p) * NN + n0 + j];
    }
    __syncthreads();

    const int d = tid;
    u64 accp[32];
    #pragma unroll
    for (int pj = 0; pj < 32; pj++) accp[pj] = 0ull;

    for (int n = 0; n < 256; n++) {
        float s = nsb[(n0 + n) * DD + d];
        u64 sp = pack2(s, s);
        const u64* arow = (const u64*)(smA + n * 66);
        #pragma unroll
        for (int pj = 0; pj < 32; pj++) accp[pj] = ffma2(arow[pj], sp, accp[pj]);
    }
    #pragma unroll
    for (int pj = 0; pj < 32; pj++) {
        float lo, hi; unpack2(accp[pj], lo, hi);
        atomicAdd(&out[((size_t)b * PP + 2 * pj)     * DD + d], lo);
        atomicAdd(&out[((size_t)b * PP + 2 * pj + 1) * DD + d], hi);
    }
}

// ---------------------------------------------------------------------------
extern "C" void kernel_launch(void* const* d_in, const int* in_sizes, int n_in,
                              void* d_out, int out_size)
{
    const float* nodes = (const float*)d_in[0];
    const float* attn  = (const float*)d_in[1];
    const float* We1   = (const float*)d_in[2];
    const float* be1   = (const float*)d_in[3];
    const float* We2   = (const float*)d_in[4];
    const float* be2   = (const float*)d_in[5];
    const float* Wn1   = (const float*)d_in[6];
    const float* bn1   = (const float*)d_in[7];
    const float* Wn2   = (const float*)d_in[8];
    const float* bn2   = (const float*)d_in[9];
    const int*   esrc  = (const int*)d_in[10];
    const int*   esnk  = (const int*)d_in[11];
    float* out = (float*)d_out;

    cudaFuncSetAttribute(gemm_kernel<0>, cudaFuncAttributeMaxDynamicSharedMemorySize, SMEM_GEMM);
    cudaFuncSetAttribute(gemm_kernel<1>, cudaFuncAttributeMaxDynamicSharedMemorySize, SMEM_GEMM);
    cudaFuncSetAttribute(gemm_kernel<2>, cudaFuncAttributeMaxDynamicSharedMemorySize, SMEM_GEMM);
    cudaFuncSetAttribute(gemm_kernel<3>, cudaFuncAttributeMaxDynamicSharedMemorySize, SMEM_GEMM);
    const int SMEM_EXT = 256 * 66 * 4;
    cudaFuncSetAttribute(extract_kernel, cudaFuncAttributeMaxDynamicSharedMemorySize, SMEM_EXT);

    __nv_bfloat16 *we1h, *we1l, *we2h, *we2l, *wn1h, *wn1l, *wn2h, *wn2l;
    cudaGetSymbolAddress((void**)&we1h, g_We1T_hi); cudaGetSymbolAddress((void**)&we1l, g_We1T_lo);
    cudaGetSymbolAddress((void**)&we2h, g_We2T_hi); cudaGetSymbolAddress((void**)&we2l, g_We2T_lo);
    cudaGetSymbolAddress((void**)&wn1h, g_Wn1T_hi); cudaGetSymbolAddress((void**)&wn1l, g_Wn1T_lo);
    cudaGetSymbolAddress((void**)&wn2h, g_Wn2T_hi); cudaGetSymbolAddress((void**)&wn2l, g_Wn2T_lo);
    splitT_kernel<<<(HH  * 512 + 255) / 256, 256>>>(We1, we1h, we1l, HH,  HH);
    splitT_kernel<<<(MSG * 512 + 255) / 256, 256>>>(We2, we2h, we2l, MSG, MSG);
    splitT_kernel<<<(HH  * 512 + 255) / 256, 256>>>(Wn1, wn1h, wn1l, HH,  HH);
    splitT_kernel<<<(256 * 512 + 255) / 256, 256>>>(Wn2, wn2h, wn2l, UPD, 256);

    copy_ns_kernel<<<(NROWS * DD + 255) / 256, 256>>>(nodes);

    float *pns, *pinc;
    __nv_bfloat16 *nsh, *nsl, *inch, *incl;
    cudaGetSymbolAddress((void**)&pns,  g_ns);
    cudaGetSymbolAddress((void**)&pinc, g_inc);
    cudaGetSymbolAddress((void**)&nsh,  g_ns_hi);  cudaGetSymbolAddress((void**)&nsl,  g_ns_lo);
    cudaGetSymbolAddress((void**)&inch, g_inc_hi); cudaGetSymbolAddress((void**)&incl, g_inc_lo);

    for (int s = 0; s < STEPS; s++) {
        split_kernel<<<(NROWS * DD + 255) / 256, 256>>>(pns, nsh, nsl, NROWS * DD);
        zero_inc_kernel<<<(NROWS * MSG + 255) / 256, 256>>>();
        gemm_kernel<0><<<EROWS / 64, 256, SMEM_GEMM>>>(esrc, esnk, be1);
        gemm_kernel<1><<<EROWS / 64, 256, SMEM_GEMM>>>(esrc, esnk, be2);
        split_kernel<<<(NROWS * MSG + 255) / 256, 256>>>(pinc, inch, incl, NROWS * MSG);
        gemm_kernel<2><<<NROWS / 64, 256, SMEM_GEMM>>>(esrc, esnk, bn1);
        gemm_kernel<3><<<NROWS / 64, 256, SMEM_GEMM>>>(esrc, esnk, bn2);
    }

    zero_out_kernel<<<(BB * PP * DD + 255) / 256, 256>>>(out, BB * PP * DD);
    extract_kernel<<<dim3(NN / 256, BB), 256, SMEM_EXT>>>(attn, out);
}

// round 6
// speedup vs baseline: 3.4854x; 1.1140x over previous
#include <cuda_runtime.h>
#include <cuda_bf16.h>
#include <cstdint>

#define BB   8
#define NN   4096
#define EE   16384
#define PP   64
#define DD   256
#define HH   512
#define MSG  256
#define UPD  254
#define STEPS 3

#define EROWS (BB * EE)   // 131072
#define NROWS (BB * NN)   // 32768

typedef unsigned long long u64;

// ---------------------------------------------------------------------------
// Device globals
// ---------------------------------------------------------------------------
__device__ float g_ns [NROWS * DD];
__device__ float g_inc[NROWS * MSG];

__device__ __nv_bfloat16 g_ns_hi [NROWS * DD];
__device__ __nv_bfloat16 g_ns_lo [NROWS * DD];
__device__ __nv_bfloat16 g_inc_hi[NROWS * MSG];
__device__ __nv_bfloat16 g_inc_lo[NROWS * MSG];
__device__ __nv_bfloat16 g_h_hi[(size_t)EROWS * HH];
__device__ __nv_bfloat16 g_h_lo[(size_t)EROWS * HH];

// transposed + split weights: WT[n][k] = W[k][n], k contiguous (512)
__device__ __nv_bfloat16 g_We1T_hi[HH * 512],  g_We1T_lo[HH * 512];
__device__ __nv_bfloat16 g_We2T_hi[MSG * 512], g_We2T_lo[MSG * 512];
__device__ __nv_bfloat16 g_Wn1T_hi[HH * 512],  g_Wn1T_lo[HH * 512];
__device__ __nv_bfloat16 g_Wn2T_hi[256 * 512], g_Wn2T_lo[256 * 512];

// ---------------------------------------------------------------------------
// PTX helpers
// ---------------------------------------------------------------------------
__device__ __forceinline__ uint32_t smem_u32(const void* p) {
    uint32_t a;
    asm("{ .reg .u64 t; cvta.to.shared.u64 t, %1; cvt.u32.u64 %0, t; }" : "=r"(a) : "l"(p));
    return a;
}
__device__ __forceinline__ void ldsm4(uint32_t* r, uint32_t a) {
    asm volatile("ldmatrix.sync.aligned.m8n8.x4.shared.b16 {%0,%1,%2,%3}, [%4];"
        : "=r"(r[0]), "=r"(r[1]), "=r"(r[2]), "=r"(r[3]) : "r"(a));
}
__device__ __forceinline__ void mma_bf16(float* c, const uint32_t* a, uint32_t b0, uint32_t b1) {
    asm volatile("mma.sync.aligned.m16n8k16.row.col.f32.bf16.bf16.f32 "
        "{%0,%1,%2,%3}, {%4,%5,%6,%7}, {%8,%9}, {%0,%1,%2,%3};"
        : "+f"(c[0]), "+f"(c[1]), "+f"(c[2]), "+f"(c[3])
        : "r"(a[0]), "r"(a[1]), "r"(a[2]), "r"(a[3]), "r"(b0), "r"(b1));
}
__device__ __forceinline__ void cpa16(uint32_t d, const void* s) {
    asm volatile("cp.async.cg.shared.global [%0], [%1], 16;" :: "r"(d), "l"(s) : "memory");
}
#define CP_COMMIT() asm volatile("cp.async.commit_group;" ::: "memory")
#define CP_WAIT2()  asm volatile("cp.async.wait_group 2;" ::: "memory")

__device__ __forceinline__ void split_bf16(float v, __nv_bfloat16& hi, __nv_bfloat16& lo) {
    hi = __float2bfloat16_rn(v);
    lo = __float2bfloat16_rn(v - __bfloat162float(hi));
}

// ---------------------------------------------------------------------------
// Utility kernels
// ---------------------------------------------------------------------------
__global__ void copy_split_ns_kernel(const float* __restrict__ src) {
    int i = blockIdx.x * blockDim.x + threadIdx.x;
    if (i < NROWS * DD) {
        float v = src[i];
        g_ns[i] = v;
        __nv_bfloat16 h, l;
        split_bf16(v, h, l);
        g_ns_hi[i] = h; g_ns_lo[i] = l;
    }
}
__global__ void zero_inc_kernel() {
    int i = blockIdx.x * blockDim.x + threadIdx.x;
    if (i < NROWS * MSG) g_inc[i] = 0.0f;
}
__global__ void zero_out_kernel(float* __restrict__ out, int n) {
    int i = blockIdx.x * blockDim.x + threadIdx.x;
    if (i < n) out[i] = 0.0f;
}
// split g_inc -> hi/lo and zero g_inc for the next step's atomics
__global__ void split_inc_kernel() {
    int i = blockIdx.x * blockDim.x + threadIdx.x;
    if (i < NROWS * MSG) {
        float v = g_inc[i];
        g_inc[i] = 0.0f;
        __nv_bfloat16 h, l;
        split_bf16(v, h, l);
        g_inc_hi[i] = h; g_inc_lo[i] = l;
    }
}
// WT[n][k] = W[k][n], rows n >= N zero-padded; W is [512][N] row-major
__global__ void splitT_kernel(const float* __restrict__ W,
                              __nv_bfloat16* __restrict__ hi,
                              __nv_bfloat16* __restrict__ lo, int N, int NT) {
    int i = blockIdx.x * blockDim.x + threadIdx.x;
    if (i < NT * 512) {
        int n = i >> 9, k = i & 511;
        float v = (n < N) ? W[k * N + n] : 0.0f;
        __nv_bfloat16 h, l;
        split_bf16(v, h, l);
        hi[i] = h; lo[i] = l;
    }
}

// ---------------------------------------------------------------------------
// Streaming mma.sync GEMM: D[128, 128] tile of A[rows, 512] @ W[512, Ntot]
//   MODE 0: edge GEMM1: A = gather [ns[src]|ns[snk]], epi relu->h hi/lo
//   MODE 1: edge GEMM2: A = h rows, epi bias + atomic scatter -> g_inc
//   MODE 2: node GEMM1: A = [inc|ns],  epi relu->h hi/lo
//   MODE 3: node GEMM2: A = h rows, epi bias + add -> g_ns (fused re-split)
// grid (m_tiles, n_chunks). 256 threads = 8 warps (2m x 4n), warp tile 64x32.
// K pipeline: 16 stages of k32, 3-stage cp.async ring, 96KB smem, 2 CTAs/SM.
// ---------------------------------------------------------------------------
#define KSTAGES 16
#define STAGE_SZ (32 * 1024)
#define AOF_HI 0
#define AOF_LO (8 * 1024)
#define BOF_HI (16 * 1024)
#define BOF_LO (24 * 1024)
#define SMEM_GEMM (3 * STAGE_SZ)

// swizzled address within a 128-row x 64B stage plane
__device__ __forceinline__ uint32_t plane_addr(int row, int cb) {
    return (uint32_t)(row * 64 + ((cb ^ ((row >> 1) & 3)) << 4));
}

template <int MODE>
__global__ __launch_bounds__(256, 2)
void gemm_kernel(const int* __restrict__ esrc, const int* __restrict__ esnk,
                 const float* __restrict__ bias)
{
    extern __shared__ char sm[];
    __shared__ int s_src[128], s_snk[128];

    const int tid  = threadIdx.x;
    const int wid  = tid >> 5, lane = tid & 31;
    const int r0   = blockIdx.x * 128;
    const int n0   = blockIdx.y * 128;
    int b = 0, e0 = 0;
    if (MODE == 0 || MODE == 1) { b = r0 >> 14; e0 = r0 & 16383; }

    const uint32_t smb = smem_u32(sm);

    if (MODE == 0) {
        if (tid < 128) s_src[tid]       = esrc[e0 + tid];
        else           s_snk[tid - 128] = esnk[e0 + tid - 128];
    } else if (MODE == 1) {
        if (tid < 128) s_snk[tid]       = esnk[e0 + tid];
    }
    __syncthreads();

    const __nv_bfloat16 *bt_hi, *bt_lo;
    if      (MODE == 0) { bt_hi = g_We1T_hi; bt_lo = g_We1T_lo; }
    else if (MODE == 1) { bt_hi = g_We2T_hi; bt_lo = g_We2T_lo; }
    else if (MODE == 2) { bt_hi = g_Wn1T_hi; bt_lo = g_Wn1T_lo; }
    else                { bt_hi = g_Wn2T_hi; bt_lo = g_Wn2T_lo; }

    auto load_stage = [&](int c, int buf) {
        uint32_t sb = smb + buf * STAGE_SZ;
        // A: 128 rows x 32 k (hi + lo)
        #pragma unroll
        for (int it = 0; it < 4; it++) {
            int u = tid + it * 256;
            int row = u >> 3, sub = u & 7;
            int hi = (sub < 4), cb = sub & 3;
            const __nv_bfloat16* src;
            if (MODE == 0) {
                int node = (c < 8) ? s_src[row] : s_snk[row];
                int k = (c & 7) * 32 + cb * 8;
                src = (hi ? g_ns_hi : g_ns_lo) + (size_t)(b * NN + node) * DD + k;
            } else if (MODE == 2) {
                int k = (c & 7) * 32 + cb * 8;
                src = (c < 8)
                    ? (hi ? g_inc_hi : g_inc_lo) + (size_t)(r0 + row) * MSG + k
                    : (hi ? g_ns_hi  : g_ns_lo ) + (size_t)(r0 + row) * DD  + k;
            } else {
                src = (hi ? g_h_hi : g_h_lo) + (size_t)(r0 + row) * HH + c * 32 + cb * 8;
            }
            cpa16(sb + (hi ? AOF_HI : AOF_LO) + plane_addr(row, cb), src);
        }
        // B: 128 n-rows x 32 k (hi + lo)
        #pragma unroll
        for (int it = 0; it < 4; it++) {
            int u = tid + it * 256;
            int row = u >> 3, sub = u & 7;
            int hi = (sub < 4), cb = sub & 3;
            const __nv_bfloat16* src =
                (hi ? bt_hi : bt_lo) + (size_t)(n0 + row) * 512 + c * 32 + cb * 8;
            cpa16(sb + (hi ? BOF_HI : BOF_LO) + plane_addr(row, cb), src);
        }
    };

    float acc[4][4][4];
    #pragma unroll
    for (int mi = 0; mi < 4; mi++)
        #pragma unroll
        for (int nj = 0; nj < 4; nj++)
            #pragma unroll
            for (int q = 0; q < 4; q++) acc[mi][nj][q] = 0.0f;

    load_stage(0, 0); CP_COMMIT();
    load_stage(1, 1); CP_COMMIT();
    load_stage(2, 2); CP_COMMIT();

    const int wm = wid & 1, wn = wid >> 1;           // 2m x 4n
    const int la15 = lane & 15, la_h = lane >> 4;
    const int lb_n = (lane & 7) + ((lane >> 4) << 3);
    const int lb_kh = (lane >> 3) & 1;
    const int rq = lane >> 2, cq = (lane & 3) * 2;

    #pragma unroll 1
    for (int c = 0; c < KSTAGES; c++) {
        CP_WAIT2();
        __syncthreads();
        uint32_t sb = smb + (c % 3) * STAGE_SZ;

        #pragma unroll
        for (int ks = 0; ks < 2; ks++) {
            uint32_t bh[2][4], bl[2][4];
            #pragma unroll
            for (int p = 0; p < 2; p++) {
                int row = wn * 32 + p * 16 + lb_n;
                uint32_t ad = sb + BOF_HI + plane_addr(row, ks * 2 + lb_kh);
                ldsm4(bh[p], ad);
                ldsm4(bl[p], ad + (BOF_LO - BOF_HI));
            }
            #pragma unroll
            for (int mi = 0; mi < 4; mi++) {
                int row = wm * 64 + mi * 16 + la15;
                uint32_t ad = sb + AOF_HI + plane_addr(row, ks * 2 + la_h);
                uint32_t ah[4], al[4];
                ldsm4(ah, ad);
                ldsm4(al, ad + (AOF_LO - AOF_HI));
                #pragma unroll
                for (int p = 0; p < 2; p++) {
                    mma_bf16(acc[mi][2 * p],     ah, bh[p][0], bh[p][1]);
                    mma_bf16(acc[mi][2 * p + 1], ah, bh[p][2], bh[p][3]);
                    mma_bf16(acc[mi][2 * p],     ah, bl[p][0], bl[p][1]);
                    mma_bf16(acc[mi][2 * p + 1], ah, bl[p][2], bl[p][3]);
                    mma_bf16(acc[mi][2 * p],     al, bh[p][0], bh[p][1]);
                    mma_bf16(acc[mi][2 * p + 1], al, bh[p][2], bh[p][3]);
                }
            }
        }
        __syncthreads();
        if (c + 3 < KSTAGES) load_stage(c + 3, c % 3);
        CP_COMMIT();
    }

    // ---- epilogue ----
    #pragma unroll
    for (int mi = 0; mi < 4; mi++) {
        #pragma unroll
        for (int nj = 0; nj < 4; nj++) {
            int col = n0 + wn * 32 + nj * 8 + cq;
            float* a4 = acc[mi][nj];
            if (MODE == 0 || MODE == 2) {
                float2 bv = *(const float2*)(bias + col);
                #pragma unroll
                for (int half = 0; half < 2; half++) {
                    int rl = wm * 64 + mi * 16 + rq + half * 8;
                    float v0 = fmaxf(a4[2 * half]     + bv.x, 0.0f);
                    float v1 = fmaxf(a4[2 * half + 1] + bv.y, 0.0f);
                    __nv_bfloat16 h0, l0, h1, l1;
                    split_bf16(v0, h0, l0);
                    split_bf16(v1, h1, l1);
                    uint32_t ph = ((uint32_t)__bfloat16_as_ushort(h1) << 16) | __bfloat16_as_ushort(h0);
                    uint32_t pl = ((uint32_t)__bfloat16_as_ushort(l1) << 16) | __bfloat16_as_ushort(l0);
                    size_t go = (size_t)(r0 + rl) * HH + col;
                    *(uint32_t*)(g_h_hi + go) = ph;
                    *(uint32_t*)(g_h_lo + go) = pl;
                }
            } else if (MODE == 1) {
                float2 bv = *(const float2*)(bias + col);
                #pragma unroll
                for (int half = 0; half < 2; half++) {
                    int rl = wm * 64 + mi * 16 + rq + half * 8;
                    float* p0 = g_inc + (size_t)(b * NN + s_snk[rl]) * MSG + col;
                    atomicAdd(p0,     a4[2 * half]     + bv.x);
                    atomicAdd(p0 + 1, a4[2 * half + 1] + bv.y);
                }
            } else {  // MODE 3
                #pragma unroll
                for (int half = 0; half < 2; half++) {
                    int rl = wm * 64 + mi * 16 + rq + half * 8;
                    size_t ro = (size_t)(r0 + rl) * DD + 2;
                    if (col < UPD) {
                        float nv = g_ns[ro + col] + a4[2 * half] + bias[col];
                        g_ns[ro + col] = nv;
                        __nv_bfloat16 h, l;
                        split_bf16(nv, h, l);
                        g_ns_hi[ro + col] = h; g_ns_lo[ro + col] = l;
                    }
                    if (col + 1 < UPD) {
                        float nv = g_ns[ro + col + 1] + a4[2 * half + 1] + bias[col + 1];
                        g_ns[ro + col + 1] = nv;
                        __nv_bfloat16 h, l;
                        split_bf16(nv, h, l);
                        g_ns_hi[ro + col + 1] = h; g_ns_lo[ro + col + 1] = l;
                    }
                }
            }
        }
    }
}

// ---------------------------------------------------------------------------
// Extraction (FFMA2 SIMT)
// ---------------------------------------------------------------------------
__device__ __forceinline__ u64 ffma2(u64 a, u64 b, u64 c) {
    u64 d; asm("fma.rn.f32x2 %0, %1, %2, %3;" : "=l"(d) : "l"(a), "l"(b), "l"(c)); return d;
}
__device__ __forceinline__ u64 pack2(float lo, float hi) {
    u64 d; asm("mov.b64 %0, {%1, %2};" : "=l"(d) : "f"(lo), "f"(hi)); return d;
}
__device__ __forceinline__ void unpack2(u64 v, float& lo, float& hi) {
    asm("mov.b64 {%0, %1}, %2;" : "=f"(lo), "=f"(hi) : "l"(v));
}

__global__ __launch_bounds__(256)
void extract_kernel(const float* __restrict__ attn, float* __restrict__ out)
{
    extern __shared__ float smA[];   // 256 * 66
    const int tid = threadIdx.x;
    const int b   = blockIdx.y;
    const int n0  = blockIdx.x * 256;
    const float* __restrict__ nsb = g_ns + (size_t)b * NN * DD;

    #pragma unroll 4
    for (int idx = tid; idx < 64 * 256; idx += 256) {
        int p = idx >> 8, j = idx & 255;
        smA[j * 66 + p] = attn[((size_t)b * PP + p) * NN + n0 + j];
    }
    __syncthreads();

    const int d = tid;
    u64 accp[32];
    #pragma unroll
    for (int pj = 0; pj < 32; pj++) accp[pj] = 0ull;

    for (int n = 0; n < 256; n++) {
        float s = nsb[(n0 + n) * DD + d];
        u64 sp = pack2(s, s);
        const u64* arow = (const u64*)(smA + n * 66);
        #pragma unroll
        for (int pj = 0; pj < 32; pj++) accp[pj] = ffma2(arow[pj], sp, accp[pj]);
    }
    #pragma unroll
    for (int pj = 0; pj < 32; pj++) {
        float lo, hi; unpack2(accp[pj], lo, hi);
        atomicAdd(&out[((size_t)b * PP + 2 * pj)     * DD + d], lo);
        atomicAdd(&out[((size_t)b * PP + 2 * pj + 1) * DD + d], hi);
    }
}

// ---------------------------------------------------------------------------
extern "C" void kernel_launch(void* const* d_in, const int* in_sizes, int n_in,
                              void* d_out, int out_size)
{
    const float* nodes = (const float*)d_in[0];
    const float* attn  = (const float*)d_in[1];
    const float* We1   = (const float*)d_in[2];
    const float* be1   = (const float*)d_in[3];
    const float* We2   = (const float*)d_in[4];
    const float* be2   = (const float*)d_in[5];
    const float* Wn1   = (const float*)d_in[6];
    const float* bn1   = (const float*)d_in[7];
    const float* Wn2   = (const float*)d_in[8];
    const float* bn2   = (const float*)d_in[9];
    const int*   esrc  = (const int*)d_in[10];
    const int*   esnk  = (const int*)d_in[11];
    float* out = (float*)d_out;

    cudaFuncSetAttribute(gemm_kernel<0>, cudaFuncAttributeMaxDynamicSharedMemorySize, SMEM_GEMM);
    cudaFuncSetAttribute(gemm_kernel<1>, cudaFuncAttributeMaxDynamicSharedMemorySize, SMEM_GEMM);
    cudaFuncSetAttribute(gemm_kernel<2>, cudaFuncAttributeMaxDynamicSharedMemorySize, SMEM_GEMM);
    cudaFuncSetAttribute(gemm_kernel<3>, cudaFuncAttributeMaxDynamicSharedMemorySize, SMEM_GEMM);
    const int SMEM_EXT = 256 * 66 * 4;
    cudaFuncSetAttribute(extract_kernel, cudaFuncAttributeMaxDynamicSharedMemorySize, SMEM_EXT);

    __nv_bfloat16 *we1h, *we1l, *we2h, *we2l, *wn1h, *wn1l, *wn2h, *wn2l;
    cudaGetSymbolAddress((void**)&we1h, g_We1T_hi); cudaGetSymbolAddress((void**)&we1l, g_We1T_lo);
    cudaGetSymbolAddress((void**)&we2h, g_We2T_hi); cudaGetSymbolAddress((void**)&we2l, g_We2T_lo);
    cudaGetSymbolAddress((void**)&wn1h, g_Wn1T_hi); cudaGetSymbolAddress((void**)&wn1l, g_Wn1T_lo);
    cudaGetSymbolAddress((void**)&wn2h, g_Wn2T_hi); cudaGetSymbolAddress((void**)&wn2l, g_Wn2T_lo);
    splitT_kernel<<<(HH  * 512 + 255) / 256, 256>>>(We1, we1h, we1l, HH,  HH);
    splitT_kernel<<<(MSG * 512 + 255) / 256, 256>>>(We2, we2h, we2l, MSG, MSG);
    splitT_kernel<<<(HH  * 512 + 255) / 256, 256>>>(Wn1, wn1h, wn1l, HH,  HH);
    splitT_kernel<<<(256 * 512 + 255) / 256, 256>>>(Wn2, wn2h, wn2l, UPD, 256);

    copy_split_ns_kernel<<<(NROWS * DD + 255) / 256, 256>>>(nodes);
    zero_inc_kernel<<<(NROWS * MSG + 255) / 256, 256>>>();

    for (int s = 0; s < STEPS; s++) {
        gemm_kernel<0><<<dim3(EROWS / 128, 4), 256, SMEM_GEMM>>>(esrc, esnk, be1);
        gemm_kernel<1><<<dim3(EROWS / 128, 2), 256, SMEM_GEMM>>>(esrc, esnk, be2);
        split_inc_kernel<<<(NROWS * MSG + 255) / 256, 256>>>();   // also re-zeroes g_inc
        gemm_kernel<2><<<dim3(NROWS / 128, 4), 256, SMEM_GEMM>>>(esrc, esnk, bn1);
        gemm_kernel<3><<<dim3(NROWS / 128, 2), 256, SMEM_GEMM>>>(esrc, esnk, bn2);
    }

    zero_out_kernel<<<(BB * PP * DD + 255) / 256, 256>>>(out, BB * PP * DD);
    extract_kernel<<<dim3(NN / 256, BB), 256, SMEM_EXT>>>(attn, out);
}

// round 7
// speedup vs baseline: 3.8677x; 1.1097x over previous
#include <cuda_runtime.h>
#include <cuda_bf16.h>
#include <cstdint>

#define BB   8
#define NN   4096
#define EE   16384
#define PP   64
#define DD   256
#define HH   512
#define MSG  256
#define UPD  254
#define STEPS 3

#define EROWS (BB * EE)   // 131072
#define NROWS (BB * NN)   // 32768

typedef unsigned long long u64;

// ---------------------------------------------------------------------------
// Device globals
// ---------------------------------------------------------------------------
__device__ float g_ns  [NROWS * DD];            // fp32 node state
__device__ float g_PQ  [(size_t)NROWS * 1024];  // P (cols 0..511) | Q (cols 512..1023)
__device__ float g_hacc[(size_t)NROWS * HH];    // scatter-accumulated edge hidden
__device__ float g_degf[NN];                    // per-node in-degree (float)

__device__ __nv_bfloat16 g_ns_hi [NROWS * DD],  g_ns_lo [NROWS * DD];
__device__ __nv_bfloat16 g_inc_hi[NROWS * MSG], g_inc_lo[NROWS * MSG];
__device__ __nv_bfloat16 g_hacc_hi[NROWS * HH], g_hacc_lo[NROWS * HH];
__device__ __nv_bfloat16 g_h_hi[(size_t)NROWS * HH], g_h_lo[(size_t)NROWS * HH];

// transposed + split weights (WT[n][k])
__device__ __nv_bfloat16 g_WPQT_hi[1024 * 256], g_WPQT_lo[1024 * 256];
__device__ __nv_bfloat16 g_We2T_hi[MSG * 512],  g_We2T_lo[MSG * 512];
__device__ __nv_bfloat16 g_Wn1T_hi[HH * 512],   g_Wn1T_lo[HH * 512];
__device__ __nv_bfloat16 g_Wn2T_hi[256 * 512],  g_Wn2T_lo[256 * 512];

// ---------------------------------------------------------------------------
// PTX helpers
// ---------------------------------------------------------------------------
__device__ __forceinline__ uint32_t smem_u32(const void* p) {
    uint32_t a;
    asm("{ .reg .u64 t; cvta.to.shared.u64 t, %1; cvt.u32.u64 %0, t; }" : "=r"(a) : "l"(p));
    return a;
}
__device__ __forceinline__ void ldsm4(uint32_t* r, uint32_t a) {
    asm volatile("ldmatrix.sync.aligned.m8n8.x4.shared.b16 {%0,%1,%2,%3}, [%4];"
        : "=r"(r[0]), "=r"(r[1]), "=r"(r[2]), "=r"(r[3]) : "r"(a));
}
__device__ __forceinline__ void mma_bf16(float* c, const uint32_t* a, uint32_t b0, uint32_t b1) {
    asm volatile("mma.sync.aligned.m16n8k16.row.col.f32.bf16.bf16.f32 "
        "{%0,%1,%2,%3}, {%4,%5,%6,%7}, {%8,%9}, {%0,%1,%2,%3};"
        : "+f"(c[0]), "+f"(c[1]), "+f"(c[2]), "+f"(c[3])
        : "r"(a[0]), "r"(a[1]), "r"(a[2]), "r"(a[3]), "r"(b0), "r"(b1));
}
__device__ __forceinline__ void cpa16(uint32_t d, const void* s) {
    asm volatile("cp.async.cg.shared.global [%0], [%1], 16;" :: "r"(d), "l"(s) : "memory");
}
#define CP_COMMIT() asm volatile("cp.async.commit_group;" ::: "memory")
#define CP_WAIT2()  asm volatile("cp.async.wait_group 2;" ::: "memory")

__device__ __forceinline__ void split_bf16(float v, __nv_bfloat16& hi, __nv_bfloat16& lo) {
    hi = __float2bfloat16_rn(v);
    lo = __float2bfloat16_rn(v - __bfloat162float(hi));
}

// ---------------------------------------------------------------------------
// Utility kernels
// ---------------------------------------------------------------------------
__global__ void copy_split_ns_kernel(const float* __restrict__ src) {
    int i = blockIdx.x * blockDim.x + threadIdx.x;
    if (i < NROWS * DD) {
        float v = src[i];
        g_ns[i] = v;
        __nv_bfloat16 h, l;
        split_bf16(v, h, l);
        g_ns_hi[i] = h; g_ns_lo[i] = l;
    }
}
__global__ void zero_hacc_kernel() {
    int i = blockIdx.x * blockDim.x + threadIdx.x;
    if (i < NROWS * HH) g_hacc[i] = 0.0f;
}
__global__ void zero_out_kernel(float* __restrict__ out, int n) {
    int i = blockIdx.x * blockDim.x + threadIdx.x;
    if (i < n) out[i] = 0.0f;
}
__global__ void zero_degf_kernel() {
    int i = blockIdx.x * blockDim.x + threadIdx.x;
    if (i < NN) g_degf[i] = 0.0f;
}
__global__ void count_deg_kernel(const int* __restrict__ esnk) {
    int i = blockIdx.x * blockDim.x + threadIdx.x;
    if (i < EE) atomicAdd(&g_degf[esnk[i]], 1.0f);
}
// split g_hacc -> hi/lo and zero it for the next step's atomics
__global__ void split_hacc_kernel() {
    int i = blockIdx.x * blockDim.x + threadIdx.x;
    if (i < NROWS * HH) {
        float v = g_hacc[i];
        g_hacc[i] = 0.0f;
        __nv_bfloat16 h, l;
        split_bf16(v, h, l);
        g_hacc_hi[i] = h; g_hacc_lo[i] = l;
    }
}
// WT[n][k] = W[k][n], rows n >= N zero-padded; W is [512][N] row-major
__global__ void splitT_kernel(const float* __restrict__ W,
                              __nv_bfloat16* __restrict__ hi,
                              __nv_bfloat16* __restrict__ lo, int N, int NT) {
    int i = blockIdx.x * blockDim.x + threadIdx.x;
    if (i < NT * 512) {
        int n = i >> 9, k = i & 511;
        float v = (n < N) ? W[k * N + n] : 0.0f;
        __nv_bfloat16 h, l;
        split_bf16(v, h, l);
        hi[i] = h; lo[i] = l;
    }
}
// WPQT[n][k], n in [0,1024), k in [0,256):
//   n < 512  -> We1[k][n]        (top half of We1: rows 0..255)
//   n >= 512 -> We1[256+k][n-512] (bottom half: rows 256..511)
__global__ void splitT_PQ_kernel(const float* __restrict__ We1) {
    int i = blockIdx.x * blockDim.x + threadIdx.x;
    if (i < 1024 * 256) {
        int n = i >> 8, k = i & 255;
        float v = (n < 512) ? We1[k * HH + n] : We1[(256 + k) * HH + (n - 512)];
        __nv_bfloat16 h, l;
        split_bf16(v, h, l);
        g_WPQT_hi[i] = h; g_WPQT_lo[i] = l;
    }
}

// ---------------------------------------------------------------------------
// edge_combine: h_e = relu(P[src] + Q[snk] + b_e1); g_hacc[snk] += h_e
// grid (EE, BB), block 128; each thread: one float4 of the 512-wide row.
// ---------------------------------------------------------------------------
__global__ __launch_bounds__(128)
void edge_combine_kernel(const int* __restrict__ esrc, const int* __restrict__ esnk,
                         const float* __restrict__ be1)
{
    const int e = blockIdx.x, b = blockIdx.y, t = threadIdx.x;
    const int src = esrc[e], snk = esnk[e];
    const float4 p = ((const float4*)(g_PQ + ((size_t)(b * NN + src)) * 1024))[t];
    const float4 q = ((const float4*)(g_PQ + ((size_t)(b * NN + snk)) * 1024 + 512))[t];
    const float4 bb = ((const float4*)be1)[t];
    float4 v;
    v.x = fmaxf(p.x + q.x + bb.x, 0.0f);
    v.y = fmaxf(p.y + q.y + bb.y, 0.0f);
    v.z = fmaxf(p.z + q.z + bb.z, 0.0f);
    v.w = fmaxf(p.w + q.w + bb.w, 0.0f);
    float* H = g_hacc + ((size_t)(b * NN + snk)) * HH + 4 * t;
    atomicAdd(H + 0, v.x);
    atomicAdd(H + 1, v.y);
    atomicAdd(H + 2, v.z);
    atomicAdd(H + 3, v.w);
}

// ---------------------------------------------------------------------------
// Streaming mma.sync GEMM over dense node rows. 128x128 CTA tile.
//   MODE 0 (KST=8):  PQ = ns @ WPQ            epi: store fp32 -> g_PQ
//   MODE 1 (KST=16): pre-inc = hacc @ We2     epi: +deg*b_e2, split -> inc hi/lo
//   MODE 2 (KST=16): h = relu([inc|ns]@Wn1+b) epi: split -> g_h hi/lo
//   MODE 3 (KST=16): ns += h@Wn2+b            epi: add + re-split ns
// 256 threads = 8 warps (2m x 4n), warp tile 64x32; 3-stage cp.async ring.
// ---------------------------------------------------------------------------
#define STAGE_SZ (32 * 1024)
#define AOF_HI 0
#define AOF_LO (8 * 1024)
#define BOF_HI (16 * 1024)
#define BOF_LO (24 * 1024)
#define SMEM_GEMM (3 * STAGE_SZ)

__device__ __forceinline__ uint32_t plane_addr(int row, int cb) {
    return (uint32_t)(row * 64 + ((cb ^ ((row >> 1) & 3)) << 4));
}

template <int MODE, int KST>
__global__ __launch_bounds__(256, 2)
void gemm_kernel(const float* __restrict__ bias)
{
    extern __shared__ char sm[];
    const int tid  = threadIdx.x;
    const int wid  = tid >> 5, lane = tid & 31;
    const int r0   = blockIdx.x * 128;
    const int n0   = blockIdx.y * 128;
    const uint32_t smb = smem_u32(sm);

    const __nv_bfloat16 *bt_hi, *bt_lo;
    if      (MODE == 0) { bt_hi = g_WPQT_hi; bt_lo = g_WPQT_lo; }
    else if (MODE == 1) { bt_hi = g_We2T_hi; bt_lo = g_We2T_lo; }
    else if (MODE == 2) { bt_hi = g_Wn1T_hi; bt_lo = g_Wn1T_lo; }
    else                { bt_hi = g_Wn2T_hi; bt_lo = g_Wn2T_lo; }
    const int BSTR = (MODE == 0) ? 256 : 512;

    auto load_stage = [&](int c, int buf) {
        uint32_t sb = smb + buf * STAGE_SZ;
        #pragma unroll
        for (int it = 0; it < 4; it++) {
            int u = tid + it * 256;
            int row = u >> 3, sub = u & 7;
            int hi = (sub < 4), cb = sub & 3;
            int k = (c & 7) * 32 + cb * 8;
            const __nv_bfloat16* src;
            if (MODE == 0) {
                src = (hi ? g_ns_hi : g_ns_lo) + (size_t)(r0 + row) * DD + c * 32 + cb * 8;
            } else if (MODE == 1) {
                src = (hi ? g_hacc_hi : g_hacc_lo) + (size_t)(r0 + row) * HH + c * 32 + cb * 8;
            } else if (MODE == 2) {
                src = (c < 8)
                    ? (hi ? g_inc_hi : g_inc_lo) + (size_t)(r0 + row) * MSG + k
                    : (hi ? g_ns_hi  : g_ns_lo ) + (size_t)(r0 + row) * DD  + k;
            } else {
                src = (hi ? g_h_hi : g_h_lo) + (size_t)(r0 + row) * HH + c * 32 + cb * 8;
            }
            cpa16(sb + (hi ? AOF_HI : AOF_LO) + plane_addr(row, cb), src);
        }
        #pragma unroll
        for (int it = 0; it < 4; it++) {
            int u = tid + it * 256;
            int row = u >> 3, sub = u & 7;
            int hi = (sub < 4), cb = sub & 3;
            const __nv_bfloat16* src =
                (hi ? bt_hi : bt_lo) + (size_t)(n0 + row) * BSTR + c * 32 + cb * 8;
            cpa16(sb + (hi ? BOF_HI : BOF_LO) + plane_addr(row, cb), src);
        }
    };

    float acc[4][4][4];
    #pragma unroll
    for (int mi = 0; mi < 4; mi++)
        #pragma unroll
        for (int nj = 0; nj < 4; nj++)
            #pragma unroll
            for (int q = 0; q < 4; q++) acc[mi][nj][q] = 0.0f;

    load_stage(0, 0); CP_COMMIT();
    load_stage(1, 1); CP_COMMIT();
    load_stage(2, 2); CP_COMMIT();

    const int wm = wid & 1, wn = wid >> 1;
    const int la15 = lane & 15, la_h = lane >> 4;
    const int lb_n = (lane & 7) + ((lane >> 4) << 3);
    const int lb_kh = (lane >> 3) & 1;
    const int rq = lane >> 2, cq = (lane & 3) * 2;

    #pragma unroll 1
    for (int c = 0; c < KST; c++) {
        CP_WAIT2();
        __syncthreads();
        uint32_t sb = smb + (c % 3) * STAGE_SZ;

        #pragma unroll
        for (int ks = 0; ks < 2; ks++) {
            uint32_t bh[2][4], bl[2][4];
            #pragma unroll
            for (int p = 0; p < 2; p++) {
                int row = wn * 32 + p * 16 + lb_n;
                uint32_t ad = sb + BOF_HI + plane_addr(row, ks * 2 + lb_kh);
                ldsm4(bh[p], ad);
                ldsm4(bl[p], ad + (BOF_LO - BOF_HI));
            }
            #pragma unroll
            for (int mi = 0; mi < 4; mi++) {
                int row = wm * 64 + mi * 16 + la15;
                uint32_t ad = sb + AOF_HI + plane_addr(row, ks * 2 + la_h);
                uint32_t ah[4], al[4];
                ldsm4(ah, ad);
                ldsm4(al, ad + (AOF_LO - AOF_HI));
                #pragma unroll
                for (int p = 0; p < 2; p++) {
                    mma_bf16(acc[mi][2 * p],     ah, bh[p][0], bh[p][1]);
                    mma_bf16(acc[mi][2 * p + 1], ah, bh[p][2], bh[p][3]);
                    mma_bf16(acc[mi][2 * p],     ah, bl[p][0], bl[p][1]);
                    mma_bf16(acc[mi][2 * p + 1], ah, bl[p][2], bl[p][3]);
                    mma_bf16(acc[mi][2 * p],     al, bh[p][0], bh[p][1]);
                    mma_bf16(acc[mi][2 * p + 1], al, bh[p][2], bh[p][3]);
                }
            }
        }
        __syncthreads();
        if (c + 3 < KST) load_stage(c + 3, c % 3);
        CP_COMMIT();
    }

    // ---- epilogue ----
    #pragma unroll
    for (int mi = 0; mi < 4; mi++) {
        #pragma unroll
        for (int nj = 0; nj < 4; nj++) {
            int col = n0 + wn * 32 + nj * 8 + cq;
            float* a4 = acc[mi][nj];
            if (MODE == 0) {
                #pragma unroll
                for (int half = 0; half < 2; half++) {
                    int rl = wm * 64 + mi * 16 + rq + half * 8;
                    float2 st = { a4[2 * half], a4[2 * half + 1] };
                    *(float2*)(g_PQ + (size_t)(r0 + rl) * 1024 + col) = st;
                }
            } else if (MODE == 1) {
                float2 bv = *(const float2*)(bias + col);
                #pragma unroll
                for (int half = 0; half < 2; half++) {
                    int rl = wm * 64 + mi * 16 + rq + half * 8;
                    float dg = g_degf[(r0 + rl) & (NN - 1)];
                    float v0 = a4[2 * half]     + dg * bv.x;
                    float v1 = a4[2 * half + 1] + dg * bv.y;
                    __nv_bfloat16 h0, l0, h1, l1;
                    split_bf16(v0, h0, l0);
                    split_bf16(v1, h1, l1);
                    uint32_t ph = ((uint32_t)__bfloat16_as_ushort(h1) << 16) | __bfloat16_as_ushort(h0);
                    uint32_t pl = ((uint32_t)__bfloat16_as_ushort(l1) << 16) | __bfloat16_as_ushort(l0);
                    size_t go = (size_t)(r0 + rl) * MSG + col;
                    *(uint32_t*)(g_inc_hi + go) = ph;
                    *(uint32_t*)(g_inc_lo + go) = pl;
                }
            } else if (MODE == 2) {
                float2 bv = *(const float2*)(bias + col);
                #pragma unroll
                for (int half = 0; half < 2; half++) {
                    int rl = wm * 64 + mi * 16 + rq + half * 8;
                    float v0 = fmaxf(a4[2 * half]     + bv.x, 0.0f);
                    float v1 = fmaxf(a4[2 * half + 1] + bv.y, 0.0f);
                    __nv_bfloat16 h0, l0, h1, l1;
                    split_bf16(v0, h0, l0);
                    split_bf16(v1, h1, l1);
                    uint32_t ph = ((uint32_t)__bfloat16_as_ushort(h1) << 16) | __bfloat16_as_ushort(h0);
                    uint32_t pl = ((uint32_t)__bfloat16_as_ushort(l1) << 16) | __bfloat16_as_ushort(l0);
                    size_t go = (size_t)(r0 + rl) * HH + col;
                    *(uint32_t*)(g_h_hi + go) = ph;
                    *(uint32_t*)(g_h_lo + go) = pl;
                }
            } else {  // MODE 3
                #pragma unroll
                for (int half = 0; half < 2; half++) {
                    int rl = wm * 64 + mi * 16 + rq + half * 8;
                    size_t ro = (size_t)(r0 + rl) * DD + 2;
                    if (col < UPD) {
                        float nv = g_ns[ro + col] + a4[2 * half] + bias[col];
                        g_ns[ro + col] = nv;
                        __nv_bfloat16 h, l;
                        split_bf16(nv, h, l);
                        g_ns_hi[ro + col] = h; g_ns_lo[ro + col] = l;
                    }
                    if (col + 1 < UPD) {
                        float nv = g_ns[ro + col + 1] + a4[2 * half + 1] + bias[col + 1];
                        g_ns[ro + col + 1] = nv;
                        __nv_bfloat16 h, l;
                        split_bf16(nv, h, l);
                        g_ns_hi[ro + col + 1] = h; g_ns_lo[ro + col + 1] = l;
                    }
                }
            }
        }
    }
}

// ---------------------------------------------------------------------------
// Extraction (FFMA2 SIMT)
// ---------------------------------------------------------------------------
__device__ __forceinline__ u64 ffma2(u64 a, u64 b, u64 c) {
    u64 d; asm("fma.rn.f32x2 %0, %1, %2, %3;" : "=l"(d) : "l"(a), "l"(b), "l"(c)); return d;
}
__device__ __forceinline__ u64 pack2(float lo, float hi) {
    u64 d; asm("mov.b64 %0, {%1, %2};" : "=l"(d) : "f"(lo), "f"(hi)); return d;
}
__device__ __forceinline__ void unpack2(u64 v, float& lo, float& hi) {
    asm("mov.b64 {%0, %1}, %2;" : "=f"(lo), "=f"(hi) : "l"(v));
}

__global__ __launch_bounds__(256)
void extract_kernel(const float* __restrict__ attn, float* __restrict__ out)
{
    extern __shared__ float smA[];   // 256 * 66
    const int tid = threadIdx.x;
    const int b   = blockIdx.y;
    const int n0  = blockIdx.x * 256;
    const float* __restrict__ nsb = g_ns + (size_t)b * NN * DD;

    #pragma unroll 4
    for (int idx = tid; idx < 64 * 256; idx += 256) {
        int p = idx >> 8, j = idx & 255;
        smA[j * 66 + p] = attn[((size_t)b * PP + p) * NN + n0 + j];
    }
    __syncthreads();

    const int d = tid;
    u64 accp[32];
    #pragma unroll
    for (int pj = 0; pj < 32; pj++) accp[pj] = 0ull;

    for (int n = 0; n < 256; n++) {
        float s = nsb[(n0 + n) * DD + d];
        u64 sp = pack2(s, s);
        const u64* arow = (const u64*)(smA + n * 66);
        #pragma unroll
        for (int pj = 0; pj < 32; pj++) accp[pj] = ffma2(arow[pj], sp, accp[pj]);
    }
    #pragma unroll
    for (int pj = 0; pj < 32; pj++) {
        float lo, hi; unpack2(accp[pj], lo, hi);
        atomicAdd(&out[((size_t)b * PP + 2 * pj)     * DD + d], lo);
        atomicAdd(&out[((size_t)b * PP + 2 * pj + 1) * DD + d], hi);
    }
}

// ---------------------------------------------------------------------------
extern "C" void kernel_launch(void* const* d_in, const int* in_sizes, int n_in,
                              void* d_out, int out_size)
{
    const float* nodes = (const float*)d_in[0];
    const float* attn  = (const float*)d_in[1];
    const float* We1   = (const float*)d_in[2];
    const float* be1   = (const float*)d_in[3];
    const float* We2   = (const float*)d_in[4];
    const float* be2   = (const float*)d_in[5];
    const float* Wn1   = (const float*)d_in[6];
    const float* bn1   = (const float*)d_in[7];
    const float* Wn2   = (const float*)d_in[8];
    const float* bn2   = (const float*)d_in[9];
    const int*   esrc  = (const int*)d_in[10];
    const int*   esnk  = (const int*)d_in[11];
    float* out = (float*)d_out;

    cudaFuncSetAttribute((const void*)gemm_kernel<0, 8>,  cudaFuncAttributeMaxDynamicSharedMemorySize, SMEM_GEMM);
    cudaFuncSetAttribute((const void*)gemm_kernel<1, 16>, cudaFuncAttributeMaxDynamicSharedMemorySize, SMEM_GEMM);
    cudaFuncSetAttribute((const void*)gemm_kernel<2, 16>, cudaFuncAttributeMaxDynamicSharedMemorySize, SMEM_GEMM);
    cudaFuncSetAttribute((const void*)gemm_kernel<3, 16>, cudaFuncAttributeMaxDynamicSharedMemorySize, SMEM_GEMM);
    const int SMEM_EXT = 256 * 66 * 4;
    cudaFuncSetAttribute((const void*)extract_kernel, cudaFuncAttributeMaxDynamicSharedMemorySize, SMEM_EXT);

    __nv_bfloat16 *we2h, *we2l, *wn1h, *wn1l, *wn2h, *wn2l;
    cudaGetSymbolAddress((void**)&we2h, g_We2T_hi); cudaGetSymbolAddress((void**)&we2l, g_We2T_lo);
    cudaGetSymbolAddress((void**)&wn1h, g_Wn1T_hi); cudaGetSymbolAddress((void**)&wn1l, g_Wn1T_lo);
    cudaGetSymbolAddress((void**)&wn2h, g_Wn2T_hi); cudaGetSymbolAddress((void**)&wn2l, g_Wn2T_lo);

    splitT_PQ_kernel<<<(1024 * 256 + 255) / 256, 256>>>(We1);
    splitT_kernel<<<(MSG * 512 + 255) / 256, 256>>>(We2, we2h, we2l, MSG, MSG);
    splitT_kernel<<<(HH  * 512 + 255) / 256, 256>>>(Wn1, wn1h, wn1l, HH,  HH);
    splitT_kernel<<<(256 * 512 + 255) / 256, 256>>>(Wn2, wn2h, wn2l, UPD, 256);

    zero_degf_kernel<<<(NN + 255) / 256, 256>>>();
    count_deg_kernel<<<(EE + 255) / 256, 256>>>(esnk);

    copy_split_ns_kernel<<<(NROWS * DD + 255) / 256, 256>>>(nodes);
    zero_hacc_kernel<<<(NROWS * HH + 255) / 256, 256>>>();

    for (int s = 0; s < STEPS; s++) {
        gemm_kernel<0, 8><<<dim3(NROWS / 128, 8), 256, SMEM_GEMM>>>(nullptr);  // PQ
        edge_combine_kernel<<<dim3(EE, BB), 128>>>(esrc, esnk, be1);           // hacc
        split_hacc_kernel<<<(NROWS * HH + 255) / 256, 256>>>();                // + zero
        gemm_kernel<1, 16><<<dim3(NROWS / 128, 2), 256, SMEM_GEMM>>>(be2);     // inc
        gemm_kernel<2, 16><<<dim3(NROWS / 128, 4), 256, SMEM_GEMM>>>(bn1);     // h
        gemm_kernel<3, 16><<<dim3(NROWS / 128, 2), 256, SMEM_GEMM>>>(bn2);     // ns +=
    }

    zero_out_kernel<<<(BB * PP * DD + 255) / 256, 256>>>(out, BB * PP * DD);
    extract_kernel<<<dim3(NN / 256, BB), 256, SMEM_EXT>>>(attn, out);
}

// round 8
// speedup vs baseline: 8.1024x; 2.0949x over previous
#include <cuda_runtime.h>
#include <cuda_bf16.h>
#include <cstdint>

#define BB   8
#define NN   4096
#define EE   16384
#define PP   64
#define DD   256
#define HH   512
#define MSG  256
#define UPD  254
#define STEPS 3

#define NROWS (BB * NN)   // 32768
#define ADJ_CAP 64        // max in-degree capacity (Binomial(16384,1/4096): P(>64) ~ 0)

typedef unsigned long long u64;

// ---------------------------------------------------------------------------
// Device globals
// ---------------------------------------------------------------------------
__device__ float g_ns  [NROWS * DD];            // fp32 node state
__device__ float g_PQ  [(size_t)NROWS * 1024];  // P (cols 0..511) | Q (cols 512..1023)
__device__ float g_degf[NN];                    // true in-degree (float, for bias)
__device__ int   g_deg [NN];                    // in-degree counter
__device__ int   g_adj [NN * ADJ_CAP];          // per-sink source lists

__device__ __nv_bfloat16 g_ns_hi [NROWS * DD],  g_ns_lo [NROWS * DD];
__device__ __nv_bfloat16 g_inc_hi[NROWS * MSG], g_inc_lo[NROWS * MSG];
__device__ __nv_bfloat16 g_hacc_hi[NROWS * HH], g_hacc_lo[NROWS * HH];
__device__ __nv_bfloat16 g_h_hi[(size_t)NROWS * HH], g_h_lo[(size_t)NROWS * HH];

// transposed + split weights (WT[n][k])
__device__ __nv_bfloat16 g_WPQT_hi[1024 * 256], g_WPQT_lo[1024 * 256];
__device__ __nv_bfloat16 g_We2T_hi[MSG * 512],  g_We2T_lo[MSG * 512];
__device__ __nv_bfloat16 g_Wn1T_hi[HH * 512],   g_Wn1T_lo[HH * 512];
__device__ __nv_bfloat16 g_Wn2T_hi[256 * 512],  g_Wn2T_lo[256 * 512];

// ---------------------------------------------------------------------------
// PTX helpers
// ---------------------------------------------------------------------------
__device__ __forceinline__ uint32_t smem_u32(const void* p) {
    uint32_t a;
    asm("{ .reg .u64 t; cvta.to.shared.u64 t, %1; cvt.u32.u64 %0, t; }" : "=r"(a) : "l"(p));
    return a;
}
__device__ __forceinline__ void ldsm4(uint32_t* r, uint32_t a) {
    asm volatile("ldmatrix.sync.aligned.m8n8.x4.shared.b16 {%0,%1,%2,%3}, [%4];"
        : "=r"(r[0]), "=r"(r[1]), "=r"(r[2]), "=r"(r[3]) : "r"(a));
}
__device__ __forceinline__ void mma_bf16(float* c, const uint32_t* a, uint32_t b0, uint32_t b1) {
    asm volatile("mma.sync.aligned.m16n8k16.row.col.f32.bf16.bf16.f32 "
        "{%0,%1,%2,%3}, {%4,%5,%6,%7}, {%8,%9}, {%0,%1,%2,%3};"
        : "+f"(c[0]), "+f"(c[1]), "+f"(c[2]), "+f"(c[3])
        : "r"(a[0]), "r"(a[1]), "r"(a[2]), "r"(a[3]), "r"(b0), "r"(b1));
}
__device__ __forceinline__ void cpa16(uint32_t d, const void* s) {
    asm volatile("cp.async.cg.shared.global [%0], [%1], 16;" :: "r"(d), "l"(s) : "memory");
}
#define CP_COMMIT() asm volatile("cp.async.commit_group;" ::: "memory")
#define CP_WAIT2()  asm volatile("cp.async.wait_group 2;" ::: "memory")

__device__ __forceinline__ void split_bf16(float v, __nv_bfloat16& hi, __nv_bfloat16& lo) {
    hi = __float2bfloat16_rn(v);
    lo = __float2bfloat16_rn(v - __bfloat162float(hi));
}
__device__ __forceinline__ uint32_t pack_bf16x2(__nv_bfloat16 a, __nv_bfloat16 b) {
    return ((uint32_t)__bfloat16_as_ushort(b) << 16) | __bfloat16_as_ushort(a);
}

// ---------------------------------------------------------------------------
// Utility kernels
// ---------------------------------------------------------------------------
__global__ void copy_split_ns_kernel(const float* __restrict__ src) {
    int i = blockIdx.x * blockDim.x + threadIdx.x;
    if (i < NROWS * DD) {
        float v = src[i];
        g_ns[i] = v;
        __nv_bfloat16 h, l;
        split_bf16(v, h, l);
        g_ns_hi[i] = h; g_ns_lo[i] = l;
    }
}
__global__ void zero_out_kernel(float* __restrict__ out, int n) {
    int i = blockIdx.x * blockDim.x + threadIdx.x;
    if (i < n) out[i] = 0.0f;
}
__global__ void zero_deg_kernel() {
    int i = blockIdx.x * blockDim.x + threadIdx.x;
    if (i < NN) g_deg[i] = 0;
}
// build adjacency: per-sink source lists (order nondeterministic; only affects
// fp32 summation order, same as the prior atomic scatter)
__global__ void build_adj_kernel(const int* __restrict__ esrc, const int* __restrict__ esnk) {
    int i = blockIdx.x * blockDim.x + threadIdx.x;
    if (i < EE) {
        int snk = esnk[i];
        int pos = atomicAdd(&g_deg[snk], 1);
        if (pos < ADJ_CAP) g_adj[snk * ADJ_CAP + pos] = esrc[i];
    }
}
__global__ void degf_kernel() {
    int i = blockIdx.x * blockDim.x + threadIdx.x;
    if (i < NN) g_degf[i] = (float)g_deg[i];
}
// WT[n][k] = W[k][n], rows n >= N zero-padded; W is [512][N] row-major
__global__ void splitT_kernel(const float* __restrict__ W,
                              __nv_bfloat16* __restrict__ hi,
                              __nv_bfloat16* __restrict__ lo, int N, int NT) {
    int i = blockIdx.x * blockDim.x + threadIdx.x;
    if (i < NT * 512) {
        int n = i >> 9, k = i & 511;
        float v = (n < N) ? W[k * N + n] : 0.0f;
        __nv_bfloat16 h, l;
        split_bf16(v, h, l);
        hi[i] = h; lo[i] = l;
    }
}
// WPQT[n][k], n in [0,1024), k in [0,256)
__global__ void splitT_PQ_kernel(const float* __restrict__ We1) {
    int i = blockIdx.x * blockDim.x + threadIdx.x;
    if (i < 1024 * 256) {
        int n = i >> 8, k = i & 255;
        float v = (n < 512) ? We1[k * HH + n] : We1[(256 + k) * HH + (n - 512)];
        __nv_bfloat16 h, l;
        split_bf16(v, h, l);
        g_WPQT_hi[i] = h; g_WPQT_lo[i] = l;
    }
}

// ---------------------------------------------------------------------------
// gather: hacc[n] = sum_{src in adj[n]} relu(P[src] + Q[n] + b_e1)
// one block (128 thr) per (node, batch); thread t owns cols 4t..4t+3.
// Writes hacc hi/lo bf16 directly (single store, no atomics, no split pass).
// ---------------------------------------------------------------------------
__global__ __launch_bounds__(128)
void gather_kernel(const float* __restrict__ be1)
{
    const int n = blockIdx.x, b = blockIdx.y, t = threadIdx.x;
    const size_t rowb = (size_t)(b * NN + n);

    float4 qb = ((const float4*)(g_PQ + rowb * 1024 + 512))[t];
    const float4 bv = ((const float4*)be1)[t];
    qb.x += bv.x; qb.y += bv.y; qb.z += bv.z; qb.w += bv.w;

    float4 acc = make_float4(0.0f, 0.0f, 0.0f, 0.0f);
    const int deg = g_deg[n];
    const int* __restrict__ adj = g_adj + n * ADJ_CAP;
    const float* __restrict__ Pb = g_PQ + (size_t)(b * NN) * 1024;

    for (int i = 0; i < deg; i++) {
        int src = adj[i];
        float4 p = ((const float4*)(Pb + (size_t)src * 1024))[t];
        acc.x += fmaxf(p.x + qb.x, 0.0f);
        acc.y += fmaxf(p.y + qb.y, 0.0f);
        acc.z += fmaxf(p.z + qb.z, 0.0f);
        acc.w += fmaxf(p.w + qb.w, 0.0f);
    }

    __nv_bfloat16 h0, l0, h1, l1, h2, l2, h3, l3;
    split_bf16(acc.x, h0, l0); split_bf16(acc.y, h1, l1);
    split_bf16(acc.z, h2, l2); split_bf16(acc.w, h3, l3);
    uint2 vh = { pack_bf16x2(h0, h1), pack_bf16x2(h2, h3) };
    uint2 vl = { pack_bf16x2(l0, l1), pack_bf16x2(l2, l3) };
    ((uint2*)(g_hacc_hi + rowb * HH))[t] = vh;
    ((uint2*)(g_hacc_lo + rowb * HH))[t] = vl;
}

// ---------------------------------------------------------------------------
// Streaming mma.sync GEMM over dense node rows. 128x128 CTA tile.
//   MODE 0 (KST=8):  PQ = ns @ WPQ            epi: store fp32 -> g_PQ
//   MODE 1 (KST=16): pre-inc = hacc @ We2     epi: +deg*b_e2, split -> inc hi/lo
//   MODE 2 (KST=16): h = relu([inc|ns]@Wn1+b) epi: split -> g_h hi/lo
//   MODE 3 (KST=16): ns += h@Wn2+b            epi: add + re-split ns
// ---------------------------------------------------------------------------
#define STAGE_SZ (32 * 1024)
#define AOF_HI 0
#define AOF_LO (8 * 1024)
#define BOF_HI (16 * 1024)
#define BOF_LO (24 * 1024)
#define SMEM_GEMM (3 * STAGE_SZ)

__device__ __forceinline__ uint32_t plane_addr(int row, int cb) {
    return (uint32_t)(row * 64 + ((cb ^ ((row >> 1) & 3)) << 4));
}

template <int MODE, int KST>
__global__ __launch_bounds__(256, 2)
void gemm_kernel(const float* __restrict__ bias)
{
    extern __shared__ char sm[];
    const int tid  = threadIdx.x;
    const int wid  = tid >> 5, lane = tid & 31;
    const int r0   = blockIdx.x * 128;
    const int n0   = blockIdx.y * 128;
    const uint32_t smb = smem_u32(sm);

    const __nv_bfloat16 *bt_hi, *bt_lo;
    if      (MODE == 0) { bt_hi = g_WPQT_hi; bt_lo = g_WPQT_lo; }
    else if (MODE == 1) { bt_hi = g_We2T_hi; bt_lo = g_We2T_lo; }
    else if (MODE == 2) { bt_hi = g_Wn1T_hi; bt_lo = g_Wn1T_lo; }
    else                { bt_hi = g_Wn2T_hi; bt_lo = g_Wn2T_lo; }
    const int BSTR = (MODE == 0) ? 256 : 512;

    auto load_stage = [&](int c, int buf) {
        uint32_t sb = smb + buf * STAGE_SZ;
        #pragma unroll
        for (int it = 0; it < 4; it++) {
            int u = tid + it * 256;
            int row = u >> 3, sub = u & 7;
            int hi = (sub < 4), cb = sub & 3;
            int k = (c & 7) * 32 + cb * 8;
            const __nv_bfloat16* src;
            if (MODE == 0) {
                src = (hi ? g_ns_hi : g_ns_lo) + (size_t)(r0 + row) * DD + c * 32 + cb * 8;
            } else if (MODE == 1) {
                src = (hi ? g_hacc_hi : g_hacc_lo) + (size_t)(r0 + row) * HH + c * 32 + cb * 8;
            } else if (MODE == 2) {
                src = (c < 8)
                    ? (hi ? g_inc_hi : g_inc_lo) + (size_t)(r0 + row) * MSG + k
                    : (hi ? g_ns_hi  : g_ns_lo ) + (size_t)(r0 + row) * DD  + k;
            } else {
                src = (hi ? g_h_hi : g_h_lo) + (size_t)(r0 + row) * HH + c * 32 + cb * 8;
            }
            cpa16(sb + (hi ? AOF_HI : AOF_LO) + plane_addr(row, cb), src);
        }
        #pragma unroll
        for (int it = 0; it < 4; it++) {
            int u = tid + it * 256;
            int row = u >> 3, sub = u & 7;
            int hi = (sub < 4), cb = sub & 3;
            const __nv_bfloat16* src =
                (hi ? bt_hi : bt_lo) + (size_t)(n0 + row) * BSTR + c * 32 + cb * 8;
            cpa16(sb + (hi ? BOF_HI : BOF_LO) + plane_addr(row, cb), src);
        }
    };

    float acc[4][4][4];
    #pragma unroll
    for (int mi = 0; mi < 4; mi++)
        #pragma unroll
        for (int nj = 0; nj < 4; nj++)
            #pragma unroll
            for (int q = 0; q < 4; q++) acc[mi][nj][q] = 0.0f;

    load_stage(0, 0); CP_COMMIT();
    load_stage(1, 1); CP_COMMIT();
    load_stage(2, 2); CP_COMMIT();

    const int wm = wid & 1, wn = wid >> 1;
    const int la15 = lane & 15, la_h = lane >> 4;
    const int lb_n = (lane & 7) + ((lane >> 4) << 3);
    const int lb_kh = (lane >> 3) & 1;
    const int rq = lane >> 2, cq = (lane & 3) * 2;

    #pragma unroll 1
    for (int c = 0; c < KST; c++) {
        CP_WAIT2();
        __syncthreads();
        uint32_t sb = smb + (c % 3) * STAGE_SZ;

        #pragma unroll
        for (int ks = 0; ks < 2; ks++) {
            uint32_t bh[2][4], bl[2][4];
            #pragma unroll
            for (int p = 0; p < 2; p++) {
                int row = wn * 32 + p * 16 + lb_n;
                uint32_t ad = sb + BOF_HI + plane_addr(row, ks * 2 + lb_kh);
                ldsm4(bh[p], ad);
                ldsm4(bl[p], ad + (BOF_LO - BOF_HI));
            }
            #pragma unroll
            for (int mi = 0; mi < 4; mi++) {
                int row = wm * 64 + mi * 16 + la15;
                uint32_t ad = sb + AOF_HI + plane_addr(row, ks * 2 + la_h);
                uint32_t ah[4], al[4];
                ldsm4(ah, ad);
                ldsm4(al, ad + (AOF_LO - AOF_HI));
                #pragma unroll
                for (int p = 0; p < 2; p++) {
                    mma_bf16(acc[mi][2 * p],     ah, bh[p][0], bh[p][1]);
                    mma_bf16(acc[mi][2 * p + 1], ah, bh[p][2], bh[p][3]);
                    mma_bf16(acc[mi][2 * p],     ah, bl[p][0], bl[p][1]);
                    mma_bf16(acc[mi][2 * p + 1], ah, bl[p][2], bl[p][3]);
                    mma_bf16(acc[mi][2 * p],     al, bh[p][0], bh[p][1]);
                    mma_bf16(acc[mi][2 * p + 1], al, bh[p][2], bh[p][3]);
                }
            }
        }
        __syncthreads();
        if (c + 3 < KST) load_stage(c + 3, c % 3);
        CP_COMMIT();
    }

    // ---- epilogue ----
    #pragma unroll
    for (int mi = 0; mi < 4; mi++) {
        #pragma unroll
        for (int nj = 0; nj < 4; nj++) {
            int col = n0 + wn * 32 + nj * 8 + cq;
            float* a4 = acc[mi][nj];
            if (MODE == 0) {
                #pragma unroll
                for (int half = 0; half < 2; half++) {
                    int rl = wm * 64 + mi * 16 + rq + half * 8;
                    float2 st = { a4[2 * half], a4[2 * half + 1] };
                    *(float2*)(g_PQ + (size_t)(r0 + rl) * 1024 + col) = st;
                }
            } else if (MODE == 1) {
                float2 bv = *(const float2*)(bias + col);
                #pragma unroll
                for (int half = 0; half < 2; half++) {
                    int rl = wm * 64 + mi * 16 + rq + half * 8;
                    float dg = g_degf[(r0 + rl) & (NN - 1)];
                    float v0 = a4[2 * half]     + dg * bv.x;
                    float v1 = a4[2 * half + 1] + dg * bv.y;
                    __nv_bfloat16 h0, l0, h1, l1;
                    split_bf16(v0, h0, l0);
                    split_bf16(v1, h1, l1);
                    size_t go = (size_t)(r0 + rl) * MSG + col;
                    *(uint32_t*)(g_inc_hi + go) = pack_bf16x2(h0, h1);
                    *(uint32_t*)(g_inc_lo + go) = pack_bf16x2(l0, l1);
                }
            } else if (MODE == 2) {
                float2 bv = *(const float2*)(bias + col);
                #pragma unroll
                for (int half = 0; half < 2; half++) {
                    int rl = wm * 64 + mi * 16 + rq + half * 8;
                    float v0 = fmaxf(a4[2 * half]     + bv.x, 0.0f);
                    float v1 = fmaxf(a4[2 * half + 1] + bv.y, 0.0f);
                    __nv_bfloat16 h0, l0, h1, l1;
                    split_bf16(v0, h0, l0);
                    split_bf16(v1, h1, l1);
                    size_t go = (size_t)(r0 + rl) * HH + col;
                    *(uint32_t*)(g_h_hi + go) = pack_bf16x2(h0, h1);
                    *(uint32_t*)(g_h_lo + go) = pack_bf16x2(l0, l1);
                }
            } else {  // MODE 3
                #pragma unroll
                for (int half = 0; half < 2; half++) {
                    int rl = wm * 64 + mi * 16 + rq + half * 8;
                    size_t ro = (size_t)(r0 + rl) * DD + 2;
                    if (col < UPD) {
                        float nv = g_ns[ro + col] + a4[2 * half] + bias[col];
                        g_ns[ro + col] = nv;
                        __nv_bfloat16 h, l;
                        split_bf16(nv, h, l);
                        g_ns_hi[ro + col] = h; g_ns_lo[ro + col] = l;
                    }
                    if (col + 1 < UPD) {
                        float nv = g_ns[ro + col + 1] + a4[2 * half + 1] + bias[col + 1];
                        g_ns[ro + col + 1] = nv;
                        __nv_bfloat16 h, l;
                        split_bf16(nv, h, l);
                        g_ns_hi[ro + col + 1] = h; g_ns_lo[ro + col + 1] = l;
                    }
                }
            }
        }
    }
}

// ---------------------------------------------------------------------------
// Extraction (FFMA2 SIMT)
// ---------------------------------------------------------------------------
__device__ __forceinline__ u64 ffma2(u64 a, u64 b, u64 c) {
    u64 d; asm("fma.rn.f32x2 %0, %1, %2, %3;" : "=l"(d) : "l"(a), "l"(b), "l"(c)); return d;
}
__device__ __forceinline__ u64 pack2(float lo, float hi) {
    u64 d; asm("mov.b64 %0, {%1, %2};" : "=l"(d) : "f"(lo), "f"(hi)); return d;
}
__device__ __forceinline__ void unpack2(u64 v, float& lo, float& hi) {
    asm("mov.b64 {%0, %1}, %2;" : "=f"(lo), "=f"(hi) : "l"(v));
}

__global__ __launch_bounds__(256)
void extract_kernel(const float* __restrict__ attn, float* __restrict__ out)
{
    extern __shared__ float smA[];   // 256 * 66
    const int tid = threadIdx.x;
    const int b   = blockIdx.y;
    const int n0  = blockIdx.x * 256;
    const float* __restrict__ nsb = g_ns + (size_t)b * NN * DD;

    #pragma unroll 4
    for (int idx = tid; idx < 64 * 256; idx += 256) {
        int p = idx >> 8, j = idx & 255;
        smA[j * 66 + p] = attn[((size_t)b * PP + p) * NN + n0 + j];
    }
    __syncthreads();

    const int d = tid;
    u64 accp[32];
    #pragma unroll
    for (int pj = 0; pj < 32; pj++) accp[pj] = 0ull;

    for (int n = 0; n < 256; n++) {
        float s = nsb[(n0 + n) * DD + d];
        u64 sp = pack2(s, s);
        const u64* arow = (const u64*)(smA + n * 66);
        #pragma unroll
        for (int pj = 0; pj < 32; pj++) accp[pj] = ffma2(arow[pj], sp, accp[pj]);
    }
    #pragma unroll
    for (int pj = 0; pj < 32; pj++) {
        float lo, hi; unpack2(accp[pj], lo, hi);
        atomicAdd(&out[((size_t)b * PP + 2 * pj)     * DD + d], lo);
        atomicAdd(&out[((size_t)b * PP + 2 * pj + 1) * DD + d], hi);
    }
}

// ---------------------------------------------------------------------------
extern "C" void kernel_launch(void* const* d_in, const int* in_sizes, int n_in,
                              void* d_out, int out_size)
{
    const float* nodes = (const float*)d_in[0];
    const float* attn  = (const float*)d_in[1];
    const float* We1   = (const float*)d_in[2];
    const float* be1   = (const float*)d_in[3];
    const float* We2   = (const float*)d_in[4];
    const float* be2   = (const float*)d_in[5];
    const float* Wn1   = (const float*)d_in[6];
    const float* bn1   = (const float*)d_in[7];
    const float* Wn2   = (const float*)d_in[8];
    const float* bn2   = (const float*)d_in[9];
    const int*   esrc  = (const int*)d_in[10];
    const int*   esnk  = (const int*)d_in[11];
    float* out = (float*)d_out;

    cudaFuncSetAttribute((const void*)gemm_kernel<0, 8>,  cudaFuncAttributeMaxDynamicSharedMemorySize, SMEM_GEMM);
    cudaFuncSetAttribute((const void*)gemm_kernel<1, 16>, cudaFuncAttributeMaxDynamicSharedMemorySize, SMEM_GEMM);
    cudaFuncSetAttribute((const void*)gemm_kernel<2, 16>, cudaFuncAttributeMaxDynamicSharedMemorySize, SMEM_GEMM);
    cudaFuncSetAttribute((const void*)gemm_kernel<3, 16>, cudaFuncAttributeMaxDynamicSharedMemorySize, SMEM_GEMM);
    const int SMEM_EXT = 256 * 66 * 4;
    cudaFuncSetAttribute((const void*)extract_kernel, cudaFuncAttributeMaxDynamicSharedMemorySize, SMEM_EXT);

    __nv_bfloat16 *we2h, *we2l, *wn1h, *wn1l, *wn2h, *wn2l;
    cudaGetSymbolAddress((void**)&we2h, g_We2T_hi); cudaGetSymbolAddress((void**)&we2l, g_We2T_lo);
    cudaGetSymbolAddress((void**)&wn1h, g_Wn1T_hi); cudaGetSymbolAddress((void**)&wn1l, g_Wn1T_lo);
    cudaGetSymbolAddress((void**)&wn2h, g_Wn2T_hi); cudaGetSymbolAddress((void**)&wn2l, g_Wn2T_lo);

    splitT_PQ_kernel<<<(1024 * 256 + 255) / 256, 256>>>(We1);
    splitT_kernel<<<(MSG * 512 + 255) / 256, 256>>>(We2, we2h, we2l, MSG, MSG);
    splitT_kernel<<<(HH  * 512 + 255) / 256, 256>>>(Wn1, wn1h, wn1l, HH,  HH);
    splitT_kernel<<<(256 * 512 + 255) / 256, 256>>>(Wn2, wn2h, wn2l, UPD, 256);

    zero_deg_kernel<<<(NN + 255) / 256, 256>>>();
    build_adj_kernel<<<(EE + 255) / 256, 256>>>(esrc, esnk);
    degf_kernel<<<(NN + 255) / 256, 256>>>();

    copy_split_ns_kernel<<<(NROWS * DD + 255) / 256, 256>>>(nodes);

    for (int s = 0; s < STEPS; s++) {
        gemm_kernel<0, 8><<<dim3(NROWS / 128, 8), 256, SMEM_GEMM>>>(nullptr);  // PQ
        gather_kernel<<<dim3(NN, BB), 128>>>(be1);                             // hacc hi/lo
        gemm_kernel<1, 16><<<dim3(NROWS / 128, 2), 256, SMEM_GEMM>>>(be2);     // inc
        gemm_kernel<2, 16><<<dim3(NROWS / 128, 4), 256, SMEM_GEMM>>>(bn1);     // h
        gemm_kernel<3, 16><<<dim3(NROWS / 128, 2), 256, SMEM_GEMM>>>(bn2);     // ns +=
    }

    zero_out_kernel<<<(BB * PP * DD + 255) / 256, 256>>>(out, BB * PP * DD);
    extract_kernel<<<dim3(NN / 256, BB), 256, SMEM_EXT>>>(attn, out);
}

// round 12
// speedup vs baseline: 8.1776x; 1.0093x over previous
#include <cuda_runtime.h>
#include <cuda_bf16.h>
#include <cstdint>

#define BB   8
#define NN   4096
#define EE   16384
#define PP   64
#define DD   256
#define HH   512
#define MSG  256
#define UPD  254
#define STEPS 3

#define NROWS (BB * NN)   // 32768
#define ADJ_CAP 64

typedef unsigned long long u64;

// ---------------------------------------------------------------------------
// Device globals
// ---------------------------------------------------------------------------
__device__ float g_ns  [NROWS * DD];            // fp32 node state
__device__ float g_PQ  [(size_t)NROWS * 1024];  // P (0..511) | Q (512..1023)
__device__ float g_Wf  [512 * 512];             // We2 @ Wn1_top (k-major)
__device__ float g_b2n1[512];                   // b_e2 @ Wn1_top
__device__ float g_degf[NN];
__device__ int   g_deg [NN];
__device__ int   g_adj [NN * ADJ_CAP];

__device__ __nv_bfloat16 g_ns_hi [NROWS * DD],  g_ns_lo [NROWS * DD];
__device__ __nv_bfloat16 g_hacc_hi[NROWS * HH], g_hacc_lo[NROWS * HH];
__device__ __nv_bfloat16 g_h_hi[(size_t)NROWS * HH], g_h_lo[(size_t)NROWS * HH];

// transposed + split weights (rows = output col n, k contiguous)
__device__ __nv_bfloat16 g_WPQT_hi[1024 * 256], g_WPQT_lo[1024 * 256];
__device__ __nv_bfloat16 g_WfT_hi [512 * 768],  g_WfT_lo [512 * 768];  // [Wf | Wn1_bot]
__device__ __nv_bfloat16 g_Wn2T_hi[256 * 512],  g_Wn2T_lo[256 * 512];

// ---------------------------------------------------------------------------
// PTX helpers
// ---------------------------------------------------------------------------
__device__ __forceinline__ uint32_t smem_u32(const void* p) {
    uint32_t a;
    asm("{ .reg .u64 t; cvta.to.shared.u64 t, %1; cvt.u32.u64 %0, t; }" : "=r"(a) : "l"(p));
    return a;
}
__device__ __forceinline__ void ldsm4(uint32_t* r, uint32_t a) {
    asm volatile("ldmatrix.sync.aligned.m8n8.x4.shared.b16 {%0,%1,%2,%3}, [%4];"
        : "=r"(r[0]), "=r"(r[1]), "=r"(r[2]), "=r"(r[3]) : "r"(a));
}
__device__ __forceinline__ void mma_bf16(float* c, const uint32_t* a, uint32_t b0, uint32_t b1) {
    asm volatile("mma.sync.aligned.m16n8k16.row.col.f32.bf16.bf16.f32 "
        "{%0,%1,%2,%3}, {%4,%5,%6,%7}, {%8,%9}, {%0,%1,%2,%3};"
        : "+f"(c[0]), "+f"(c[1]), "+f"(c[2]), "+f"(c[3])
        : "r"(a[0]), "r"(a[1]), "r"(a[2]), "r"(a[3]), "r"(b0), "r"(b1));
}
__device__ __forceinline__ void cpa16(uint32_t d, const void* s) {
    asm volatile("cp.async.cg.shared.global [%0], [%1], 16;" :: "r"(d), "l"(s) : "memory");
}
#define CP_COMMIT() asm volatile("cp.async.commit_group;" ::: "memory")
#define CP_WAIT1()  asm volatile("cp.async.wait_group 1;" ::: "memory")
#define CP_WAIT0()  asm volatile("cp.async.wait_group 0;" ::: "memory")

__device__ __forceinline__ void split_bf16(float v, __nv_bfloat16& hi, __nv_bfloat16& lo) {
    hi = __float2bfloat16_rn(v);
    lo = __float2bfloat16_rn(v - __bfloat162float(hi));
}
__device__ __forceinline__ uint32_t pack_bf16x2(__nv_bfloat16 a, __nv_bfloat16 b) {
    return ((uint32_t)__bfloat16_as_ushort(b) << 16) | __bfloat16_as_ushort(a);
}

// ---------------------------------------------------------------------------
// Utility kernels
// ---------------------------------------------------------------------------
__global__ void copy_split_ns_kernel(const float* __restrict__ src) {
    int i = blockIdx.x * blockDim.x + threadIdx.x;
    if (i < NROWS * DD) {
        float v = src[i];
        g_ns[i] = v;
        __nv_bfloat16 h, l;
        split_bf16(v, h, l);
        g_ns_hi[i] = h; g_ns_lo[i] = l;
    }
}
__global__ void zero_out_kernel(float* __restrict__ out, int n) {
    int i = blockIdx.x * blockDim.x + threadIdx.x;
    if (i < n) out[i] = 0.0f;
}
__global__ void zero_deg_kernel() {
    int i = blockIdx.x * blockDim.x + threadIdx.x;
    if (i < NN) g_deg[i] = 0;
}
__global__ void build_adj_kernel(const int* __restrict__ esrc, const int* __restrict__ esnk) {
    int i = blockIdx.x * blockDim.x + threadIdx.x;
    if (i < EE) {
        int snk = esnk[i];
        int pos = atomicAdd(&g_deg[snk], 1);
        if (pos < ADJ_CAP) g_adj[snk * ADJ_CAP + pos] = esrc[i];
    }
}
__global__ void degf_kernel() {
    int i = blockIdx.x * blockDim.x + threadIdx.x;
    if (i < NN) g_degf[i] = (float)g_deg[i];
}
// WT[n][k] = W[k][n], rows n >= N zero-padded; W is [512][N] row-major
__global__ void splitT_kernel(const float* __restrict__ W,
                              __nv_bfloat16* __restrict__ hi,
                              __nv_bfloat16* __restrict__ lo, int N, int NT) {
    int i = blockIdx.x * blockDim.x + threadIdx.x;
    if (i < NT * 512) {
        int n = i >> 9, k = i & 511;
        float v = (n < N) ? W[k * N + n] : 0.0f;
        __nv_bfloat16 h, l;
        split_bf16(v, h, l);
        hi[i] = h; lo[i] = l;
    }
}
// WPQT[n][k], n in [0,1024), k in [0,256)
__global__ void splitT_PQ_kernel(const float* __restrict__ We1) {
    int i = blockIdx.x * blockDim.x + threadIdx.x;
    if (i < 1024 * 256) {
        int n = i >> 8, k = i & 255;
        float v = (n < 512) ? We1[k * HH + n] : We1[(256 + k) * HH + (n - 512)];
        __nv_bfloat16 h, l;
        split_bf16(v, h, l);
        g_WPQT_hi[i] = h; g_WPQT_lo[i] = l;
    }
}
// Wf[k][n] = sum_j We2[k][j] * Wn1[j][n]  (k,n in [0,512), j in [0,256))
__global__ void fuse_w_kernel(const float* __restrict__ We2, const float* __restrict__ Wn1) {
    int i = blockIdx.x * blockDim.x + threadIdx.x;
    if (i < 512 * 512) {
        int k = i >> 9, n = i & 511;
        float acc = 0.0f;
        #pragma unroll 4
        for (int j = 0; j < 256; j++)
            acc = fmaf(We2[k * MSG + j], Wn1[j * HH + n], acc);
        g_Wf[i] = acc;
    }
}
__global__ void b2n1_kernel(const float* __restrict__ be2, const float* __restrict__ Wn1) {
    int n = blockIdx.x * blockDim.x + threadIdx.x;
    if (n < 512) {
        float acc = 0.0f;
        for (int j = 0; j < 256; j++)
            acc = fmaf(be2[j], Wn1[j * HH + n], acc);
        g_b2n1[n] = acc;
    }
}
// WfT[n][k]: k<512 -> Wf[k][n]; k>=512 -> Wn1[256+(k-512)][n]  (Wn1_bot)
__global__ void splitT_Wf_kernel(const float* __restrict__ Wn1) {
    int i = blockIdx.x * blockDim.x + threadIdx.x;
    if (i < 512 * 768) {
        int n = i / 768, k = i % 768;
        float v = (k < 512) ? g_Wf[k * 512 + n] : Wn1[(256 + k - 512) * HH + n];
        __nv_bfloat16 h, l;
        split_bf16(v, h, l);
        g_WfT_hi[i] = h; g_WfT_lo[i] = l;
    }
}

// ---------------------------------------------------------------------------
// gather: hacc[n] = sum_{src in adj[n]} relu(P[src] + Q[n] + b_e1)
// ---------------------------------------------------------------------------
__global__ __launch_bounds__(128)
void gather_kernel(const float* __restrict__ be1)
{
    const int n = blockIdx.x, b = blockIdx.y, t = threadIdx.x;
    const size_t rowb = (size_t)(b * NN + n);

    float4 qb = ((const float4*)(g_PQ + rowb * 1024 + 512))[t];
    const float4 bv = ((const float4*)be1)[t];
    qb.x += bv.x; qb.y += bv.y; qb.z += bv.z; qb.w += bv.w;

    float4 acc = make_float4(0.0f, 0.0f, 0.0f, 0.0f);
    const int deg = g_deg[n];
    const int* __restrict__ adj = g_adj + n * ADJ_CAP;
    const float* __restrict__ Pb = g_PQ + (size_t)(b * NN) * 1024;

    for (int i = 0; i < deg; i++) {
        int src = adj[i];
        float4 p = ((const float4*)(Pb + (size_t)src * 1024))[t];
        acc.x += fmaxf(p.x + qb.x, 0.0f);
        acc.y += fmaxf(p.y + qb.y, 0.0f);
        acc.z += fmaxf(p.z + qb.z, 0.0f);
        acc.w += fmaxf(p.w + qb.w, 0.0f);
    }

    __nv_bfloat16 h0, l0, h1, l1, h2, l2, h3, l3;
    split_bf16(acc.x, h0, l0); split_bf16(acc.y, h1, l1);
    split_bf16(acc.z, h2, l2); split_bf16(acc.w, h3, l3);
    uint2 vh = { pack_bf16x2(h0, h1), pack_bf16x2(h2, h3) };
    uint2 vl = { pack_bf16x2(l0, l1), pack_bf16x2(l2, l3) };
    ((uint2*)(g_hacc_hi + rowb * HH))[t] = vh;
    ((uint2*)(g_hacc_lo + rowb * HH))[t] = vl;
}

// ---------------------------------------------------------------------------
// Streaming mma.sync GEMM, 128x128 CTA tile, single-sync 3-buf/2-ahead ring.
//   MODE 0 (KST=8):  PQ = ns @ WPQ                      epi: fp32 -> g_PQ
//   MODE 2 (KST=24): h = relu([hacc|ns]@WfT + bn1 + deg*b2n1)  epi: split -> g_h
//   MODE 3 (KST=16): ns += h@Wn2 + bn2                  epi: add + re-split ns
// ---------------------------------------------------------------------------
#define STAGE_SZ (32 * 1024)
#define AOF_HI 0
#define AOF_LO (8 * 1024)
#define BOF_HI (16 * 1024)
#define BOF_LO (24 * 1024)
#define SMEM_GEMM (3 * STAGE_SZ)

__device__ __forceinline__ uint32_t plane_addr(int row, int cb) {
    return (uint32_t)(row * 64 + ((cb ^ ((row >> 1) & 3)) << 4));
}

template <int MODE, int KST>
__global__ __launch_bounds__(256, 2)
void gemm_kernel(const float* __restrict__ bias)
{
    extern __shared__ char sm[];
    const int tid  = threadIdx.x;
    const int wid  = tid >> 5, lane = tid & 31;
    const int r0   = blockIdx.x * 128;
    const int n0   = blockIdx.y * 128;
    const uint32_t smb = smem_u32(sm);

    const __nv_bfloat16 *bt_hi, *bt_lo;
    if      (MODE == 0) { bt_hi = g_WPQT_hi; bt_lo = g_WPQT_lo; }
    else if (MODE == 2) { bt_hi = g_WfT_hi;  bt_lo = g_WfT_lo;  }
    else                { bt_hi = g_Wn2T_hi; bt_lo = g_Wn2T_lo; }
    const int BSTR = (MODE == 0) ? 256 : (MODE == 2) ? 768 : 512;

    auto load_stage = [&](int c, int buf) {
        uint32_t sb = smb + buf * STAGE_SZ;
        #pragma unroll
        for (int it = 0; it < 4; it++) {
            int u = tid + it * 256;
            int row = u >> 3, sub = u & 7;
            int hi = (sub < 4), cb = sub & 3;
            const __nv_bfloat16* src;
            if (MODE == 0) {
                src = (hi ? g_ns_hi : g_ns_lo) + (size_t)(r0 + row) * DD + c * 32 + cb * 8;
            } else if (MODE == 2) {
                src = (c < 16)
                    ? (hi ? g_hacc_hi : g_hacc_lo) + (size_t)(r0 + row) * HH + c * 32 + cb * 8
                    : (hi ? g_ns_hi   : g_ns_lo  ) + (size_t)(r0 + row) * DD + (c - 16) * 32 + cb * 8;
            } else {
                src = (hi ? g_h_hi : g_h_lo) + (size_t)(r0 + row) * HH + c * 32 + cb * 8;
            }
            cpa16(sb + (hi ? AOF_HI : AOF_LO) + plane_addr(row, cb), src);
        }
        #pragma unroll
        for (int it = 0; it < 4; it++) {
            int u = tid + it * 256;
            int row = u >> 3, sub = u & 7;
            int hi = (sub < 4), cb = sub & 3;
            const __nv_bfloat16* src =
                (hi ? bt_hi : bt_lo) + (size_t)(n0 + row) * BSTR + c * 32 + cb * 8;
            cpa16(sb + (hi ? BOF_HI : BOF_LO) + plane_addr(row, cb), src);
        }
    };

    float acc[4][4][4];
    #pragma unroll
    for (int mi = 0; mi < 4; mi++)
        #pragma unroll
        for (int nj = 0; nj < 4; nj++)
            #pragma unroll
            for (int q = 0; q < 4; q++) acc[mi][nj][q] = 0.0f;

    load_stage(0, 0); CP_COMMIT();
    load_stage(1, 1); CP_COMMIT();

    const int wm = wid & 1, wn = wid >> 1;
    const int la15 = lane & 15, la_h = lane >> 4;
    const int lb_n = (lane & 7) + ((lane >> 4) << 3);
    const int lb_kh = (lane >> 3) & 1;
    const int rq = lane >> 2, cq = (lane & 3) * 2;

    #pragma unroll 1
    for (int c = 0; c < KST; c++) {
        if (c + 2 < KST) { CP_WAIT1(); } else { CP_WAIT0(); }
        __syncthreads();
        if (c + 2 < KST) { load_stage(c + 2, (c + 2) % 3); CP_COMMIT(); }

        uint32_t sb = smb + (c % 3) * STAGE_SZ;
        #pragma unroll
        for (int ks = 0; ks < 2; ks++) {
            uint32_t bh[2][4], bl[2][4];
            #pragma unroll
            for (int p = 0; p < 2; p++) {
                int row = wn * 32 + p * 16 + lb_n;
                uint32_t ad = sb + BOF_HI + plane_addr(row, ks * 2 + lb_kh);
                ldsm4(bh[p], ad);
                ldsm4(bl[p], ad + (BOF_LO - BOF_HI));
            }
            #pragma unroll
            for (int mi = 0; mi < 4; mi++) {
                int row = wm * 64 + mi * 16 + la15;
                uint32_t ad = sb + AOF_HI + plane_addr(row, ks * 2 + la_h);
                uint32_t ah[4], al[4];
                ldsm4(ah, ad);
                ldsm4(al, ad + (AOF_LO - AOF_HI));
                #pragma unroll
                for (int p = 0; p < 2; p++) {
                    mma_bf16(acc[mi][2 * p],     ah, bh[p][0], bh[p][1]);
                    mma_bf16(acc[mi][2 * p + 1], ah, bh[p][2], bh[p][3]);
                    mma_bf16(acc[mi][2 * p],     ah, bl[p][0], bl[p][1]);
                    mma_bf16(acc[mi][2 * p + 1], ah, bl[p][2], bl[p][3]);
                    mma_bf16(acc[mi][2 * p],     al, bh[p][0], bh[p][1]);
                    mma_bf16(acc[mi][2 * p + 1], al, bh[p][2], bh[p][3]);
                }
            }
        }
    }

    // ---- epilogue ----
    #pragma unroll
    for (int mi = 0; mi < 4; mi++) {
        #pragma unroll
        for (int nj = 0; nj < 4; nj++) {
            int col = n0 + wn * 32 + nj * 8 + cq;
            float* a4 = acc[mi][nj];
            if (MODE == 0) {
                #pragma unroll
                for (int half = 0; half < 2; half++) {
                    int rl = wm * 64 + mi * 16 + rq + half * 8;
                    float2 st = { a4[2 * half], a4[2 * half + 1] };
                    *(float2*)(g_PQ + (size_t)(r0 + rl) * 1024 + col) = st;
                }
            } else if (MODE == 2) {
                float2 bv  = *(const float2*)(bias + col);
                float2 b2  = *(const float2*)(g_b2n1 + col);
                #pragma unroll
                for (int half = 0; half < 2; half++) {
                    int rl = wm * 64 + mi * 16 + rq + half * 8;
                    float dg = g_degf[(r0 + rl) & (NN - 1)];
                    float v0 = fmaxf(a4[2 * half]     + bv.x + dg * b2.x, 0.0f);
                    float v1 = fmaxf(a4[2 * half + 1] + bv.y + dg * b2.y, 0.0f);
                    __nv_bfloat16 h0, l0, h1, l1;
                    split_bf16(v0, h0, l0);
                    split_bf16(v1, h1, l1);
                    size_t go = (size_t)(r0 + rl) * HH + col;
                    *(uint32_t*)(g_h_hi + go) = pack_bf16x2(h0, h1);
                    *(uint32_t*)(g_h_lo + go) = pack_bf16x2(l0, l1);
                }
            } else {  // MODE 3
                #pragma unroll
                for (int half = 0; half < 2; half++) {
                    int rl = wm * 64 + mi * 16 + rq + half * 8;
                    size_t ro = (size_t)(r0 + rl) * DD + 2;
                    if (col < UPD) {
                        float nv = g_ns[ro + col] + a4[2 * half] + bias[col];
                        g_ns[ro + col] = nv;
                        __nv_bfloat16 h, l;
                        split_bf16(nv, h, l);
                        g_ns_hi[ro + col] = h; g_ns_lo[ro + col] = l;
                    }
                    if (col + 1 < UPD) {
                        float nv = g_ns[ro + col + 1] + a4[2 * half + 1] + bias[col + 1];
                        g_ns[ro + col + 1] = nv;
                        __nv_bfloat16 h, l;
                        split_bf16(nv, h, l);
                        g_ns_hi[ro + col + 1] = h; g_ns_lo[ro + col + 1] = l;
                    }
                }
            }
        }
    }
}

// ---------------------------------------------------------------------------
// Extraction (FFMA2 SIMT)
// ---------------------------------------------------------------------------
__device__ __forceinline__ u64 ffma2(u64 a, u64 b, u64 c) {
    u64 d; asm("fma.rn.f32x2 %0, %1, %2, %3;" : "=l"(d) : "l"(a), "l"(b), "l"(c)); return d;
}
__device__ __forceinline__ u64 pack2(float lo, float hi) {
    u64 d; asm("mov.b64 %0, {%1, %2};" : "=l"(d) : "f"(lo), "f"(hi)); return d;
}
__device__ __forceinline__ void unpack2(u64 v, float& lo, float& hi) {
    asm("mov.b64 {%0, %1}, %2;" : "=f"(lo), "=f"(hi) : "l"(v));
}

__global__ __launch_bounds__(256)
void extract_kernel(const float* __restrict__ attn, float* __restrict__ out)
{
    extern __shared__ float smA[];   // 256 * 66
    const int tid = threadIdx.x;
    const int b   = blockIdx.y;
    const int n0  = blockIdx.x * 256;
    const float* __restrict__ nsb = g_ns + (size_t)b * NN * DD;

    #pragma unroll 4
    for (int idx = tid; idx < 64 * 256; idx += 256) {
        int p = idx >> 8, j = idx & 255;
        smA[j * 66 + p] = attn[((size_t)b * PP + p) * NN + n0 + j];
    }
    __syncthreads();

    const int d = tid;
    u64 accp[32];
    #pragma unroll
    for (int pj = 0; pj < 32; pj++) accp[pj] = 0ull;

    for (int n = 0; n < 256; n++) {
        float s = nsb[(n0 + n) * DD + d];
        u64 sp = pack2(s, s);
        const u64* arow = (const u64*)(smA + n * 66);
        #pragma unroll
        for (int pj = 0; pj < 32; pj++) accp[pj] = ffma2(arow[pj], sp, accp[pj]);
    }
    #pragma unroll
    for (int pj = 0; pj < 32; pj++) {
        float lo, hi; unpack2(accp[pj], lo, hi);
        atomicAdd(&out[((size_t)b * PP + 2 * pj)     * DD + d], lo);
        atomicAdd(&out[((size_t)b * PP + 2 * pj + 1) * DD + d], hi);
    }
}

// ---------------------------------------------------------------------------
extern "C" void kernel_launch(void* const* d_in, const int* in_sizes, int n_in,
                              void* d_out, int out_size)
{
    const float* nodes = (const float*)d_in[0];
    const float* attn  = (const float*)d_in[1];
    const float* We1   = (const float*)d_in[2];
    const float* be1   = (const float*)d_in[3];
    const float* We2   = (const float*)d_in[4];
    const float* be2   = (const float*)d_in[5];
    const float* Wn1   = (const float*)d_in[6];
    const float* bn1   = (const float*)d_in[7];
    const float* Wn2   = (const float*)d_in[8];
    const float* bn2   = (const float*)d_in[9];
    const int*   esrc  = (const int*)d_in[10];
    const int*   esnk  = (const int*)d_in[11];
    float* out = (float*)d_out;

    cudaFuncSetAttribute((const void*)gemm_kernel<0, 8>,  cudaFuncAttributeMaxDynamicSharedMemorySize, SMEM_GEMM);
    cudaFuncSetAttribute((const void*)gemm_kernel<2, 24>, cudaFuncAttributeMaxDynamicSharedMemorySize, SMEM_GEMM);
    cudaFuncSetAttribute((const void*)gemm_kernel<3, 16>, cudaFuncAttributeMaxDynamicSharedMemorySize, SMEM_GEMM);
    const int SMEM_EXT = 256 * 66 * 4;
    cudaFuncSetAttribute((const void*)extract_kernel, cudaFuncAttributeMaxDynamicSharedMemorySize, SMEM_EXT);

    __nv_bfloat16 *wn2h, *wn2l;
    cudaGetSymbolAddress((void**)&wn2h, g_Wn2T_hi); cudaGetSymbolAddress((void**)&wn2l, g_Wn2T_lo);

    splitT_PQ_kernel<<<(1024 * 256 + 255) / 256, 256>>>(We1);
    splitT_kernel<<<(256 * 512 + 255) / 256, 256>>>(Wn2, wn2h, wn2l, UPD, 256);
    fuse_w_kernel<<<(512 * 512 + 255) / 256, 256>>>(We2, Wn1);
    b2n1_kernel<<<2, 256>>>(be2, Wn1);
    splitT_Wf_kernel<<<(512 * 768 + 255) / 256, 256>>>(Wn1);

    zero_deg_kernel<<<(NN + 255) / 256, 256>>>();
    build_adj_kernel<<<(EE + 255) / 256, 256>>>(esrc, esnk);
    degf_kernel<<<(NN + 255) / 256, 256>>>();

    copy_split_ns_kernel<<<(NROWS * DD + 255) / 256, 256>>>(nodes);

    for (int s = 0; s < STEPS; s++) {
        gemm_kernel<0, 8><<<dim3(NROWS / 128, 8), 256, SMEM_GEMM>>>(nullptr);   // PQ
        gather_kernel<<<dim3(NN, BB), 128>>>(be1);                              // hacc
        gemm_kernel<2, 24><<<dim3(NROWS / 128, 4), 256, SMEM_GEMM>>>(bn1);      // h
        gemm_kernel<3, 16><<<dim3(NROWS / 128, 2), 256, SMEM_GEMM>>>(bn2);      // ns +=
    }

    zero_out_kernel<<<(BB * PP * DD + 255) / 256, 256>>>(out, BB * PP * DD);
    extract_kernel<<<dim3(NN / 256, BB), 256, SMEM_EXT>>>(attn, out);
}

// round 13
// speedup vs baseline: 11.2545x; 1.3763x over previous
#include <cuda_runtime.h>
#include <cuda_fp16.h>
#include <cstdint>

#define BB   8
#define NN   4096
#define EE   16384
#define PP   64
#define DD   256
#define HH   512
#define MSG  256
#define UPD  254
#define STEPS 3

#define NROWS (BB * NN)   // 32768
#define ADJ_CAP 64

typedef unsigned long long u64;

// ---------------------------------------------------------------------------
// Device globals
// ---------------------------------------------------------------------------
__device__ float g_ns  [NROWS * DD];            // fp32 node state (master)
__device__ float g_PQ  [(size_t)NROWS * 1024];  // P (0..511) | Q (512..1023)
__device__ float g_Wf  [512 * 512];             // We2 @ Wn1_top
__device__ float g_b2n1[512];                   // b_e2 @ Wn1_top
__device__ float g_degf[NN];
__device__ int   g_deg [NN];
__device__ int   g_adj [NN * ADJ_CAP];

// fp16 activation planes (single, no lo residual)
__device__ __half g_ns_h  [NROWS * DD];
__device__ __half g_hacc_h[NROWS * HH];
__device__ __half g_h_h   [(size_t)NROWS * HH];

// fp16 weightT hi/lo pairs (rows = output col n, k contiguous)
__device__ __half g_WPQT_h[1024 * 256], g_WPQT_l[1024 * 256];
__device__ __half g_WfT_h [512 * 768],  g_WfT_l [512 * 768];   // [Wf | Wn1_bot]
__device__ __half g_Wn2T_h[256 * 512],  g_Wn2T_l[256 * 512];

// ---------------------------------------------------------------------------
// PTX helpers
// ---------------------------------------------------------------------------
__device__ __forceinline__ uint32_t smem_u32(const void* p) {
    uint32_t a;
    asm("{ .reg .u64 t; cvta.to.shared.u64 t, %1; cvt.u32.u64 %0, t; }" : "=r"(a) : "l"(p));
    return a;
}
__device__ __forceinline__ void ldsm4(uint32_t* r, uint32_t a) {
    asm volatile("ldmatrix.sync.aligned.m8n8.x4.shared.b16 {%0,%1,%2,%3}, [%4];"
        : "=r"(r[0]), "=r"(r[1]), "=r"(r[2]), "=r"(r[3]) : "r"(a));
}
__device__ __forceinline__ void mma_f16(float* c, const uint32_t* a, uint32_t b0, uint32_t b1) {
    asm volatile("mma.sync.aligned.m16n8k16.row.col.f32.f16.f16.f32 "
        "{%0,%1,%2,%3}, {%4,%5,%6,%7}, {%8,%9}, {%0,%1,%2,%3};"
        : "+f"(c[0]), "+f"(c[1]), "+f"(c[2]), "+f"(c[3])
        : "r"(a[0]), "r"(a[1]), "r"(a[2]), "r"(a[3]), "r"(b0), "r"(b1));
}
__device__ __forceinline__ void cpa16(uint32_t d, const void* s) {
    asm volatile("cp.async.cg.shared.global [%0], [%1], 16;" :: "r"(d), "l"(s) : "memory");
}
#define CP_COMMIT() asm volatile("cp.async.commit_group;" ::: "memory")
#define CP_WAIT1()  asm volatile("cp.async.wait_group 1;" ::: "memory")
#define CP_WAIT0()  asm volatile("cp.async.wait_group 0;" ::: "memory")

__device__ __forceinline__ void split_f16(float v, __half& h, __half& l) {
    h = __float2half_rn(v);
    l = __float2half_rn(v - __half2float(h));
}
__device__ __forceinline__ uint32_t pack_h2(__half a, __half b) {
    return ((uint32_t)__half_as_ushort(b) << 16) | __half_as_ushort(a);
}

// ---------------------------------------------------------------------------
// Utility kernels
// ---------------------------------------------------------------------------
__global__ void copy_split_ns_kernel(const float* __restrict__ src) {
    int i = blockIdx.x * blockDim.x + threadIdx.x;
    if (i < NROWS * DD) {
        float v = src[i];
        g_ns[i] = v;
        g_ns_h[i] = __float2half_rn(v);
    }
}
__global__ void zero_out_kernel(float* __restrict__ out, int n) {
    int i = blockIdx.x * blockDim.x + threadIdx.x;
    if (i < n) out[i] = 0.0f;
}
__global__ void zero_deg_kernel() {
    int i = blockIdx.x * blockDim.x + threadIdx.x;
    if (i < NN) g_deg[i] = 0;
}
__global__ void build_adj_kernel(const int* __restrict__ esrc, const int* __restrict__ esnk) {
    int i = blockIdx.x * blockDim.x + threadIdx.x;
    if (i < EE) {
        int snk = esnk[i];
        int pos = atomicAdd(&g_deg[snk], 1);
        if (pos < ADJ_CAP) g_adj[snk * ADJ_CAP + pos] = esrc[i];
    }
}
__global__ void degf_kernel() {
    int i = blockIdx.x * blockDim.x + threadIdx.x;
    if (i < NN) g_degf[i] = (float)g_deg[i];
}
// WT[n][k] = W[k][n] (fp16 hi/lo), rows n >= N zero-padded; W is [512][N]
__global__ void splitT_kernel(const float* __restrict__ W,
                              __half* __restrict__ hi, __half* __restrict__ lo,
                              int N, int NT) {
    int i = blockIdx.x * blockDim.x + threadIdx.x;
    if (i < NT * 512) {
        int n = i >> 9, k = i & 511;
        float v = (n < N) ? W[k * N + n] : 0.0f;
        __half h, l;
        split_f16(v, h, l);
        hi[i] = h; lo[i] = l;
    }
}
// WPQT[n][k], n in [0,1024), k in [0,256)
__global__ void splitT_PQ_kernel(const float* __restrict__ We1) {
    int i = blockIdx.x * blockDim.x + threadIdx.x;
    if (i < 1024 * 256) {
        int n = i >> 8, k = i & 255;
        float v = (n < 512) ? We1[k * HH + n] : We1[(256 + k) * HH + (n - 512)];
        __half h, l;
        split_f16(v, h, l);
        g_WPQT_h[i] = h; g_WPQT_l[i] = l;
    }
}
// Wf = We2(512x256) @ Wn1_top(256x512), smem-tiled 64x64
__global__ __launch_bounds__(256)
void fuse_w_kernel(const float* __restrict__ We2, const float* __restrict__ Wn1) {
    __shared__ float sA[64][65];
    __shared__ float sB[64][65];
    const int tid = threadIdx.x;
    const int k0 = blockIdx.y * 64, n0 = blockIdx.x * 64;
    const int ty = tid >> 4, tx = tid & 15;
    float acc[4][4];
    #pragma unroll
    for (int i = 0; i < 4; i++)
        #pragma unroll
        for (int l = 0; l < 4; l++) acc[i][l] = 0.0f;

    for (int j0 = 0; j0 < 256; j0 += 64) {
        #pragma unroll
        for (int it = 0; it < 16; it++) {
            int u = tid + it * 256;
            int r = u >> 6, c = u & 63;
            sA[r][c] = We2[(k0 + r) * MSG + j0 + c];
            sB[r][c] = Wn1[(j0 + r) * HH + n0 + c];
        }
        __syncthreads();
        #pragma unroll 8
        for (int jj = 0; jj < 64; jj++) {
            float a[4], b[4];
            #pragma unroll
            for (int i = 0; i < 4; i++) a[i] = sA[ty * 4 + i][jj];
            #pragma unroll
            for (int l = 0; l < 4; l++) b[l] = sB[jj][tx * 4 + l];
            #pragma unroll
            for (int i = 0; i < 4; i++)
                #pragma unroll
                for (int l = 0; l < 4; l++) acc[i][l] = fmaf(a[i], b[l], acc[i][l]);
        }
        __syncthreads();
    }
    #pragma unroll
    for (int i = 0; i < 4; i++)
        #pragma unroll
        for (int l = 0; l < 4; l++)
            g_Wf[(k0 + ty * 4 + i) * 512 + n0 + tx * 4 + l] = acc[i][l];
}
// b2n1[n] = sum_j be2[j] * Wn1[j][n]; be2 cached in smem, coalesced Wn1 reads
__global__ __launch_bounds__(256)
void b2n1_kernel(const float* __restrict__ be2, const float* __restrict__ Wn1) {
    __shared__ float sb2[256];
    const int tid = threadIdx.x;
    sb2[tid] = be2[tid];
    __syncthreads();
    int n = blockIdx.x * 256 + tid;
    float acc = 0.0f;
    #pragma unroll 8
    for (int j = 0; j < 256; j++)
        acc = fmaf(sb2[j], Wn1[j * HH + n], acc);
    g_b2n1[n] = acc;
}
// WfT[n][k]: k<512 -> Wf[k][n]; k>=512 -> Wn1[256+(k-512)][n]  (fp16 hi/lo)
__global__ void splitT_Wf_kernel(const float* __restrict__ Wn1) {
    int i = blockIdx.x * blockDim.x + threadIdx.x;
    if (i < 512 * 768) {
        int n = i / 768, k = i % 768;
        float v = (k < 512) ? g_Wf[k * 512 + n] : Wn1[(256 + k - 512) * HH + n];
        __half h, l;
        split_f16(v, h, l);
        g_WfT_h[i] = h; g_WfT_l[i] = l;
    }
}

// ---------------------------------------------------------------------------
// gather: hacc[n] = sum_{src in adj[n]} relu(P[src] + Q[n] + b_e1)  -> fp16
// ---------------------------------------------------------------------------
__global__ __launch_bounds__(128)
void gather_kernel(const float* __restrict__ be1)
{
    const int n = blockIdx.x, b = blockIdx.y, t = threadIdx.x;
    const size_t rowb = (size_t)(b * NN + n);

    float4 qb = ((const float4*)(g_PQ + rowb * 1024 + 512))[t];
    const float4 bv = ((const float4*)be1)[t];
    qb.x += bv.x; qb.y += bv.y; qb.z += bv.z; qb.w += bv.w;

    float4 acc = make_float4(0.0f, 0.0f, 0.0f, 0.0f);
    const int deg = g_deg[n];
    const int* __restrict__ adj = g_adj + n * ADJ_CAP;
    const float* __restrict__ Pb = g_PQ + (size_t)(b * NN) * 1024;

    for (int i = 0; i < deg; i++) {
        int src = adj[i];
        float4 p = ((const float4*)(Pb + (size_t)src * 1024))[t];
        acc.x += fmaxf(p.x + qb.x, 0.0f);
        acc.y += fmaxf(p.y + qb.y, 0.0f);
        acc.z += fmaxf(p.z + qb.z, 0.0f);
        acc.w += fmaxf(p.w + qb.w, 0.0f);
    }

    uint2 v;
    v.x = pack_h2(__float2half_rn(acc.x), __float2half_rn(acc.y));
    v.y = pack_h2(__float2half_rn(acc.z), __float2half_rn(acc.w));
    ((uint2*)(g_hacc_h + rowb * HH))[t] = v;
}

// ---------------------------------------------------------------------------
// Streaming mma.sync GEMM, fp16 2-term (A single plane, B = Whi + Wlo).
// 128x128 CTA tile, single-sync 3-buf/2-ahead ring, stage = k32 = 24KB.
//   MODE 0 (KST=8):  PQ = ns @ WPQ                         epi: fp32 -> g_PQ
//   MODE 2 (KST=24): h = relu([hacc|ns]@WfT + bn1 + deg*b2n1)  epi: fp16 -> g_h_h
//   MODE 3 (KST=16): ns += h@Wn2 + bn2                     epi: fp32 ns + fp16 ns_h
// ---------------------------------------------------------------------------
#define STAGE_SZ (24 * 1024)
#define AOF      0
#define BOF_HI   (8 * 1024)
#define BOF_LO   (16 * 1024)
#define SMEM_GEMM (3 * STAGE_SZ)

__device__ __forceinline__ uint32_t plane_addr(int row, int cb) {
    return (uint32_t)(row * 64 + ((cb ^ ((row >> 1) & 3)) << 4));
}

template <int MODE, int KST>
__global__ __launch_bounds__(256, 2)
void gemm_kernel(const float* __restrict__ bias)
{
    extern __shared__ char sm[];
    const int tid  = threadIdx.x;
    const int wid  = tid >> 5, lane = tid & 31;
    const int r0   = blockIdx.x * 128;
    const int n0   = blockIdx.y * 128;
    const uint32_t smb = smem_u32(sm);

    const __half *bt_hi, *bt_lo;
    if      (MODE == 0) { bt_hi = g_WPQT_h; bt_lo = g_WPQT_l; }
    else if (MODE == 2) { bt_hi = g_WfT_h;  bt_lo = g_WfT_l;  }
    else                { bt_hi = g_Wn2T_h; bt_lo = g_Wn2T_l; }
    const int BSTR = (MODE == 0) ? 256 : (MODE == 2) ? 768 : 512;

    auto load_stage = [&](int c, int buf) {
        uint32_t sb = smb + buf * STAGE_SZ;
        // A: 128 rows x 32 k fp16 = 512 x 16B chunks
        #pragma unroll
        for (int it = 0; it < 2; it++) {
            int u = tid + it * 256;
            int row = u >> 2, cb = u & 3;
            const __half* src;
            if (MODE == 0) {
                src = g_ns_h + (size_t)(r0 + row) * DD + c * 32 + cb * 8;
            } else if (MODE == 2) {
                src = (c < 16)
                    ? g_hacc_h + (size_t)(r0 + row) * HH + c * 32 + cb * 8
                    : g_ns_h   + (size_t)(r0 + row) * DD + (c - 16) * 32 + cb * 8;
            } else {
                src = g_h_h + (size_t)(r0 + row) * HH + c * 32 + cb * 8;
            }
            cpa16(sb + AOF + plane_addr(row, cb), src);
        }
        // B: 128 n-rows x 32 k, hi + lo
        #pragma unroll
        for (int it = 0; it < 4; it++) {
            int u = tid + it * 256;
            int hi = (u < 512);
            int v = u & 511;
            int row = v >> 2, cb = v & 3;
            const __half* src = (hi ? bt_hi : bt_lo) + (size_t)(n0 + row) * BSTR + c * 32 + cb * 8;
            cpa16(sb + (hi ? BOF_HI : BOF_LO) + plane_addr(row, cb), src);
        }
    };

    float acc[4][4][4];
    #pragma unroll
    for (int mi = 0; mi < 4; mi++)
        #pragma unroll
        for (int nj = 0; nj < 4; nj++)
            #pragma unroll
            for (int q = 0; q < 4; q++) acc[mi][nj][q] = 0.0f;

    load_stage(0, 0); CP_COMMIT();
    load_stage(1, 1); CP_COMMIT();

    const int wm = wid & 1, wn = wid >> 1;
    const int la15 = lane & 15, la_h = lane >> 4;
    const int lb_n = (lane & 7) + ((lane >> 4) << 3);
    const int lb_kh = (lane >> 3) & 1;
    const int rq = lane >> 2, cq = (lane & 3) * 2;

    #pragma unroll 1
    for (int c = 0; c < KST; c++) {
        if (c + 2 < KST) { CP_WAIT1(); } else { CP_WAIT0(); }
        __syncthreads();
        if (c + 2 < KST) { load_stage(c + 2, (c + 2) % 3); CP_COMMIT(); }

        uint32_t sb = smb + (c % 3) * STAGE_SZ;
        #pragma unroll
        for (int ks = 0; ks < 2; ks++) {
            uint32_t bh[2][4], bl[2][4];
            #pragma unroll
            for (int p = 0; p < 2; p++) {
                int row = wn * 32 + p * 16 + lb_n;
                uint32_t ad = sb + BOF_HI + plane_addr(row, ks * 2 + lb_kh);
                ldsm4(bh[p], ad);
                ldsm4(bl[p], ad + (BOF_LO - BOF_HI));
            }
            #pragma unroll
            for (int mi = 0; mi < 4; mi++) {
                int row = wm * 64 + mi * 16 + la15;
                uint32_t a[4];
                ldsm4(a, sb + AOF + plane_addr(row, ks * 2 + la_h));
                #pragma unroll
                for (int p = 0; p < 2; p++) {
                    mma_f16(acc[mi][2 * p],     a, bh[p][0], bh[p][1]);
                    mma_f16(acc[mi][2 * p + 1], a, bh[p][2], bh[p][3]);
                    mma_f16(acc[mi][2 * p],     a, bl[p][0], bl[p][1]);
                    mma_f16(acc[mi][2 * p + 1], a, bl[p][2], bl[p][3]);
                }
            }
        }
    }

    // ---- epilogue ----
    #pragma unroll
    for (int mi = 0; mi < 4; mi++) {
        #pragma unroll
        for (int nj = 0; nj < 4; nj++) {
            int col = n0 + wn * 32 + nj * 8 + cq;
            float* a4 = acc[mi][nj];
            if (MODE == 0) {
                #pragma unroll
                for (int half = 0; half < 2; half++) {
                    int rl = wm * 64 + mi * 16 + rq + half * 8;
                    float2 st = { a4[2 * half], a4[2 * half + 1] };
                    *(float2*)(g_PQ + (size_t)(r0 + rl) * 1024 + col) = st;
                }
            } else if (MODE == 2) {
                float2 bv = *(const float2*)(bias + col);
                float2 b2 = *(const float2*)(g_b2n1 + col);
                #pragma unroll
                for (int half = 0; half < 2; half++) {
                    int rl = wm * 64 + mi * 16 + rq + half * 8;
                    float dg = g_degf[(r0 + rl) & (NN - 1)];
                    float v0 = fmaxf(a4[2 * half]     + bv.x + dg * b2.x, 0.0f);
                    float v1 = fmaxf(a4[2 * half + 1] + bv.y + dg * b2.y, 0.0f);
                    size_t go = (size_t)(r0 + rl) * HH + col;
                    *(uint32_t*)(g_h_h + go) = pack_h2(__float2half_rn(v0), __float2half_rn(v1));
                }
            } else {  // MODE 3
                #pragma unroll
                for (int half = 0; half < 2; half++) {
                    int rl = wm * 64 + mi * 16 + rq + half * 8;
                    size_t ro = (size_t)(r0 + rl) * DD + 2;
                    if (col < UPD) {
                        float nv = g_ns[ro + col] + a4[2 * half] + bias[col];
                        g_ns[ro + col] = nv;
                        g_ns_h[ro + col] = __float2half_rn(nv);
                    }
                    if (col + 1 < UPD) {
                        float nv = g_ns[ro + col + 1] + a4[2 * half + 1] + bias[col + 1];
                        g_ns[ro + col + 1] = nv;
                        g_ns_h[ro + col + 1] = __float2half_rn(nv);
                    }
                }
            }
        }
    }
}

// ---------------------------------------------------------------------------
// Extraction (FFMA2 SIMT, fp32 exact from g_ns)
// ---------------------------------------------------------------------------
__device__ __forceinline__ u64 ffma2(u64 a, u64 b, u64 c) {
    u64 d; asm("fma.rn.f32x2 %0, %1, %2, %3;" : "=l"(d) : "l"(a), "l"(b), "l"(c)); return d;
}
__device__ __forceinline__ u64 pack2(float lo, float hi) {
    u64 d; asm("mov.b64 %0, {%1, %2};" : "=l"(d) : "f"(lo), "f"(hi)); return d;
}
__device__ __forceinline__ void unpack2(u64 v, float& lo, float& hi) {
    asm("mov.b64 {%0, %1}, %2;" : "=f"(lo), "=f"(hi) : "l"(v));
}

__global__ __launch_bounds__(256)
void extract_kernel(const float* __restrict__ attn, float* __restrict__ out)
{
    extern __shared__ float smA[];   // 256 * 66
    const int tid = threadIdx.x;
    const int b   = blockIdx.y;
    const int n0  = blockIdx.x * 256;
    const float* __restrict__ nsb = g_ns + (size_t)b * NN * DD;

    #pragma unroll 4
    for (int idx = tid; idx < 64 * 256; idx += 256) {
        int p = idx >> 8, j = idx & 255;
        smA[j * 66 + p] = attn[((size_t)b * PP + p) * NN + n0 + j];
    }
    __syncthreads();

    const int d = tid;
    u64 accp[32];
    #pragma unroll
    for (int pj = 0; pj < 32; pj++) accp[pj] = 0ull;

    for (int n = 0; n < 256; n++) {
        float s = nsb[(n0 + n) * DD + d];
        u64 sp = pack2(s, s);
        const u64* arow = (const u64*)(smA + n * 66);
        #pragma unroll
        for (int pj = 0; pj < 32; pj++) accp[pj] = ffma2(arow[pj], sp, accp[pj]);
    }
    #pragma unroll
    for (int pj = 0; pj < 32; pj++) {
        float lo, hi; unpack2(accp[pj], lo, hi);
        atomicAdd(&out[((size_t)b * PP + 2 * pj)     * DD + d], lo);
        atomicAdd(&out[((size_t)b * PP + 2 * pj + 1) * DD + d], hi);
    }
}

// ---------------------------------------------------------------------------
extern "C" void kernel_launch(void* const* d_in, const int* in_sizes, int n_in,
                              void* d_out, int out_size)
{
    const float* nodes = (const float*)d_in[0];
    const float* attn  = (const float*)d_in[1];
    const float* We1   = (const float*)d_in[2];
    const float* be1   = (const float*)d_in[3];
    const float* We2   = (const float*)d_in[4];
    const float* be2   = (const float*)d_in[5];
    const float* Wn1   = (const float*)d_in[6];
    const float* bn1   = (const float*)d_in[7];
    const float* Wn2   = (const float*)d_in[8];
    const float* bn2   = (const float*)d_in[9];
    const int*   esrc  = (const int*)d_in[10];
    const int*   esnk  = (const int*)d_in[11];
    float* out = (float*)d_out;

    cudaFuncSetAttribute((const void*)gemm_kernel<0, 8>,  cudaFuncAttributeMaxDynamicSharedMemorySize, SMEM_GEMM);
    cudaFuncSetAttribute((const void*)gemm_kernel<2, 24>, cudaFuncAttributeMaxDynamicSharedMemorySize, SMEM_GEMM);
    cudaFuncSetAttribute((const void*)gemm_kernel<3, 16>, cudaFuncAttributeMaxDynamicSharedMemorySize, SMEM_GEMM);
    const int SMEM_EXT = 256 * 66 * 4;
    cudaFuncSetAttribute((const void*)extract_kernel, cudaFuncAttributeMaxDynamicSharedMemorySize, SMEM_EXT);

    __half *wn2h, *wn2l;
    cudaGetSymbolAddress((void**)&wn2h, g_Wn2T_h); cudaGetSymbolAddress((void**)&wn2l, g_Wn2T_l);

    splitT_PQ_kernel<<<(1024 * 256 + 255) / 256, 256>>>(We1);
    splitT_kernel<<<(256 * 512 + 255) / 256, 256>>>(Wn2, wn2h, wn2l, UPD, 256);
    fuse_w_kernel<<<dim3(8, 8), 256>>>(We2, Wn1);
    b2n1_kernel<<<2, 256>>>(be2, Wn1);
    splitT_Wf_kernel<<<(512 * 768 + 255) / 256, 256>>>(Wn1);

    zero_deg_kernel<<<(NN + 255) / 256, 256>>>();
    build_adj_kernel<<<(EE + 255) / 256, 256>>>(esrc, esnk);
    degf_kernel<<<(NN + 255) / 256, 256>>>();

    copy_split_ns_kernel<<<(NROWS * DD + 255) / 256, 256>>>(nodes);

    for (int s = 0; s < STEPS; s++) {
        gemm_kernel<0, 8><<<dim3(NROWS / 128, 8), 256, SMEM_GEMM>>>(nullptr);   // PQ
        gather_kernel<<<dim3(NN, BB), 128>>>(be1);                              // hacc fp16
        gemm_kernel<2, 24><<<dim3(NROWS / 128, 4), 256, SMEM_GEMM>>>(bn1);      // h
        gemm_kernel<3, 16><<<dim3(NROWS / 128, 2), 256, SMEM_GEMM>>>(bn2);      // ns +=
    }

    zero_out_kernel<<<(BB * PP * DD + 255) / 256, 256>>>(out, BB * PP * DD);
    extract_kernel<<<dim3(NN / 256, BB), 256, SMEM_EXT>>>(attn, out);
}

// round 14
// speedup vs baseline: 12.5232x; 1.1127x over previous
#include <cuda_runtime.h>
#include <cuda_fp16.h>
#include <cstdint>

#define BB   8
#define NN   4096
#define EE   16384
#define PP   64
#define DD   256
#define HH   512
#define MSG  256
#define UPD  254
#define STEPS 3

#define NROWS (BB * NN)   // 32768
#define ADJ_CAP 64

typedef unsigned long long u64;

// ---------------------------------------------------------------------------
// Device globals
// ---------------------------------------------------------------------------
__device__ float g_ns  [NROWS * DD];            // fp32 node state (master)
__device__ float g_Wf  [512 * 512];             // We2 @ Wn1_top
__device__ float g_b2n1[512];                   // b_e2 @ Wn1_top
__device__ float g_degf[NN];
__device__ int   g_deg [NN];
__device__ int   g_adj [NN * ADJ_CAP];

// fp16 activation planes
__device__ __half g_PQ_h  [(size_t)NROWS * 1024];  // P (0..511) | Q (512..1023)
__device__ __half g_ns_h  [NROWS * DD];
__device__ __half g_hacc_h[NROWS * HH];
__device__ __half g_h_h   [(size_t)NROWS * HH];

// fp16 weightT planes (rows = output col n, k contiguous)
__device__ __half g_WPQT_h[1024 * 256];                       // single term
__device__ __half g_WfT_h [512 * 768],  g_WfT_l [512 * 768];  // [Wf | Wn1_bot] hi/lo
__device__ __half g_Wn2T_h[256 * 512],  g_Wn2T_l[256 * 512];

// ---------------------------------------------------------------------------
// PTX helpers
// ---------------------------------------------------------------------------
__device__ __forceinline__ uint32_t smem_u32(const void* p) {
    uint32_t a;
    asm("{ .reg .u64 t; cvta.to.shared.u64 t, %1; cvt.u32.u64 %0, t; }" : "=r"(a) : "l"(p));
    return a;
}
__device__ __forceinline__ void ldsm4(uint32_t* r, uint32_t a) {
    asm volatile("ldmatrix.sync.aligned.m8n8.x4.shared.b16 {%0,%1,%2,%3}, [%4];"
        : "=r"(r[0]), "=r"(r[1]), "=r"(r[2]), "=r"(r[3]) : "r"(a));
}
__device__ __forceinline__ void mma_f16(float* c, const uint32_t* a, uint32_t b0, uint32_t b1) {
    asm volatile("mma.sync.aligned.m16n8k16.row.col.f32.f16.f16.f32 "
        "{%0,%1,%2,%3}, {%4,%5,%6,%7}, {%8,%9}, {%0,%1,%2,%3};"
        : "+f"(c[0]), "+f"(c[1]), "+f"(c[2]), "+f"(c[3])
        : "r"(a[0]), "r"(a[1]), "r"(a[2]), "r"(a[3]), "r"(b0), "r"(b1));
}
__device__ __forceinline__ void cpa16(uint32_t d, const void* s) {
    asm volatile("cp.async.cg.shared.global [%0], [%1], 16;" :: "r"(d), "l"(s) : "memory");
}
#define CP_COMMIT() asm volatile("cp.async.commit_group;" ::: "memory")
#define CP_WAIT1()  asm volatile("cp.async.wait_group 1;" ::: "memory")
#define CP_WAIT0()  asm volatile("cp.async.wait_group 0;" ::: "memory")

__device__ __forceinline__ void split_f16(float v, __half& h, __half& l) {
    h = __float2half_rn(v);
    l = __float2half_rn(v - __half2float(h));
}
__device__ __forceinline__ uint32_t pack_h2(__half a, __half b) {
    return ((uint32_t)__half_as_ushort(b) << 16) | __half_as_ushort(a);
}

// ---------------------------------------------------------------------------
// Utility kernels
// ---------------------------------------------------------------------------
__global__ void copy_split_ns_kernel(const float* __restrict__ src) {
    int i = blockIdx.x * blockDim.x + threadIdx.x;
    if (i < NROWS * DD) {
        float v = src[i];
        g_ns[i] = v;
        g_ns_h[i] = __float2half_rn(v);
    }
}
__global__ void zero_out_kernel(float* __restrict__ out, int n) {
    int i = blockIdx.x * blockDim.x + threadIdx.x;
    if (i < n) out[i] = 0.0f;
}
__global__ void zero_deg_kernel() {
    int i = blockIdx.x * blockDim.x + threadIdx.x;
    if (i < NN) g_deg[i] = 0;
}
__global__ void build_adj_kernel(const int* __restrict__ esrc, const int* __restrict__ esnk) {
    int i = blockIdx.x * blockDim.x + threadIdx.x;
    if (i < EE) {
        int snk = esnk[i];
        int pos = atomicAdd(&g_deg[snk], 1);
        if (pos < ADJ_CAP) g_adj[snk * ADJ_CAP + pos] = esrc[i];
    }
}
__global__ void degf_kernel() {
    int i = blockIdx.x * blockDim.x + threadIdx.x;
    if (i < NN) g_degf[i] = (float)g_deg[i];
}
// WT[n][k] = W[k][n] (fp16 hi/lo), rows n >= N zero-padded; W is [512][N]
__global__ void splitT_kernel(const float* __restrict__ W,
                              __half* __restrict__ hi, __half* __restrict__ lo,
                              int N, int NT) {
    int i = blockIdx.x * blockDim.x + threadIdx.x;
    if (i < NT * 512) {
        int n = i >> 9, k = i & 511;
        float v = (n < N) ? W[k * N + n] : 0.0f;
        __half h, l;
        split_f16(v, h, l);
        hi[i] = h; lo[i] = l;
    }
}
// WPQT[n][k] single fp16 plane, n in [0,1024), k in [0,256)
__global__ void splitT_PQ_kernel(const float* __restrict__ We1) {
    int i = blockIdx.x * blockDim.x + threadIdx.x;
    if (i < 1024 * 256) {
        int n = i >> 8, k = i & 255;
        float v = (n < 512) ? We1[k * HH + n] : We1[(256 + k) * HH + (n - 512)];
        g_WPQT_h[i] = __float2half_rn(v);
    }
}
// Wf = We2(512x256) @ Wn1_top(256x512), smem-tiled 64x64
__global__ __launch_bounds__(256)
void fuse_w_kernel(const float* __restrict__ We2, const float* __restrict__ Wn1) {
    __shared__ float sA[64][65];
    __shared__ float sB[64][65];
    const int tid = threadIdx.x;
    const int k0 = blockIdx.y * 64, n0 = blockIdx.x * 64;
    const int ty = tid >> 4, tx = tid & 15;
    float acc[4][4];
    #pragma unroll
    for (int i = 0; i < 4; i++)
        #pragma unroll
        for (int l = 0; l < 4; l++) acc[i][l] = 0.0f;

    for (int j0 = 0; j0 < 256; j0 += 64) {
        #pragma unroll
        for (int it = 0; it < 16; it++) {
            int u = tid + it * 256;
            int r = u >> 6, c = u & 63;
            sA[r][c] = We2[(k0 + r) * MSG + j0 + c];
            sB[r][c] = Wn1[(j0 + r) * HH + n0 + c];
        }
        __syncthreads();
        #pragma unroll 8
        for (int jj = 0; jj < 64; jj++) {
            float a[4], b[4];
            #pragma unroll
            for (int i = 0; i < 4; i++) a[i] = sA[ty * 4 + i][jj];
            #pragma unroll
            for (int l = 0; l < 4; l++) b[l] = sB[jj][tx * 4 + l];
            #pragma unroll
            for (int i = 0; i < 4; i++)
                #pragma unroll
                for (int l = 0; l < 4; l++) acc[i][l] = fmaf(a[i], b[l], acc[i][l]);
        }
        __syncthreads();
    }
    #pragma unroll
    for (int i = 0; i < 4; i++)
        #pragma unroll
        for (int l = 0; l < 4; l++)
            g_Wf[(k0 + ty * 4 + i) * 512 + n0 + tx * 4 + l] = acc[i][l];
}
// b2n1[n] = sum_j be2[j] * Wn1[j][n]; grid 16, j-split 8-way + smem reduce
__global__ __launch_bounds__(256)
void b2n1_kernel(const float* __restrict__ be2, const float* __restrict__ Wn1) {
    __shared__ float red[8][33];
    const int tid = threadIdx.x;
    const int nloc = tid & 31, jgrp = tid >> 5;
    const int n = blockIdx.x * 32 + nloc;
    float acc = 0.0f;
    #pragma unroll 8
    for (int i = 0; i < 32; i++) {
        int j = jgrp * 32 + i;
        acc = fmaf(be2[j], Wn1[j * HH + n], acc);
    }
    red[jgrp][nloc] = acc;
    __syncthreads();
    if (jgrp == 0) {
        float s = acc;
        #pragma unroll
        for (int g = 1; g < 8; g++) s += red[g][nloc];
        g_b2n1[n] = s;
    }
}
// WfT[n][k]: k<512 -> Wf[k][n]; k>=512 -> Wn1[256+(k-512)][n]  (fp16 hi/lo)
__global__ void splitT_Wf_kernel(const float* __restrict__ Wn1) {
    int i = blockIdx.x * blockDim.x + threadIdx.x;
    if (i < 512 * 768) {
        int n = i / 768, k = i % 768;
        float v = (k < 512) ? g_Wf[k * 512 + n] : Wn1[(256 + k - 512) * HH + n];
        __half h, l;
        split_f16(v, h, l);
        g_WfT_h[i] = h; g_WfT_l[i] = l;
    }
}

// ---------------------------------------------------------------------------
// gather: hacc[n] = sum_{src in adj[n]} relu(P[src] + Q[n] + b_e1)  (fp16 P/Q)
// ---------------------------------------------------------------------------
__global__ __launch_bounds__(128)
void gather_kernel(const float* __restrict__ be1)
{
    const int n = blockIdx.x, b = blockIdx.y, t = threadIdx.x;
    const size_t rowb = (size_t)(b * NN + n);

    uint2 qraw = ((const uint2*)(g_PQ_h + rowb * 1024 + 512))[t];
    float2 q01 = __half22float2(*(const __half2*)&qraw.x);
    float2 q23 = __half22float2(*(const __half2*)&qraw.y);
    const float4 bv = ((const float4*)be1)[t];
    float4 qb = { q01.x + bv.x, q01.y + bv.y, q23.x + bv.z, q23.y + bv.w };

    float4 acc = make_float4(0.0f, 0.0f, 0.0f, 0.0f);
    const int deg = g_deg[n];
    const int* __restrict__ adj = g_adj + n * ADJ_CAP;
    const __half* __restrict__ Pb = g_PQ_h + (size_t)(b * NN) * 1024;

    for (int i = 0; i < deg; i++) {
        int src = adj[i];
        uint2 praw = ((const uint2*)(Pb + (size_t)src * 1024))[t];
        float2 p01 = __half22float2(*(const __half2*)&praw.x);
        float2 p23 = __half22float2(*(const __half2*)&praw.y);
        acc.x += fmaxf(p01.x + qb.x, 0.0f);
        acc.y += fmaxf(p01.y + qb.y, 0.0f);
        acc.z += fmaxf(p23.x + qb.z, 0.0f);
        acc.w += fmaxf(p23.y + qb.w, 0.0f);
    }

    uint2 v;
    v.x = pack_h2(__float2half_rn(acc.x), __float2half_rn(acc.y));
    v.y = pack_h2(__float2half_rn(acc.z), __float2half_rn(acc.w));
    ((uint2*)(g_hacc_h + rowb * HH))[t] = v;
}

// ---------------------------------------------------------------------------
// Streaming mma.sync GEMM, fp16; NTERM weight terms (1 or 2).
// 128x128 CTA tile, single-sync 3-buf/2-ahead ring, stage 24KB.
//   MODE 0 (KST=8,  NTERM=1): PQ = ns @ WPQ                  epi: fp16 -> g_PQ_h
//   MODE 2 (KST=24, NTERM=2): h = relu([hacc|ns]@WfT + ...)  epi: fp16 -> g_h_h
//   MODE 3 (KST=16, NTERM=2): ns += h@Wn2 + bn2              epi: fp32 ns + fp16 ns_h
// ---------------------------------------------------------------------------
#define STAGE_SZ (24 * 1024)
#define AOF      0
#define BOF_HI   (8 * 1024)
#define BOF_LO   (16 * 1024)
#define SMEM_GEMM (3 * STAGE_SZ)

__device__ __forceinline__ uint32_t plane_addr(int row, int cb) {
    return (uint32_t)(row * 64 + ((cb ^ ((row >> 1) & 3)) << 4));
}

template <int MODE, int KST, int NTERM>
__global__ __launch_bounds__(256, 2)
void gemm_kernel(const float* __restrict__ bias)
{
    extern __shared__ char sm[];
    const int tid  = threadIdx.x;
    const int wid  = tid >> 5, lane = tid & 31;
    const int r0   = blockIdx.x * 128;
    const int n0   = blockIdx.y * 128;
    const uint32_t smb = smem_u32(sm);

    const __half *bt_hi, *bt_lo;
    if      (MODE == 0) { bt_hi = g_WPQT_h; bt_lo = g_WPQT_h; }
    else if (MODE == 2) { bt_hi = g_WfT_h;  bt_lo = g_WfT_l;  }
    else                { bt_hi = g_Wn2T_h; bt_lo = g_Wn2T_l; }
    const int BSTR = (MODE == 0) ? 256 : (MODE == 2) ? 768 : 512;

    auto load_stage = [&](int c, int buf) {
        uint32_t sb = smb + buf * STAGE_SZ;
        // A: 128 rows x 32 k fp16 = 512 x 16B chunks
        #pragma unroll
        for (int it = 0; it < 2; it++) {
            int u = tid + it * 256;
            int row = u >> 2, cb = u & 3;
            const __half* src;
            if (MODE == 0) {
                src = g_ns_h + (size_t)(r0 + row) * DD + c * 32 + cb * 8;
            } else if (MODE == 2) {
                src = (c < 16)
                    ? g_hacc_h + (size_t)(r0 + row) * HH + c * 32 + cb * 8
                    : g_ns_h   + (size_t)(r0 + row) * DD + (c - 16) * 32 + cb * 8;
            } else {
                src = g_h_h + (size_t)(r0 + row) * HH + c * 32 + cb * 8;
            }
            cpa16(sb + AOF + plane_addr(row, cb), src);
        }
        // B: 128 n-rows x 32 k, hi (+ lo if NTERM==2)
        #pragma unroll
        for (int it = 0; it < 2 * NTERM; it++) {
            int u = tid + it * 256;
            int hi = (u < 512);
            int v = u & 511;
            int row = v >> 2, cb = v & 3;
            const __half* src = (hi ? bt_hi : bt_lo) + (size_t)(n0 + row) * BSTR + c * 32 + cb * 8;
            cpa16(sb + (hi ? BOF_HI : BOF_LO) + plane_addr(row, cb), src);
        }
    };

    float acc[4][4][4];
    #pragma unroll
    for (int mi = 0; mi < 4; mi++)
        #pragma unroll
        for (int nj = 0; nj < 4; nj++)
            #pragma unroll
            for (int q = 0; q < 4; q++) acc[mi][nj][q] = 0.0f;

    load_stage(0, 0); CP_COMMIT();
    load_stage(1, 1); CP_COMMIT();

    const int wm = wid & 1, wn = wid >> 1;
    const int la15 = lane & 15, la_h = lane >> 4;
    const int lb_n = (lane & 7) + ((lane >> 4) << 3);
    const int lb_kh = (lane >> 3) & 1;
    const int rq = lane >> 2, cq = (lane & 3) * 2;

    #pragma unroll 1
    for (int c = 0; c < KST; c++) {
        if (c + 2 < KST) { CP_WAIT1(); } else { CP_WAIT0(); }
        __syncthreads();
        if (c + 2 < KST) { load_stage(c + 2, (c + 2) % 3); CP_COMMIT(); }

        uint32_t sb = smb + (c % 3) * STAGE_SZ;
        #pragma unroll
        for (int ks = 0; ks < 2; ks++) {
            uint32_t bh[2][4], bl[2][4];
            #pragma unroll
            for (int p = 0; p < 2; p++) {
                int row = wn * 32 + p * 16 + lb_n;
                uint32_t ad = sb + BOF_HI + plane_addr(row, ks * 2 + lb_kh);
                ldsm4(bh[p], ad);
                if (NTERM == 2) ldsm4(bl[p], ad + (BOF_LO - BOF_HI));
            }
            #pragma unroll
            for (int mi = 0; mi < 4; mi++) {
                int row = wm * 64 + mi * 16 + la15;
                uint32_t a[4];
                ldsm4(a, sb + AOF + plane_addr(row, ks * 2 + la_h));
                #pragma unroll
                for (int p = 0; p < 2; p++) {
                    mma_f16(acc[mi][2 * p],     a, bh[p][0], bh[p][1]);
                    mma_f16(acc[mi][2 * p + 1], a, bh[p][2], bh[p][3]);
                    if (NTERM == 2) {
                        mma_f16(acc[mi][2 * p],     a, bl[p][0], bl[p][1]);
                        mma_f16(acc[mi][2 * p + 1], a, bl[p][2], bl[p][3]);
                    }
                }
            }
        }
    }

    // ---- epilogue ----
    #pragma unroll
    for (int mi = 0; mi < 4; mi++) {
        #pragma unroll
        for (int nj = 0; nj < 4; nj++) {
            int col = n0 + wn * 32 + nj * 8 + cq;
            float* a4 = acc[mi][nj];
            if (MODE == 0) {
                #pragma unroll
                for (int half = 0; half < 2; half++) {
                    int rl = wm * 64 + mi * 16 + rq + half * 8;
                    *(uint32_t*)(g_PQ_h + (size_t)(r0 + rl) * 1024 + col) =
                        pack_h2(__float2half_rn(a4[2 * half]), __float2half_rn(a4[2 * half + 1]));
                }
            } else if (MODE == 2) {
                float2 bv = *(const float2*)(bias + col);
                float2 b2 = *(const float2*)(g_b2n1 + col);
                #pragma unroll
                for (int half = 0; half < 2; half++) {
                    int rl = wm * 64 + mi * 16 + rq + half * 8;
                    float dg = g_degf[(r0 + rl) & (NN - 1)];
                    float v0 = fmaxf(a4[2 * half]     + bv.x + dg * b2.x, 0.0f);
                    float v1 = fmaxf(a4[2 * half + 1] + bv.y + dg * b2.y, 0.0f);
                    size_t go = (size_t)(r0 + rl) * HH + col;
                    *(uint32_t*)(g_h_h + go) = pack_h2(__float2half_rn(v0), __float2half_rn(v1));
                }
            } else {  // MODE 3
                #pragma unroll
                for (int half = 0; half < 2; half++) {
                    int rl = wm * 64 + mi * 16 + rq + half * 8;
                    size_t ro = (size_t)(r0 + rl) * DD + 2;
                    if (col < UPD) {
                        float nv = g_ns[ro + col] + a4[2 * half] + bias[col];
                        g_ns[ro + col] = nv;
                        g_ns_h[ro + col] = __float2half_rn(nv);
                    }
                    if (col + 1 < UPD) {
                        float nv = g_ns[ro + col + 1] + a4[2 * half + 1] + bias[col + 1];
                        g_ns[ro + col + 1] = nv;
                        g_ns_h[ro + col + 1] = __float2half_rn(nv);
                    }
                }
            }
        }
    }
}

// ---------------------------------------------------------------------------
// Extraction (FFMA2 SIMT, fp32 exact from g_ns)
// ---------------------------------------------------------------------------
__device__ __forceinline__ u64 ffma2(u64 a, u64 b, u64 c) {
    u64 d; asm("fma.rn.f32x2 %0, %1, %2, %3;" : "=l"(d) : "l"(a), "l"(b), "l"(c)); return d;
}
__device__ __forceinline__ u64 pack2(float lo, float hi) {
    u64 d; asm("mov.b64 %0, {%1, %2};" : "=l"(d) : "f"(lo), "f"(hi)); return d;
}
__device__ __forceinline__ void unpack2(u64 v, float& lo, float& hi) {
    asm("mov.b64 {%0, %1}, %2;" : "=f"(lo), "=f"(hi) : "l"(v));
}

__global__ __launch_bounds__(256)
void extract_kernel(const float* __restrict__ attn, float* __restrict__ out)
{
    extern __shared__ float smA[];   // 256 * 66
    const int tid = threadIdx.x;
    const int b   = blockIdx.y;
    const int n0  = blockIdx.x * 256;
    const float* __restrict__ nsb = g_ns + (size_t)b * NN * DD;

    #pragma unroll 4
    for (int idx = tid; idx < 64 * 256; idx += 256) {
        int p = idx >> 8, j = idx & 255;
        smA[j * 66 + p] = attn[((size_t)b * PP + p) * NN + n0 + j];
    }
    __syncthreads();

    const int d = tid;
    u64 accp[32];
    #pragma unroll
    for (int pj = 0; pj < 32; pj++) accp[pj] = 0ull;

    for (int n = 0; n < 256; n++) {
        float s = nsb[(n0 + n) * DD + d];
        u64 sp = pack2(s, s);
        const u64* arow = (const u64*)(smA + n * 66);
        #pragma unroll
        for (int pj = 0; pj < 32; pj++) accp[pj] = ffma2(arow[pj], sp, accp[pj]);
    }
    #pragma unroll
    for (int pj = 0; pj < 32; pj++) {
        float lo, hi; unpack2(accp[pj], lo, hi);
        atomicAdd(&out[((size_t)b * PP + 2 * pj)     * DD + d], lo);
        atomicAdd(&out[((size_t)b * PP + 2 * pj + 1) * DD + d], hi);
    }
}

// ---------------------------------------------------------------------------
extern "C" void kernel_launch(void* const* d_in, const int* in_sizes, int n_in,
                              void* d_out, int out_size)
{
    const float* nodes = (const float*)d_in[0];
    const float* attn  = (const float*)d_in[1];
    const float* We1   = (const float*)d_in[2];
    const float* be1   = (const float*)d_in[3];
    const float* We2   = (const float*)d_in[4];
    const float* be2   = (const float*)d_in[5];
    const float* Wn1   = (const float*)d_in[6];
    const float* bn1   = (const float*)d_in[7];
    const float* Wn2   = (const float*)d_in[8];
    const float* bn2   = (const float*)d_in[9];
    const int*   esrc  = (const int*)d_in[10];
    const int*   esnk  = (const int*)d_in[11];
    float* out = (float*)d_out;

    cudaFuncSetAttribute((const void*)gemm_kernel<0, 8, 1>,  cudaFuncAttributeMaxDynamicSharedMemorySize, SMEM_GEMM);
    cudaFuncSetAttribute((const void*)gemm_kernel<2, 24, 2>, cudaFuncAttributeMaxDynamicSharedMemorySize, SMEM_GEMM);
    cudaFuncSetAttribute((const void*)gemm_kernel<3, 16, 2>, cudaFuncAttributeMaxDynamicSharedMemorySize, SMEM_GEMM);
    const int SMEM_EXT = 256 * 66 * 4;
    cudaFuncSetAttribute((const void*)extract_kernel, cudaFuncAttributeMaxDynamicSharedMemorySize, SMEM_EXT);

    __half *wn2h, *wn2l;
    cudaGetSymbolAddress((void**)&wn2h, g_Wn2T_h); cudaGetSymbolAddress((void**)&wn2l, g_Wn2T_l);

    splitT_PQ_kernel<<<(1024 * 256 + 255) / 256, 256>>>(We1);
    splitT_kernel<<<(256 * 512 + 255) / 256, 256>>>(Wn2, wn2h, wn2l, UPD, 256);
    fuse_w_kernel<<<dim3(8, 8), 256>>>(We2, Wn1);
    b2n1_kernel<<<16, 256>>>(be2, Wn1);
    splitT_Wf_kernel<<<(512 * 768 + 255) / 256, 256>>>(Wn1);

    zero_deg_kernel<<<(NN + 255) / 256, 256>>>();
    build_adj_kernel<<<(EE + 255) / 256, 256>>>(esrc, esnk);
    degf_kernel<<<(NN + 255) / 256, 256>>>();

    copy_split_ns_kernel<<<(NROWS * DD + 255) / 256, 256>>>(nodes);

    for (int s = 0; s < STEPS; s++) {
        gemm_kernel<0, 8, 1><<<dim3(NROWS / 128, 8), 256, SMEM_GEMM>>>(nullptr);  // PQ
        gather_kernel<<<dim3(NN, BB), 128>>>(be1);                                // hacc fp16
        gemm_kernel<2, 24, 2><<<dim3(NROWS / 128, 4), 256, SMEM_GEMM>>>(bn1);     // h
        gemm_kernel<3, 16, 2><<<dim3(NROWS / 128, 2), 256, SMEM_GEMM>>>(bn2);     // ns +=
    }

    zero_out_kernel<<<(BB * PP * DD + 255) / 256, 256>>>(out, BB * PP * DD);
    extract_kernel<<<dim3(NN / 256, BB), 256, SMEM_EXT>>>(attn, out);
}

// round 15
// speedup vs baseline: 15.1647x; 1.2109x over previous
#include <cuda_runtime.h>
#include <cuda_fp16.h>
#include <cstdint>

#define BB   8
#define NN   4096
#define EE   16384
#define PP   64
#define DD   256
#define HH   512
#define MSG  256
#define UPD  254
#define STEPS 3

#define NROWS (BB * NN)   // 32768
#define ADJ_CAP 64

typedef unsigned long long u64;

// ---------------------------------------------------------------------------
// Device globals
// ---------------------------------------------------------------------------
__device__ float g_ns  [NROWS * DD];            // fp32 node state (master)
__device__ float g_Wf  [512 * 512];             // We2 @ Wn1_top
__device__ float g_b2n1[512];                   // b_e2 @ Wn1_top
__device__ float g_degf[NN];
__device__ int   g_deg [NN];
__device__ int   g_adj [NN * ADJ_CAP];

// fp16 activation planes
__device__ __half g_PQ_h  [(size_t)NROWS * 1024];  // P (0..511) | Q (512..1023)
__device__ __half g_ns_h  [NROWS * DD];
__device__ __half g_hacc_h[NROWS * HH];
__device__ __half g_h_h   [(size_t)NROWS * HH];

// fp16 weightT planes (rows = output col n, k contiguous) — single term
__device__ __half g_WPQT_h[1024 * 256];
__device__ __half g_WfT_h [512 * 768];   // [Wf | Wn1_bot]
__device__ __half g_Wn2T_h[256 * 512];

// ---------------------------------------------------------------------------
// PTX helpers
// ---------------------------------------------------------------------------
__device__ __forceinline__ uint32_t smem_u32(const void* p) {
    uint32_t a;
    asm("{ .reg .u64 t; cvta.to.shared.u64 t, %1; cvt.u32.u64 %0, t; }" : "=r"(a) : "l"(p));
    return a;
}
__device__ __forceinline__ void ldsm4(uint32_t* r, uint32_t a) {
    asm volatile("ldmatrix.sync.aligned.m8n8.x4.shared.b16 {%0,%1,%2,%3}, [%4];"
        : "=r"(r[0]), "=r"(r[1]), "=r"(r[2]), "=r"(r[3]) : "r"(a));
}
__device__ __forceinline__ void mma_f16(float* c, const uint32_t* a, uint32_t b0, uint32_t b1) {
    asm volatile("mma.sync.aligned.m16n8k16.row.col.f32.f16.f16.f32 "
        "{%0,%1,%2,%3}, {%4,%5,%6,%7}, {%8,%9}, {%0,%1,%2,%3};"
        : "+f"(c[0]), "+f"(c[1]), "+f"(c[2]), "+f"(c[3])
        : "r"(a[0]), "r"(a[1]), "r"(a[2]), "r"(a[3]), "r"(b0), "r"(b1));
}
__device__ __forceinline__ void cpa16(uint32_t d, const void* s) {
    asm volatile("cp.async.cg.shared.global [%0], [%1], 16;" :: "r"(d), "l"(s) : "memory");
}
#define CP_COMMIT() asm volatile("cp.async.commit_group;" ::: "memory")
#define CP_WAIT1()  asm volatile("cp.async.wait_group 1;" ::: "memory")
#define CP_WAIT0()  asm volatile("cp.async.wait_group 0;" ::: "memory")

__device__ __forceinline__ uint32_t pack_h2(__half a, __half b) {
    return ((uint32_t)__half_as_ushort(b) << 16) | __half_as_ushort(a);
}

// ---------------------------------------------------------------------------
// Utility kernels
// ---------------------------------------------------------------------------
__global__ void copy_split_ns_kernel(const float* __restrict__ src) {
    int i = blockIdx.x * blockDim.x + threadIdx.x;
    if (i < NROWS * DD) {
        float v = src[i];
        g_ns[i] = v;
        g_ns_h[i] = __float2half_rn(v);
    }
}
__global__ void zero_out_kernel(float* __restrict__ out, int n) {
    int i = blockIdx.x * blockDim.x + threadIdx.x;
    if (i < n) out[i] = 0.0f;
}
__global__ void zero_deg_kernel() {
    int i = blockIdx.x * blockDim.x + threadIdx.x;
    if (i < NN) g_deg[i] = 0;
}
__global__ void build_adj_kernel(const int* __restrict__ esrc, const int* __restrict__ esnk) {
    int i = blockIdx.x * blockDim.x + threadIdx.x;
    if (i < EE) {
        int snk = esnk[i];
        int pos = atomicAdd(&g_deg[snk], 1);
        if (pos < ADJ_CAP) g_adj[snk * ADJ_CAP + pos] = esrc[i];
    }
}
__global__ void degf_kernel() {
    int i = blockIdx.x * blockDim.x + threadIdx.x;
    if (i < NN) g_degf[i] = (float)g_deg[i];
}
// WT[n][k] = W[k][n] single fp16 plane, rows n >= N zero-padded; W is [512][N]
__global__ void splitT_kernel(const float* __restrict__ W,
                              __half* __restrict__ hi, int N, int NT) {
    int i = blockIdx.x * blockDim.x + threadIdx.x;
    if (i < NT * 512) {
        int n = i >> 9, k = i & 511;
        float v = (n < N) ? W[k * N + n] : 0.0f;
        hi[i] = __float2half_rn(v);
    }
}
// WPQT[n][k] single fp16 plane, n in [0,1024), k in [0,256)
__global__ void splitT_PQ_kernel(const float* __restrict__ We1) {
    int i = blockIdx.x * blockDim.x + threadIdx.x;
    if (i < 1024 * 256) {
        int n = i >> 8, k = i & 255;
        float v = (n < 512) ? We1[k * HH + n] : We1[(256 + k) * HH + (n - 512)];
        g_WPQT_h[i] = __float2half_rn(v);
    }
}
// Wf = We2(512x256) @ Wn1_top(256x512), smem-tiled 64x64
__global__ __launch_bounds__(256)
void fuse_w_kernel(const float* __restrict__ We2, const float* __restrict__ Wn1) {
    __shared__ float sA[64][65];
    __shared__ float sB[64][65];
    const int tid = threadIdx.x;
    const int k0 = blockIdx.y * 64, n0 = blockIdx.x * 64;
    const int ty = tid >> 4, tx = tid & 15;
    float acc[4][4];
    #pragma unroll
    for (int i = 0; i < 4; i++)
        #pragma unroll
        for (int l = 0; l < 4; l++) acc[i][l] = 0.0f;

    for (int j0 = 0; j0 < 256; j0 += 64) {
        #pragma unroll
        for (int it = 0; it < 16; it++) {
            int u = tid + it * 256;
            int r = u >> 6, c = u & 63;
            sA[r][c] = We2[(k0 + r) * MSG + j0 + c];
            sB[r][c] = Wn1[(j0 + r) * HH + n0 + c];
        }
        __syncthreads();
        #pragma unroll 8
        for (int jj = 0; jj < 64; jj++) {
            float a[4], b[4];
            #pragma unroll
            for (int i = 0; i < 4; i++) a[i] = sA[ty * 4 + i][jj];
            #pragma unroll
            for (int l = 0; l < 4; l++) b[l] = sB[jj][tx * 4 + l];
            #pragma unroll
            for (int i = 0; i < 4; i++)
                #pragma unroll
                for (int l = 0; l < 4; l++) acc[i][l] = fmaf(a[i], b[l], acc[i][l]);
        }
        __syncthreads();
    }
    #pragma unroll
    for (int i = 0; i < 4; i++)
        #pragma unroll
        for (int l = 0; l < 4; l++)
            g_Wf[(k0 + ty * 4 + i) * 512 + n0 + tx * 4 + l] = acc[i][l];
}
// b2n1[n] = sum_j be2[j] * Wn1[j][n]; grid 16, j-split 8-way + smem reduce
__global__ __launch_bounds__(256)
void b2n1_kernel(const float* __restrict__ be2, const float* __restrict__ Wn1) {
    __shared__ float red[8][33];
    const int tid = threadIdx.x;
    const int nloc = tid & 31, jgrp = tid >> 5;
    const int n = blockIdx.x * 32 + nloc;
    float acc = 0.0f;
    #pragma unroll 8
    for (int i = 0; i < 32; i++) {
        int j = jgrp * 32 + i;
        acc = fmaf(be2[j], Wn1[j * HH + n], acc);
    }
    red[jgrp][nloc] = acc;
    __syncthreads();
    if (jgrp == 0) {
        float s = acc;
        #pragma unroll
        for (int g = 1; g < 8; g++) s += red[g][nloc];
        g_b2n1[n] = s;
    }
}
// WfT[n][k]: k<512 -> Wf[k][n]; k>=512 -> Wn1[256+(k-512)][n]  (single fp16)
__global__ void splitT_Wf_kernel(const float* __restrict__ Wn1) {
    int i = blockIdx.x * blockDim.x + threadIdx.x;
    if (i < 512 * 768) {
        int n = i / 768, k = i % 768;
        float v = (k < 512) ? g_Wf[k * 512 + n] : Wn1[(256 + k - 512) * HH + n];
        g_WfT_h[i] = __float2half_rn(v);
    }
}

// ---------------------------------------------------------------------------
// gather: hacc[n] = sum_{src in adj[n]} relu(P[src] + Q[n] + b_e1)  (fp16 P/Q)
// ---------------------------------------------------------------------------
__global__ __launch_bounds__(128)
void gather_kernel(const float* __restrict__ be1)
{
    const int n = blockIdx.x, b = blockIdx.y, t = threadIdx.x;
    const size_t rowb = (size_t)(b * NN + n);

    uint2 qraw = ((const uint2*)(g_PQ_h + rowb * 1024 + 512))[t];
    float2 q01 = __half22float2(*(const __half2*)&qraw.x);
    float2 q23 = __half22float2(*(const __half2*)&qraw.y);
    const float4 bv = ((const float4*)be1)[t];
    float4 qb = { q01.x + bv.x, q01.y + bv.y, q23.x + bv.z, q23.y + bv.w };

    float4 acc = make_float4(0.0f, 0.0f, 0.0f, 0.0f);
    const int deg = g_deg[n];
    const int* __restrict__ adj = g_adj + n * ADJ_CAP;
    const __half* __restrict__ Pb = g_PQ_h + (size_t)(b * NN) * 1024;

    for (int i = 0; i < deg; i++) {
        int src = adj[i];
        uint2 praw = ((const uint2*)(Pb + (size_t)src * 1024))[t];
        float2 p01 = __half22float2(*(const __half2*)&praw.x);
        float2 p23 = __half22float2(*(const __half2*)&praw.y);
        acc.x += fmaxf(p01.x + qb.x, 0.0f);
        acc.y += fmaxf(p01.y + qb.y, 0.0f);
        acc.z += fmaxf(p23.x + qb.z, 0.0f);
        acc.w += fmaxf(p23.y + qb.w, 0.0f);
    }

    uint2 v;
    v.x = pack_h2(__float2half_rn(acc.x), __float2half_rn(acc.y));
    v.y = pack_h2(__float2half_rn(acc.z), __float2half_rn(acc.w));
    ((uint2*)(g_hacc_h + rowb * HH))[t] = v;
}

// ---------------------------------------------------------------------------
// Streaming mma.sync GEMM, fp16 single weight term.
// 128x128 CTA tile, single-sync 3-buf/2-ahead ring, stage 16KB (A 8K + B 8K).
//   MODE 0 (KST=8):  PQ = ns @ WPQ                         epi: fp16 -> g_PQ_h
//   MODE 2 (KST=24): h = relu([hacc|ns]@WfT + bn1 + deg*b2n1)  epi: fp16 -> g_h_h
//   MODE 3 (KST=16): ns += h@Wn2 + bn2                     epi: fp32 ns + fp16 ns_h
// ---------------------------------------------------------------------------
#define STAGE_SZ (16 * 1024)
#define AOF      0
#define BOF      (8 * 1024)
#define SMEM_GEMM (3 * STAGE_SZ)

__device__ __forceinline__ uint32_t plane_addr(int row, int cb) {
    return (uint32_t)(row * 64 + ((cb ^ ((row >> 1) & 3)) << 4));
}

template <int MODE, int KST>
__global__ __launch_bounds__(256, 2)
void gemm_kernel(const float* __restrict__ bias)
{
    extern __shared__ char sm[];
    const int tid  = threadIdx.x;
    const int wid  = tid >> 5, lane = tid & 31;
    const int r0   = blockIdx.x * 128;
    const int n0   = blockIdx.y * 128;
    const uint32_t smb = smem_u32(sm);

    const __half* bt;
    if      (MODE == 0) bt = g_WPQT_h;
    else if (MODE == 2) bt = g_WfT_h;
    else                bt = g_Wn2T_h;
    const int BSTR = (MODE == 0) ? 256 : (MODE == 2) ? 768 : 512;

    auto load_stage = [&](int c, int buf) {
        uint32_t sb = smb + buf * STAGE_SZ;
        // A: 128 rows x 32 k fp16
        #pragma unroll
        for (int it = 0; it < 2; it++) {
            int u = tid + it * 256;
            int row = u >> 2, cb = u & 3;
            const __half* src;
            if (MODE == 0) {
                src = g_ns_h + (size_t)(r0 + row) * DD + c * 32 + cb * 8;
            } else if (MODE == 2) {
                src = (c < 16)
                    ? g_hacc_h + (size_t)(r0 + row) * HH + c * 32 + cb * 8
                    : g_ns_h   + (size_t)(r0 + row) * DD + (c - 16) * 32 + cb * 8;
            } else {
                src = g_h_h + (size_t)(r0 + row) * HH + c * 32 + cb * 8;
            }
            cpa16(sb + AOF + plane_addr(row, cb), src);
        }
        // B: 128 n-rows x 32 k
        #pragma unroll
        for (int it = 0; it < 2; it++) {
            int u = tid + it * 256;
            int row = u >> 2, cb = u & 3;
            const __half* src = bt + (size_t)(n0 + row) * BSTR + c * 32 + cb * 8;
            cpa16(sb + BOF + plane_addr(row, cb), src);
        }
    };

    float acc[4][4][4];
    #pragma unroll
    for (int mi = 0; mi < 4; mi++)
        #pragma unroll
        for (int nj = 0; nj < 4; nj++)
            #pragma unroll
            for (int q = 0; q < 4; q++) acc[mi][nj][q] = 0.0f;

    load_stage(0, 0); CP_COMMIT();
    load_stage(1, 1); CP_COMMIT();

    const int wm = wid & 1, wn = wid >> 1;
    const int la15 = lane & 15, la_h = lane >> 4;
    const int lb_n = (lane & 7) + ((lane >> 4) << 3);
    const int lb_kh = (lane >> 3) & 1;
    const int rq = lane >> 2, cq = (lane & 3) * 2;

    #pragma unroll 1
    for (int c = 0; c < KST; c++) {
        if (c + 2 < KST) { CP_WAIT1(); } else { CP_WAIT0(); }
        __syncthreads();
        if (c + 2 < KST) { load_stage(c + 2, (c + 2) % 3); CP_COMMIT(); }

        uint32_t sb = smb + (c % 3) * STAGE_SZ;
        #pragma unroll
        for (int ks = 0; ks < 2; ks++) {
            uint32_t bh[2][4];
            #pragma unroll
            for (int p = 0; p < 2; p++) {
                int row = wn * 32 + p * 16 + lb_n;
                ldsm4(bh[p], sb + BOF + plane_addr(row, ks * 2 + lb_kh));
            }
            #pragma unroll
            for (int mi = 0; mi < 4; mi++) {
                int row = wm * 64 + mi * 16 + la15;
                uint32_t a[4];
                ldsm4(a, sb + AOF + plane_addr(row, ks * 2 + la_h));
                #pragma unroll
                for (int p = 0; p < 2; p++) {
                    mma_f16(acc[mi][2 * p],     a, bh[p][0], bh[p][1]);
                    mma_f16(acc[mi][2 * p + 1], a, bh[p][2], bh[p][3]);
                }
            }
        }
    }

    // ---- epilogue ----
    #pragma unroll
    for (int mi = 0; mi < 4; mi++) {
        #pragma unroll
        for (int nj = 0; nj < 4; nj++) {
            int col = n0 + wn * 32 + nj * 8 + cq;
            float* a4 = acc[mi][nj];
            if (MODE == 0) {
                #pragma unroll
                for (int half = 0; half < 2; half++) {
                    int rl = wm * 64 + mi * 16 + rq + half * 8;
                    *(uint32_t*)(g_PQ_h + (size_t)(r0 + rl) * 1024 + col) =
                        pack_h2(__float2half_rn(a4[2 * half]), __float2half_rn(a4[2 * half + 1]));
                }
            } else if (MODE == 2) {
                float2 bv = *(const float2*)(bias + col);
                float2 b2 = *(const float2*)(g_b2n1 + col);
                #pragma unroll
                for (int half = 0; half < 2; half++) {
                    int rl = wm * 64 + mi * 16 + rq + half * 8;
                    float dg = g_degf[(r0 + rl) & (NN - 1)];
                    float v0 = fmaxf(a4[2 * half]     + bv.x + dg * b2.x, 0.0f);
                    float v1 = fmaxf(a4[2 * half + 1] + bv.y + dg * b2.y, 0.0f);
                    size_t go = (size_t)(r0 + rl) * HH + col;
                    *(uint32_t*)(g_h_h + go) = pack_h2(__float2half_rn(v0), __float2half_rn(v1));
                }
            } else {  // MODE 3
                #pragma unroll
                for (int half = 0; half < 2; half++) {
                    int rl = wm * 64 + mi * 16 + rq + half * 8;
                    size_t ro = (size_t)(r0 + rl) * DD + 2;
                    if (col < UPD) {
                        float nv = g_ns[ro + col] + a4[2 * half] + bias[col];
                        g_ns[ro + col] = nv;
                        g_ns_h[ro + col] = __float2half_rn(nv);
                    }
                    if (col + 1 < UPD) {
                        float nv = g_ns[ro + col + 1] + a4[2 * half + 1] + bias[col + 1];
                        g_ns[ro + col + 1] = nv;
                        g_ns_h[ro + col + 1] = __float2half_rn(nv);
                    }
                }
            }
        }
    }
}

// ---------------------------------------------------------------------------
// Extraction (FFMA2 SIMT, fp32 exact from g_ns)
// ---------------------------------------------------------------------------
__device__ __forceinline__ u64 ffma2(u64 a, u64 b, u64 c) {
    u64 d; asm("fma.rn.f32x2 %0, %1, %2, %3;" : "=l"(d) : "l"(a), "l"(b), "l"(c)); return d;
}
__device__ __forceinline__ u64 pack2(float lo, float hi) {
    u64 d; asm("mov.b64 %0, {%1, %2};" : "=l"(d) : "f"(lo), "f"(hi)); return d;
}
__device__ __forceinline__ void unpack2(u64 v, float& lo, float& hi) {
    asm("mov.b64 {%0, %1}, %2;" : "=f"(lo), "=f"(hi) : "l"(v));
}

__global__ __launch_bounds__(256)
void extract_kernel(const float* __restrict__ attn, float* __restrict__ out)
{
    extern __shared__ float smA[];   // 256 * 66
    const int tid = threadIdx.x;
    const int b   = blockIdx.y;
    const int n0  = blockIdx.x * 256;
    const float* __restrict__ nsb = g_ns + (size_t)b * NN * DD;

    #pragma unroll 4
    for (int idx = tid; idx < 64 * 256; idx += 256) {
        int p = idx >> 8, j = idx & 255;
        smA[j * 66 + p] = attn[((size_t)b * PP + p) * NN + n0 + j];
    }
    __syncthreads();

    const int d = tid;
    u64 accp[32];
    #pragma unroll
    for (int pj = 0; pj < 32; pj++) accp[pj] = 0ull;

    for (int n = 0; n < 256; n++) {
        float s = nsb[(n0 + n) * DD + d];
        u64 sp = pack2(s, s);
        const u64* arow = (const u64*)(smA + n * 66);
        #pragma unroll
        for (int pj = 0; pj < 32; pj++) accp[pj] = ffma2(arow[pj], sp, accp[pj]);
    }
    #pragma unroll
    for (int pj = 0; pj < 32; pj++) {
        float lo, hi; unpack2(accp[pj], lo, hi);
        atomicAdd(&out[((size_t)b * PP + 2 * pj)     * DD + d], lo);
        atomicAdd(&out[((size_t)b * PP + 2 * pj + 1) * DD + d], hi);
    }
}

// ---------------------------------------------------------------------------
extern "C" void kernel_launch(void* const* d_in, const int* in_sizes, int n_in,
                              void* d_out, int out_size)
{
    const float* nodes = (const float*)d_in[0];
    const float* attn  = (const float*)d_in[1];
    const float* We1   = (const float*)d_in[2];
    const float* be1   = (const float*)d_in[3];
    const float* We2   = (const float*)d_in[4];
    const float* be2   = (const float*)d_in[5];
    const float* Wn1   = (const float*)d_in[6];
    const float* bn1   = (const float*)d_in[7];
    const float* Wn2   = (const float*)d_in[8];
    const float* bn2   = (const float*)d_in[9];
    const int*   esrc  = (const int*)d_in[10];
    const int*   esnk  = (const int*)d_in[11];
    float* out = (float*)d_out;

    cudaFuncSetAttribute((const void*)gemm_kernel<0, 8>,  cudaFuncAttributeMaxDynamicSharedMemorySize, SMEM_GEMM);
    cudaFuncSetAttribute((const void*)gemm_kernel<2, 24>, cudaFuncAttributeMaxDynamicSharedMemorySize, SMEM_GEMM);
    cudaFuncSetAttribute((const void*)gemm_kernel<3, 16>, cudaFuncAttributeMaxDynamicSharedMemorySize, SMEM_GEMM);
    const int SMEM_EXT = 256 * 66 * 4;
    cudaFuncSetAttribute((const void*)extract_kernel, cudaFuncAttributeMaxDynamicSharedMemorySize, SMEM_EXT);

    __half* wn2h;
    cudaGetSymbolAddress((void**)&wn2h, g_Wn2T_h);

    splitT_PQ_kernel<<<(1024 * 256 + 255) / 256, 256>>>(We1);
    splitT_kernel<<<(256 * 512 + 255) / 256, 256>>>(Wn2, wn2h, UPD, 256);
    fuse_w_kernel<<<dim3(8, 8), 256>>>(We2, Wn1);
    b2n1_kernel<<<16, 256>>>(be2, Wn1);
    splitT_Wf_kernel<<<(512 * 768 + 255) / 256, 256>>>(Wn1);

    zero_deg_kernel<<<(NN + 255) / 256, 256>>>();
    build_adj_kernel<<<(EE + 255) / 256, 256>>>(esrc, esnk);
    degf_kernel<<<(NN + 255) / 256, 256>>>();

    copy_split_ns_kernel<<<(NROWS * DD + 255) / 256, 256>>>(nodes);

    for (int s = 0; s < STEPS; s++) {
        gemm_kernel<0, 8><<<dim3(NROWS / 128, 8), 256, SMEM_GEMM>>>(nullptr);   // PQ
        gather_kernel<<<dim3(NN, BB), 128>>>(be1);                              // hacc fp16
        gemm_kernel<2, 24><<<dim3(NROWS / 128, 4), 256, SMEM_GEMM>>>(bn1);      // h
        gemm_kernel<3, 16><<<dim3(NROWS / 128, 2), 256, SMEM_GEMM>>>(bn2);      // ns +=
    }

    zero_out_kernel<<<(BB * PP * DD + 255) / 256, 256>>>(out, BB * PP * DD);
    extract_kernel<<<dim3(NN / 256, BB), 256, SMEM_EXT>>>(attn, out);
}